// round 7
// baseline (speedup 1.0000x reference)
#include <cuda_runtime.h>
#include <cuda_fp16.h>
#include <cstdint>
#include <math.h>

// Problem constants
#define Bc   2
#define Tc   8192
#define Hc   8
#define Dc   128
#define HIDc 1024
#define NCc  128          // T / CHUNK
#define Fc   256          // hedgehog feature dim (2*DQK)
#define MTOT (Bc*Tc)      // 16384 tokens

// ---------------------------------------------------------------------------
// Scratch (device globals — no allocations allowed)
// ---------------------------------------------------------------------------
__device__ __half g_xh  [(size_t)MTOT*HIDc];      // 32 MB
__device__ __half g_wqh [HIDc*HIDc];
__device__ __half g_wkh [HIDc*HIDc];
__device__ __half g_wvh [HIDc*HIDc];
__device__ __half g_woh [HIDc*HIDc];
__device__ __half g_wq2 [HIDc*HIDc];              // folded fmq @ Wq (per head)
__device__ __half g_wk2 [HIDc*HIDc];              // folded fmk @ Wk
__device__ __half g_q   [(size_t)MTOT*HIDc];      // y_q = x @ Wq2^T
__device__ __half g_k   [(size_t)MTOT*HIDc];      // y_k
__device__ __half g_v   [(size_t)MTOT*HIDc];
__device__ __half g_qf  [(size_t)MTOT*Hc*Fc];     // 64 MB (pre-scaled)
__device__ __half g_kf  [(size_t)MTOT*Hc*Fc];     // 64 MB
__device__ __half g_kvh [(size_t)Bc*Hc*NCc*Fc*Dc]; // 128 MB per-chunk KV (fp16)
__device__ __half g_s   [(size_t)Bc*Hc*NCc*Fc*Dc]; // 128 MB exclusive prefix (fp16)
__device__ __half g_oh  [(size_t)MTOT*HIDc];      // attention out / rmsnorm in-place

// ---------------------------------------------------------------------------
// Helpers
// ---------------------------------------------------------------------------
__device__ __forceinline__ uint32_t smem_u32(const void* p) {
    uint32_t a;
    asm("{ .reg .u64 t; cvta.to.shared.u64 t, %1; cvt.u32.u64 %0, t; }" : "=r"(a) : "l"(p));
    return a;
}
__device__ __forceinline__ uint32_t pack2(float lo, float hi) {
    __half2 h = __floats2half2_rn(lo, hi);
    return *reinterpret_cast<uint32_t*>(&h);
}
__device__ __forceinline__ void mma_f16(float* c, const uint32_t* a, const uint32_t* b) {
    asm volatile(
        "mma.sync.aligned.m16n8k16.row.col.f32.f16.f16.f32 "
        "{%0,%1,%2,%3}, {%4,%5,%6,%7}, {%8,%9}, {%0,%1,%2,%3};"
        : "+f"(c[0]), "+f"(c[1]), "+f"(c[2]), "+f"(c[3])
        : "r"(a[0]), "r"(a[1]), "r"(a[2]), "r"(a[3]), "r"(b[0]), "r"(b[1]));
}
#define LDSM4(r, addr) \
    asm volatile("ldmatrix.sync.aligned.m8n8.x4.shared.b16 {%0,%1,%2,%3}, [%4];" \
        : "=r"((r)[0]), "=r"((r)[1]), "=r"((r)[2]), "=r"((r)[3]) : "r"(addr))
#define LDSM4T(r, addr) \
    asm volatile("ldmatrix.sync.aligned.m8n8.x4.trans.shared.b16 {%0,%1,%2,%3}, [%4];" \
        : "=r"((r)[0]), "=r"((r)[1]), "=r"((r)[2]), "=r"((r)[3]) : "r"(addr))
__device__ __forceinline__ void cp16(uint32_t dst, const void* src) {
    asm volatile("cp.async.cg.shared.global [%0], [%1], 16;" :: "r"(dst), "l"(src) : "memory");
}
#define CP_COMMIT() asm volatile("cp.async.commit_group;" ::: "memory")
#define CP_WAIT(n)  asm volatile("cp.async.wait_group %0;" :: "n"(n) : "memory")

// ---------------------------------------------------------------------------
// f32 -> f16 conversion (n multiple of 2048)
// ---------------------------------------------------------------------------
__global__ __launch_bounds__(256) void f2h(const float* __restrict__ s,
                                           __half* __restrict__ d, int n)
{
    int i = (blockIdx.x * 256 + threadIdx.x) * 8;
    if (i < n) {
        float4 a = *(const float4*)(s + i), b = *(const float4*)(s + i + 4);
        *(uint4*)(d + i) = make_uint4(pack2(a.x, a.y), pack2(a.z, a.w),
                                      pack2(b.x, b.y), pack2(b.z, b.w));
    }
}
// 4 weight matrices in one launch (grid.z selects)
__global__ __launch_bounds__(256) void wconv(
    const float* __restrict__ w0, const float* __restrict__ w1,
    const float* __restrict__ w2, const float* __restrict__ w3)
{
    const int z = blockIdx.z;
    const float* s = (z == 0) ? w0 : (z == 1) ? w1 : (z == 2) ? w2 : w3;
    __half* d = (z == 0) ? g_wqh : (z == 1) ? g_wkh : (z == 2) ? g_wvh : g_woh;
    int i = (blockIdx.x * 256 + threadIdx.x) * 8;
    float4 a = *(const float4*)(s + i), b = *(const float4*)(s + i + 4);
    *(uint4*)(d + i) = make_uint4(pack2(a.x, a.y), pack2(a.z, a.w),
                                  pack2(b.x, b.y), pack2(b.z, b.w));
}

// ---------------------------------------------------------------------------
// Fold: W2[h*128+i, c] = sum_j fm[i,j] * W[h*128+j, c]
// Block: (colTile ct, head h, z=q/k). 256 threads, warp grid 4(M)x2(N),
// warp tile 32x64, K=128. fm f32 -> f16 in smem; W block fp16 via ldsm.trans.
// ---------------------------------------------------------------------------
#define FSKP 136
#define FD_A 0
#define FD_B (128*FSKP*2)               // 34816
#define FOLD_SMEM (2*128*FSKP*2)        // 69632

__global__ __launch_bounds__(256) void fold_w(
    const float* __restrict__ fmq, const float* __restrict__ fmk)
{
    const int z = blockIdx.z;
    const float* fm = z ? fmk : fmq;
    const __half* W = z ? g_wkh : g_wqh;
    __half* W2 = z ? g_wk2 : g_wq2;

    extern __shared__ char smc[];
    const uint32_t sb = smem_u32(smc);
    const int tid = threadIdx.x, wid = tid >> 5, lane = tid & 31;
    const int wm = wid & 3, wn = wid >> 2;
    const int qr = lane >> 2, qc = lane & 3;
    const int ct = blockIdx.x, h = blockIdx.y;

    // fm 128x128 f32 -> f16 smem [i][j]
#pragma unroll
    for (int it = 0; it < 16; it++) {
        int e = tid + it * 256;
        int r = e >> 5, c4 = e & 31;
        float4 f = *(const float4*)(fm + r * 128 + c4 * 4);
        *(uint2*)(smc + FD_A + ((uint32_t)r * FSKP + c4 * 4) * 2) =
            make_uint2(pack2(f.x, f.y), pack2(f.z, f.w));
    }
    // W block fp16 smem [j][c] (j = k dim, c = n dim)
#pragma unroll
    for (int it = 0; it < 8; it++) {
        int e = tid + it * 256;
        int r = e >> 4, p = e & 15;
        *(uint4*)(smc + FD_B + ((uint32_t)r * FSKP + p * 8) * 2) =
            *(const uint4*)(&W[(size_t)(h * 128 + r) * 1024 + ct * 128 + p * 8]);
    }
    __syncthreads();

    float acc[2][8][4];
#pragma unroll
    for (int mf = 0; mf < 2; mf++)
#pragma unroll
        for (int nf = 0; nf < 8; nf++)
#pragma unroll
            for (int i = 0; i < 4; i++) acc[mf][nf][i] = 0.f;

    const uint32_t a_off = FD_A + (uint32_t)(wm*32 + (lane&7) + ((lane>>3)&1)*8) * (FSKP*2)
                         + (lane>>4)*16;
    const uint32_t cb = (lane & 7) + ((lane >> 3) & 1) * 8;
    const uint32_t nb = (lane >> 4) * 8;

#pragma unroll
    for (int ks = 0; ks < 8; ks++) {
        uint32_t a[2][4];
        LDSM4(a[0], sb + a_off + ks * 32);
        LDSM4(a[1], sb + a_off + 16 * FSKP * 2 + ks * 32);
#pragma unroll
        for (int np = 0; np < 4; np++) {
            uint32_t b[4];
            LDSM4T(b, sb + FD_B + ((ks*16 + cb) * FSKP + wn*64 + np*16 + nb) * 2);
            mma_f16(acc[0][2*np],   a[0], b);
            mma_f16(acc[0][2*np+1], a[0], b + 2);
            mma_f16(acc[1][2*np],   a[1], b);
            mma_f16(acc[1][2*np+1], a[1], b + 2);
        }
    }

#pragma unroll
    for (int mf = 0; mf < 2; mf++) {
        const int i0 = h * 128 + wm * 32 + mf * 16 + qr;
#pragma unroll
        for (int nf = 0; nf < 8; nf++) {
            const int c0 = ct * 128 + wn * 64 + nf * 8 + qc * 2;
            *(uint32_t*)&W2[(size_t)i0 * 1024 + c0] = pack2(acc[mf][nf][0], acc[mf][nf][1]);
            *(uint32_t*)&W2[(size_t)(i0 + 8) * 1024 + c0] = pack2(acc[mf][nf][2], acc[mf][nf][3]);
        }
    }
}

// ---------------------------------------------------------------------------
// fp16 GEMM: Y[M,1024] = X[M,1024] @ W[1024,1024]^T
// CTA 128x256, BK=32, 3-stage cp.async, 8 warps 2(M)x4(N), warp tile 64x64.
// grid (N/256, M/128, nz); z selects (W, Y). HALF: fp16 vs f32 output.
// ---------------------------------------------------------------------------
#define SKP_B   80
#define GA_B    (128*SKP_B)           // 10240 (A: 128 rows)
#define GB_B    (256*SKP_B)           // 20480 (B: 256 rows)
#define GSTG    (GA_B + GB_B)         // 30720
#define GEMM_SMEM (3*GSTG)            // 92160

template<int HALF>
__global__ __launch_bounds__(256, 1) void gemm_t(
    const __half* __restrict__ X,
    const __half* __restrict__ W0, const __half* __restrict__ W1,
    const __half* __restrict__ W2,
    __half* __restrict__ Y0, __half* __restrict__ Y1, __half* __restrict__ Y2,
    float* __restrict__ Yf)
{
    const int z = blockIdx.z;
    const __half* W = (z == 0) ? W0 : ((z == 1) ? W1 : W2);
    __half* Yh = (z == 0) ? Y0 : ((z == 1) ? Y1 : Y2);

    extern __shared__ char smc[];
    const uint32_t sb = smem_u32(smc);
    const int tid = threadIdx.x, wid = tid >> 5, lane = tid & 31;
    const int wm = wid & 1, wn = wid >> 1;     // 2(M) x 4(N)
    const int qr = lane >> 2, qc = lane & 3;
    const int m0 = blockIdx.y * 128, n0 = blockIdx.x * 256;

    const int pr = tid >> 2, pp = tid & 3;     // pr 0..63, pp 0..3
    const __half* Xp = X + (size_t)(m0 + pr) * 1024 + pp * 8;
    const __half* Wp = W + (size_t)(n0 + pr) * 1024 + pp * 8;
    const uint32_t sA0 = (uint32_t)pr * SKP_B + pp * 16;
    const uint32_t sA1 = sA0 + 64 * SKP_B;

    const uint32_t a_off = (uint32_t)(wm*64 + (lane&7) + ((lane>>3)&1)*8) * SKP_B
                         + (lane>>4)*16;
    const uint32_t b_off = (uint32_t)(wn*64 + (lane>>4)*8 + (lane&7)) * SKP_B
                         + ((lane>>3)&1)*16;

    float acc[4][8][4];
#pragma unroll
    for (int mf = 0; mf < 4; mf++)
#pragma unroll
        for (int nf = 0; nf < 8; nf++)
#pragma unroll
            for (int i = 0; i < 4; i++) acc[mf][nf][i] = 0.f;

#define LOAD_STAGE(kt, st) {                                          \
    uint32_t base = sb + (st) * GSTG;                                 \
    const __half* xk = Xp + (kt) * 32;                                \
    const __half* wk = Wp + (kt) * 32;                                \
    cp16(base + sA0, xk);                                             \
    cp16(base + sA1, xk + (size_t)64 * 1024);                         \
    cp16(base + GA_B + sA0, wk);                                      \
    cp16(base + GA_B + sA1, wk + (size_t)64 * 1024);                  \
    cp16(base + GA_B + sA0 + 128 * SKP_B, wk + (size_t)128 * 1024);   \
    cp16(base + GA_B + sA1 + 128 * SKP_B, wk + (size_t)192 * 1024); }

    LOAD_STAGE(0, 0); CP_COMMIT();
    LOAD_STAGE(1, 1); CP_COMMIT();

    for (int kt = 0; kt < 32; kt++) {
        const int st = kt % 3;
        CP_WAIT(1);
        __syncthreads();
        const uint32_t As = sb + st * GSTG, Bs = As + GA_B;
#pragma unroll
        for (int ks = 0; ks < 2; ks++) {
            uint32_t a[4][4];
#pragma unroll
            for (int mf = 0; mf < 4; mf++)
                LDSM4(a[mf], As + a_off + mf * (16 * SKP_B) + ks * 32);
#pragma unroll
            for (int np = 0; np < 4; np++) {
                uint32_t b[4];
                LDSM4(b, Bs + b_off + np * (16 * SKP_B) + ks * 32);
#pragma unroll
                for (int mf = 0; mf < 4; mf++) {
                    mma_f16(acc[mf][2*np],   a[mf], b);
                    mma_f16(acc[mf][2*np+1], a[mf], b + 2);
                }
            }
        }
        if (kt + 2 < 32) LOAD_STAGE(kt + 2, (kt + 2) % 3);
        CP_COMMIT();
    }
#undef LOAD_STAGE

#pragma unroll
    for (int mf = 0; mf < 4; mf++) {
        const int r0 = m0 + wm * 64 + mf * 16 + qr;
#pragma unroll
        for (int nf = 0; nf < 8; nf++) {
            const int c0 = n0 + wn * 64 + nf * 8 + qc * 2;
            if (HALF) {
                *(uint32_t*)&Yh[(size_t)r0 * 1024 + c0] =
                    pack2(acc[mf][nf][0], acc[mf][nf][1]);
                *(uint32_t*)&Yh[(size_t)(r0 + 8) * 1024 + c0] =
                    pack2(acc[mf][nf][2], acc[mf][nf][3]);
            } else {
                *(float2*)&Yf[(size_t)r0 * 1024 + c0] =
                    make_float2(acc[mf][nf][0], acc[mf][nf][1]);
                *(float2*)&Yf[(size_t)(r0 + 8) * 1024 + c0] =
                    make_float2(acc[mf][nf][2], acc[mf][nf][3]);
            }
        }
    }
}

// ---------------------------------------------------------------------------
// Hedgehog softmax (matmul folded into the GEMM weights):
// features = softmax(concat(2(y+b), -2(y+b))) * scale
// One warp per (token, head) row. grid (MTOT*Hc/8, 1, 2); z: 0=q, 1=k.
// ---------------------------------------------------------------------------
__global__ __launch_bounds__(256) void hh_soft(
    const float* __restrict__ biasq, const float* __restrict__ biask)
{
    const int z = blockIdx.z;
    const __half* src = z ? g_k : g_q;
    __half* dst = z ? g_kf : g_qf;
    const float* bias = z ? biask : biasq;
    const float scale = z ? 1.0f : 0.0625f;   // 256^-0.5 folded into qf

    const int wid = threadIdx.x >> 5, lane = threadIdx.x & 31;
    const int r = blockIdx.x * 8 + wid;       // (t, h) row
    const int t = r >> 3, h = r & 7;

    // lane holds 4 consecutive y values
    uint2 raw = *(const uint2*)(src + (size_t)t * HIDc + h * 128 + lane * 4);
    float2 p0 = __half22float2(*(__half2*)&raw.x);
    float2 p1 = __half22float2(*(__half2*)&raw.y);
    float4 bv = *(const float4*)(bias + lane * 4);

    float y[4];
    y[0] = 2.f * (p0.x + bv.x); y[1] = 2.f * (p0.y + bv.y);
    y[2] = 2.f * (p1.x + bv.z); y[3] = 2.f * (p1.y + bv.w);

    float m = fmaxf(fmaxf(fabsf(y[0]), fabsf(y[1])), fmaxf(fabsf(y[2]), fabsf(y[3])));
#pragma unroll
    for (int off = 16; off >= 1; off >>= 1)
        m = fmaxf(m, __shfl_xor_sync(0xffffffffu, m, off));

    float ep[4], en[4], zs = 0.f;
#pragma unroll
    for (int j = 0; j < 4; j++) {
        ep[j] = __expf( y[j] - m);
        en[j] = __expf(-y[j] - m);
        zs += ep[j] + en[j];
    }
#pragma unroll
    for (int off = 16; off >= 1; off >>= 1)
        zs += __shfl_xor_sync(0xffffffffu, zs, off);
    const float inv = scale / zs;

    __half* drow = dst + (size_t)r * Fc;
    *(uint2*)(drow + lane * 4) =
        make_uint2(pack2(ep[0]*inv, ep[1]*inv), pack2(ep[2]*inv, ep[3]*inv));
    *(uint2*)(drow + 128 + lane * 4) =
        make_uint2(pack2(en[0]*inv, en[1]*inv), pack2(en[2]*inv, en[3]*inv));
}

// ---------------------------------------------------------------------------
// KV per chunk (fp16 mma): KV[d,e] = sum_c kf[c,d] * v[c,e]  (256 x 128)
// ---------------------------------------------------------------------------
#define KVQ 0
#define KVV 33792
#define KV_SMEM 51200

__global__ __launch_bounds__(512) void kv_kernel()
{
    extern __shared__ char smc[];
    const uint32_t sb = smem_u32(smc);
    const int chunk = blockIdx.x, h = blockIdx.y, b = blockIdx.z;
    const int tid = threadIdx.x, wid = tid >> 5, lane = tid & 31;
    const int wm = wid & 3, wn = wid >> 2;
    const int g = lane >> 2, t4 = lane & 3;
    const int t0 = chunk * 64;

    const size_t kbase = ((size_t)(b*Tc + t0) * Hc + h) * Fc;
#pragma unroll
    for (int i = 0; i < 4; i++) {
        int l = tid + i * 512;
        int r = l >> 5, p = l & 31;
        *(uint4*)(smc + KVQ + ((uint32_t)r * 264 + p * 8) * 2) =
            *(const uint4*)(&g_kf[kbase + (size_t)r * (Hc*Fc) + p * 8]);
    }
#pragma unroll
    for (int i = 0; i < 2; i++) {
        int l = tid + i * 512;
        int r = l >> 4, p = l & 15;
        *(uint4*)(smc + KVV + ((uint32_t)r * 136 + p * 8) * 2) =
            *(const uint4*)(&g_v[(size_t)(b*Tc + t0 + r) * HIDc + h * 128 + p * 8]);
    }
    __syncthreads();

    float acc[4][4][4];
#pragma unroll
    for (int mf = 0; mf < 4; mf++)
#pragma unroll
        for (int nf = 0; nf < 4; nf++)
#pragma unroll
            for (int i = 0; i < 4; i++) acc[mf][nf][i] = 0.f;

    const uint32_t ca = (lane & 7) + ((lane >> 4) & 1) * 8;
    const uint32_t ma = ((lane >> 3) & 1) * 8;
    const uint32_t cb = (lane & 7) + ((lane >> 3) & 1) * 8;
    const uint32_t nb = (lane >> 4) * 8;

#pragma unroll
    for (int ks = 0; ks < 4; ks++) {
        uint32_t bb[2][4];
#pragma unroll
        for (int np = 0; np < 2; np++)
            LDSM4T(bb[np], sb + KVV + ((ks*16 + cb) * 136 + wn*32 + np*16 + nb) * 2);
#pragma unroll
        for (int mf = 0; mf < 4; mf++) {
            uint32_t a[4];
            LDSM4T(a, sb + KVQ + ((ks*16 + ca) * 264 + wm*64 + mf*16 + ma) * 2);
            mma_f16(acc[mf][0], a, bb[0]);
            mma_f16(acc[mf][1], a, bb[0] + 2);
            mma_f16(acc[mf][2], a, bb[1]);
            mma_f16(acc[mf][3], a, bb[1] + 2);
        }
    }

    const size_t base = (((size_t)(b*Hc + h)) * NCc + chunk) * (size_t)(Fc * Dc);
#pragma unroll
    for (int mf = 0; mf < 4; mf++)
#pragma unroll
        for (int nf = 0; nf < 4; nf++) {
            int d = wm * 64 + mf * 16 + g;
            int e = wn * 32 + nf * 8 + t4 * 2;
            *(uint32_t*)&g_kvh[base + (size_t)d * 128 + e] =
                pack2(acc[mf][nf][0], acc[mf][nf][1]);
            *(uint32_t*)&g_kvh[base + (size_t)(d + 8) * 128 + e] =
                pack2(acc[mf][nf][2], acc[mf][nf][3]);
        }
}

// ---------------------------------------------------------------------------
// Exclusive prefix over chunks, fp16 in, f32 accumulate, fp16 out
// ---------------------------------------------------------------------------
__global__ __launch_bounds__(256) void prefix_kernel()
{
    const int bh  = blockIdx.y;
    const int idx = (blockIdx.x * 256 + threadIdx.x) * 2;
    const size_t stride = (size_t)Fc * Dc;
    size_t p = (size_t)bh * NCc * stride + idx;
    float ax = 0.f, ay = 0.f;
    for (int i = 0; i < NCc; i++) {
        float2 t = __half22float2(*(const __half2*)&g_kvh[p]);
        *(uint32_t*)&g_s[p] = pack2(ax, ay);
        ax += t.x; ay += t.y;
        p += stride;
    }
}

// ---------------------------------------------------------------------------
// Output per chunk (fp16 mma): o = tril(qf @ kf^T) @ v + qf @ S  -> fp16
// ---------------------------------------------------------------------------
#define OQF 0
#define OKF 33792
#define OV  67584
#define OAT 84992
#define OS  94208
#define OUT_SMEM 163840

__global__ __launch_bounds__(256) void out_kernel()
{
    extern __shared__ char smc[];
    const uint32_t sb = smem_u32(smc);
    const int chunk = blockIdx.x, h = blockIdx.y, b = blockIdx.z;
    const int tid = threadIdx.x, wid = tid >> 5, lane = tid & 31;
    const int g = lane >> 2, t4 = lane & 3;
    const int t0 = chunk * 64;

    const size_t qbase = ((size_t)(b*Tc + t0) * Hc + h) * Fc;
#pragma unroll
    for (int i = 0; i < 8; i++) {
        int l = tid + i * 256;
        int r = l >> 5, p = l & 31;
        size_t gs = qbase + (size_t)r * (Hc*Fc) + p * 8;
        *(uint4*)(smc + OQF + ((uint32_t)r * 264 + p * 8) * 2) = *(const uint4*)(&g_qf[gs]);
        *(uint4*)(smc + OKF + ((uint32_t)r * 264 + p * 8) * 2) = *(const uint4*)(&g_kf[gs]);
    }
#pragma unroll
    for (int i = 0; i < 4; i++) {
        int l = tid + i * 256;
        int r = l >> 4, p = l & 15;
        *(uint4*)(smc + OV + ((uint32_t)r * 136 + p * 8) * 2) =
            *(const uint4*)(&g_v[(size_t)(b*Tc + t0 + r) * HIDc + h * 128 + p * 8]);
    }
    const size_t sbase = (((size_t)(b*Hc + h)) * NCc + chunk) * (size_t)(Fc * Dc);
#pragma unroll
    for (int i = 0; i < 16; i++) {
        int l = tid + i * 256;
        int f = l >> 4, p = l & 15;
        *(uint4*)(smc + OS + ((uint32_t)f * 136 + p * 8) * 2) =
            *(const uint4*)(&g_s[sbase + (size_t)f * 128 + p * 8]);
    }
    __syncthreads();

    // phase 1: scores = tril(qf @ kf^T)
    {
        const int wm = wid & 1, wn = wid >> 1;
        float sc[2][2][4];
#pragma unroll
        for (int mf = 0; mf < 2; mf++)
#pragma unroll
            for (int nf = 0; nf < 2; nf++)
#pragma unroll
                for (int i = 0; i < 4; i++) sc[mf][nf][i] = 0.f;

        const uint32_t aoff = OQF + (uint32_t)(wm*32 + (lane&7) + ((lane>>3)&1)*8) * 528
                            + (lane>>4)*16;
        const uint32_t boff = OKF + (uint32_t)(wn*16 + (lane>>4)*8 + (lane&7)) * 528
                            + ((lane>>3)&1)*16;
#pragma unroll
        for (int ks = 0; ks < 16; ks++) {
            uint32_t a[2][4], bbf[4];
            LDSM4(a[0], sb + aoff + ks * 32);
            LDSM4(a[1], sb + aoff + 16 * 528 + ks * 32);
            LDSM4(bbf, sb + boff + ks * 32);
            mma_f16(sc[0][0], a[0], bbf);
            mma_f16(sc[0][1], a[0], bbf + 2);
            mma_f16(sc[1][0], a[1], bbf);
            mma_f16(sc[1][1], a[1], bbf + 2);
        }
#pragma unroll
        for (int mf = 0; mf < 2; mf++)
#pragma unroll
            for (int nf = 0; nf < 2; nf++) {
                int ci = wm*32 + mf*16 + g;
                int cj = wn*16 + nf*8 + t4*2;
                float v0 = (cj     <= ci) ? sc[mf][nf][0] : 0.f;
                float v1 = (cj + 1 <= ci) ? sc[mf][nf][1] : 0.f;
                *(uint32_t*)(smc + OAT + ((uint32_t)ci * 72 + cj) * 2) = pack2(v0, v1);
                int ci2 = ci + 8;
                float v2 = (cj     <= ci2) ? sc[mf][nf][2] : 0.f;
                float v3 = (cj + 1 <= ci2) ? sc[mf][nf][3] : 0.f;
                *(uint32_t*)(smc + OAT + ((uint32_t)ci2 * 72 + cj) * 2) = pack2(v2, v3);
            }
    }
    __syncthreads();

    // phase 2: o = attn @ v + qf @ S
    {
        const int wm = wid & 1, wn = wid >> 1;
        float o[2][4][4];
#pragma unroll
        for (int mf = 0; mf < 2; mf++)
#pragma unroll
            for (int nf = 0; nf < 4; nf++)
#pragma unroll
                for (int i = 0; i < 4; i++) o[mf][nf][i] = 0.f;

        const uint32_t cb = (lane & 7) + ((lane >> 3) & 1) * 8;
        const uint32_t nb = (lane >> 4) * 8;

        const uint32_t a1 = OAT + (uint32_t)(wm*32 + (lane&7) + ((lane>>3)&1)*8) * 144
                          + (lane>>4)*16;
#pragma unroll
        for (int ks = 0; ks < 4; ks++) {
            uint32_t a[2][4];
            LDSM4(a[0], sb + a1 + ks * 32);
            LDSM4(a[1], sb + a1 + 16 * 144 + ks * 32);
#pragma unroll
            for (int np = 0; np < 2; np++) {
                uint32_t bbf[4];
                LDSM4T(bbf, sb + OV + ((ks*16 + cb) * 136 + wn*32 + np*16 + nb) * 2);
                mma_f16(o[0][2*np],   a[0], bbf);
                mma_f16(o[0][2*np+1], a[0], bbf + 2);
                mma_f16(o[1][2*np],   a[1], bbf);
                mma_f16(o[1][2*np+1], a[1], bbf + 2);
            }
        }
        const uint32_t a2 = OQF + (uint32_t)(wm*32 + (lane&7) + ((lane>>3)&1)*8) * 528
                          + (lane>>4)*16;
#pragma unroll
        for (int ks = 0; ks < 16; ks++) {
            uint32_t a[2][4];
            LDSM4(a[0], sb + a2 + ks * 32);
            LDSM4(a[1], sb + a2 + 16 * 528 + ks * 32);
#pragma unroll
            for (int np = 0; np < 2; np++) {
                uint32_t bbf[4];
                LDSM4T(bbf, sb + OS + ((ks*16 + cb) * 136 + wn*32 + np*16 + nb) * 2);
                mma_f16(o[0][2*np],   a[0], bbf);
                mma_f16(o[0][2*np+1], a[0], bbf + 2);
                mma_f16(o[1][2*np],   a[1], bbf);
                mma_f16(o[1][2*np+1], a[1], bbf + 2);
            }
        }
#pragma unroll
        for (int mf = 0; mf < 2; mf++)
#pragma unroll
            for (int nf = 0; nf < 4; nf++) {
                int r = t0 + wm*32 + mf*16 + g;
                int e = wn*32 + nf*8 + t4*2;
                size_t base = (size_t)(b*Tc + r) * HIDc + h * 128 + e;
                *(uint32_t*)&g_oh[base] = pack2(o[mf][nf][0], o[mf][nf][1]);
                *(uint32_t*)&g_oh[base + (size_t)8 * HIDc] =
                    pack2(o[mf][nf][2], o[mf][nf][3]);
            }
    }
}

// ---------------------------------------------------------------------------
// RMSNorm over last dim 1024, fp16 in-place in g_oh
// ---------------------------------------------------------------------------
__global__ __launch_bounds__(256) void rmsnorm_kernel()
{
    const int t = blockIdx.x;
    __half2* row = (__half2*)(g_oh + (size_t)t * HIDc);
    const int tid = threadIdx.x;

    float2 v0 = __half22float2(row[tid]);
    float2 v1 = __half22float2(row[tid + 256]);
    float s = v0.x*v0.x + v0.y*v0.y + v1.x*v1.x + v1.y*v1.y;
#pragma unroll
    for (int off = 16; off >= 1; off >>= 1)
        s += __shfl_xor_sync(0xffffffffu, s, off);

    __shared__ float wsum[8];
    if ((tid & 31) == 0) wsum[tid >> 5] = s;
    __syncthreads();
    float tot = 0.f;
#pragma unroll
    for (int w = 0; w < 8; w++) tot += wsum[w];

    const float r = rsqrtf(tot * (1.f / HIDc) + 1e-5f);
    row[tid]       = __floats2half2_rn(v0.x * r, v0.y * r);
    row[tid + 256] = __floats2half2_rn(v1.x * r, v1.y * r);
}

// ---------------------------------------------------------------------------
// Launch
// ---------------------------------------------------------------------------
extern "C" void kernel_launch(void* const* d_in, const int* in_sizes, int n_in,
                              void* d_out, int out_size)
{
    const float* x    = (const float*)d_in[0];
    const float* Wq   = (const float*)d_in[1];
    const float* Wk   = (const float*)d_in[2];
    const float* Wv   = (const float*)d_in[3];
    const float* Wo   = (const float*)d_in[4];
    const float* fmqw = (const float*)d_in[5];
    const float* fmqb = (const float*)d_in[6];
    const float* fmkw = (const float*)d_in[7];
    const float* fmkb = (const float*)d_in[8];
    float* out = (float*)d_out;

    __half *xh, *wvh, *woh, *wq2, *wk2, *qh, *kh, *vh, *oh;
    cudaGetSymbolAddress((void**)&xh,  g_xh);
    cudaGetSymbolAddress((void**)&wvh, g_wvh);
    cudaGetSymbolAddress((void**)&woh, g_woh);
    cudaGetSymbolAddress((void**)&wq2, g_wq2);
    cudaGetSymbolAddress((void**)&wk2, g_wk2);
    cudaGetSymbolAddress((void**)&qh,  g_q);
    cudaGetSymbolAddress((void**)&kh,  g_k);
    cudaGetSymbolAddress((void**)&vh,  g_v);
    cudaGetSymbolAddress((void**)&oh,  g_oh);

    cudaFuncSetAttribute(gemm_t<1>, cudaFuncAttributeMaxDynamicSharedMemorySize, GEMM_SMEM);
    cudaFuncSetAttribute(gemm_t<0>, cudaFuncAttributeMaxDynamicSharedMemorySize, GEMM_SMEM);
    cudaFuncSetAttribute(fold_w,    cudaFuncAttributeMaxDynamicSharedMemorySize, FOLD_SMEM);
    cudaFuncSetAttribute(kv_kernel, cudaFuncAttributeMaxDynamicSharedMemorySize, KV_SMEM);
    cudaFuncSetAttribute(out_kernel,cudaFuncAttributeMaxDynamicSharedMemorySize, OUT_SMEM);

    // conversions + weight folding
    f2h<<<MTOT*HIDc/2048, 256>>>(x, xh, MTOT*HIDc);
    wconv<<<dim3(HIDc*HIDc/2048, 1, 4), 256>>>(Wq, Wk, Wv, Wo);
    fold_w<<<dim3(8, 8, 2), 256, FOLD_SMEM>>>(fmqw, fmkw);

    // fused QKV GEMM (q,k use folded weights -> y directly)
    gemm_t<1><<<dim3(HIDc/256, MTOT/128, 3), 256, GEMM_SMEM>>>(
        xh, wq2, wk2, wvh, qh, kh, vh, nullptr);

    // softmax-only hedgehog
    hh_soft<<<dim3(MTOT*Hc/8, 1, 2), 256>>>(fmqb, fmkb);

    dim3 cg(NCc, Hc, Bc);
    kv_kernel<<<cg, 512, KV_SMEM>>>();
    prefix_kernel<<<dim3(64, Bc*Hc), 256>>>();
    out_kernel<<<cg, 256, OUT_SMEM>>>();

    rmsnorm_kernel<<<MTOT, 256>>>();
    gemm_t<0><<<dim3(HIDc/256, MTOT/128, 1), 256, GEMM_SMEM>>>(
        oh, woh, woh, woh, nullptr, nullptr, nullptr, out);
}

// round 8
// speedup vs baseline: 1.1111x; 1.1111x over previous
#include <cuda_runtime.h>
#include <cuda_fp16.h>
#include <cstdint>
#include <math.h>

// Problem constants
#define Bc   2
#define Tc   8192
#define Hc   8
#define Dc   128
#define HIDc 1024
#define NCc  128          // T / CHUNK
#define Fc   256          // hedgehog feature dim (2*DQK)
#define MTOT (Bc*Tc)      // 16384 tokens

// ---------------------------------------------------------------------------
// Scratch (device globals — no allocations allowed)
// ---------------------------------------------------------------------------
__device__ __half g_xh  [(size_t)MTOT*HIDc];      // 32 MB
__device__ __half g_wqh [HIDc*HIDc];
__device__ __half g_wkh [HIDc*HIDc];
__device__ __half g_wvh [HIDc*HIDc];
__device__ __half g_woh [HIDc*HIDc];
__device__ __half g_wq2 [HIDc*HIDc];              // folded fmq @ Wq (per head)
__device__ __half g_wk2 [HIDc*HIDc];              // folded fmk @ Wk
__device__ __half g_q   [(size_t)MTOT*HIDc];      // y_q = x @ Wq2^T
__device__ __half g_k   [(size_t)MTOT*HIDc];      // y_k
__device__ __half g_v   [(size_t)MTOT*HIDc];
__device__ __half g_qf  [(size_t)MTOT*Hc*Fc];     // 64 MB (pre-scaled)
__device__ __half g_kf  [(size_t)MTOT*Hc*Fc];     // 64 MB
__device__ __half g_kvh [(size_t)Bc*Hc*NCc*Fc*Dc]; // 128 MB per-chunk KV (fp16)
__device__ __half g_s   [(size_t)Bc*Hc*NCc*Fc*Dc]; // 128 MB exclusive prefix (fp16)
__device__ __half g_oh  [(size_t)MTOT*HIDc];      // attention out / rmsnorm in-place

// ---------------------------------------------------------------------------
// Helpers
// ---------------------------------------------------------------------------
__device__ __forceinline__ uint32_t smem_u32(const void* p) {
    uint32_t a;
    asm("{ .reg .u64 t; cvta.to.shared.u64 t, %1; cvt.u32.u64 %0, t; }" : "=r"(a) : "l"(p));
    return a;
}
__device__ __forceinline__ uint32_t pack2(float lo, float hi) {
    __half2 h = __floats2half2_rn(lo, hi);
    return *reinterpret_cast<uint32_t*>(&h);
}
__device__ __forceinline__ void mma_f16(float* c, const uint32_t* a, const uint32_t* b) {
    asm volatile(
        "mma.sync.aligned.m16n8k16.row.col.f32.f16.f16.f32 "
        "{%0,%1,%2,%3}, {%4,%5,%6,%7}, {%8,%9}, {%0,%1,%2,%3};"
        : "+f"(c[0]), "+f"(c[1]), "+f"(c[2]), "+f"(c[3])
        : "r"(a[0]), "r"(a[1]), "r"(a[2]), "r"(a[3]), "r"(b[0]), "r"(b[1]));
}
#define LDSM4(r, addr) \
    asm volatile("ldmatrix.sync.aligned.m8n8.x4.shared.b16 {%0,%1,%2,%3}, [%4];" \
        : "=r"((r)[0]), "=r"((r)[1]), "=r"((r)[2]), "=r"((r)[3]) : "r"(addr))
#define LDSM4T(r, addr) \
    asm volatile("ldmatrix.sync.aligned.m8n8.x4.trans.shared.b16 {%0,%1,%2,%3}, [%4];" \
        : "=r"((r)[0]), "=r"((r)[1]), "=r"((r)[2]), "=r"((r)[3]) : "r"(addr))
__device__ __forceinline__ void cp16(uint32_t dst, const void* src) {
    asm volatile("cp.async.cg.shared.global [%0], [%1], 16;" :: "r"(dst), "l"(src) : "memory");
}
#define CP_COMMIT() asm volatile("cp.async.commit_group;" ::: "memory")
#define CP_WAIT(n)  asm volatile("cp.async.wait_group %0;" :: "n"(n) : "memory")

// ---------------------------------------------------------------------------
// f32 -> f16 conversion (n multiple of 2048)
// ---------------------------------------------------------------------------
__global__ __launch_bounds__(256) void f2h(const float* __restrict__ s,
                                           __half* __restrict__ d, int n)
{
    int i = (blockIdx.x * 256 + threadIdx.x) * 8;
    if (i < n) {
        float4 a = *(const float4*)(s + i), b = *(const float4*)(s + i + 4);
        *(uint4*)(d + i) = make_uint4(pack2(a.x, a.y), pack2(a.z, a.w),
                                      pack2(b.x, b.y), pack2(b.z, b.w));
    }
}
// 4 weight matrices in one launch (grid.z selects)
__global__ __launch_bounds__(256) void wconv(
    const float* __restrict__ w0, const float* __restrict__ w1,
    const float* __restrict__ w2, const float* __restrict__ w3)
{
    const int z = blockIdx.z;
    const float* s = (z == 0) ? w0 : (z == 1) ? w1 : (z == 2) ? w2 : w3;
    __half* d = (z == 0) ? g_wqh : (z == 1) ? g_wkh : (z == 2) ? g_wvh : g_woh;
    int i = (blockIdx.x * 256 + threadIdx.x) * 8;
    float4 a = *(const float4*)(s + i), b = *(const float4*)(s + i + 4);
    *(uint4*)(d + i) = make_uint4(pack2(a.x, a.y), pack2(a.z, a.w),
                                  pack2(b.x, b.y), pack2(b.z, b.w));
}

// ---------------------------------------------------------------------------
// Fold: W2[h*128+i, c] = sum_j fm[i,j] * W[h*128+j, c]
// ---------------------------------------------------------------------------
#define FSKP 136
#define FD_A 0
#define FD_B (128*FSKP*2)               // 34816
#define FOLD_SMEM (2*128*FSKP*2)        // 69632

__global__ __launch_bounds__(256) void fold_w(
    const float* __restrict__ fmq, const float* __restrict__ fmk)
{
    const int z = blockIdx.z;
    const float* fm = z ? fmk : fmq;
    const __half* W = z ? g_wkh : g_wqh;
    __half* W2 = z ? g_wk2 : g_wq2;

    extern __shared__ char smc[];
    const uint32_t sb = smem_u32(smc);
    const int tid = threadIdx.x, wid = tid >> 5, lane = tid & 31;
    const int wm = wid & 3, wn = wid >> 2;
    const int qr = lane >> 2, qc = lane & 3;
    const int ct = blockIdx.x, h = blockIdx.y;

#pragma unroll
    for (int it = 0; it < 16; it++) {
        int e = tid + it * 256;
        int r = e >> 5, c4 = e & 31;
        float4 f = *(const float4*)(fm + r * 128 + c4 * 4);
        *(uint2*)(smc + FD_A + ((uint32_t)r * FSKP + c4 * 4) * 2) =
            make_uint2(pack2(f.x, f.y), pack2(f.z, f.w));
    }
#pragma unroll
    for (int it = 0; it < 8; it++) {
        int e = tid + it * 256;
        int r = e >> 4, p = e & 15;
        *(uint4*)(smc + FD_B + ((uint32_t)r * FSKP + p * 8) * 2) =
            *(const uint4*)(&W[(size_t)(h * 128 + r) * 1024 + ct * 128 + p * 8]);
    }
    __syncthreads();

    float acc[2][8][4];
#pragma unroll
    for (int mf = 0; mf < 2; mf++)
#pragma unroll
        for (int nf = 0; nf < 8; nf++)
#pragma unroll
            for (int i = 0; i < 4; i++) acc[mf][nf][i] = 0.f;

    const uint32_t a_off = FD_A + (uint32_t)(wm*32 + (lane&7) + ((lane>>3)&1)*8) * (FSKP*2)
                         + (lane>>4)*16;
    const uint32_t cb = (lane & 7) + ((lane >> 3) & 1) * 8;
    const uint32_t nb = (lane >> 4) * 8;

#pragma unroll
    for (int ks = 0; ks < 8; ks++) {
        uint32_t a[2][4];
        LDSM4(a[0], sb + a_off + ks * 32);
        LDSM4(a[1], sb + a_off + 16 * FSKP * 2 + ks * 32);
#pragma unroll
        for (int np = 0; np < 4; np++) {
            uint32_t b[4];
            LDSM4T(b, sb + FD_B + ((ks*16 + cb) * FSKP + wn*64 + np*16 + nb) * 2);
            mma_f16(acc[0][2*np],   a[0], b);
            mma_f16(acc[0][2*np+1], a[0], b + 2);
            mma_f16(acc[1][2*np],   a[1], b);
            mma_f16(acc[1][2*np+1], a[1], b + 2);
        }
    }

#pragma unroll
    for (int mf = 0; mf < 2; mf++) {
        const int i0 = h * 128 + wm * 32 + mf * 16 + qr;
#pragma unroll
        for (int nf = 0; nf < 8; nf++) {
            const int c0 = ct * 128 + wn * 64 + nf * 8 + qc * 2;
            *(uint32_t*)&W2[(size_t)i0 * 1024 + c0] = pack2(acc[mf][nf][0], acc[mf][nf][1]);
            *(uint32_t*)&W2[(size_t)(i0 + 8) * 1024 + c0] = pack2(acc[mf][nf][2], acc[mf][nf][3]);
        }
    }
}

// ---------------------------------------------------------------------------
// fp16 GEMM: Y[M,1024] = X[M,1024] @ W[1024,1024]^T
// CTA 128x128, BK=32, 4-stage cp.async, 8 warps 4x2, warp tile 32x64.
// 2 CTAs/SM. grid (8, M/128, nz); z selects (W, Y).
// ---------------------------------------------------------------------------
#define SKP_B   80
#define GA_B    (128*SKP_B)           // 10240
#define GSTG    (2*GA_B)              // 20480
#define GEMM_SMEM (4*GSTG)            // 81920

template<int HALF>
__global__ __launch_bounds__(256, 2) void gemm_t(
    const __half* __restrict__ X,
    const __half* __restrict__ W0, const __half* __restrict__ W1,
    const __half* __restrict__ W2,
    __half* __restrict__ Y0, __half* __restrict__ Y1, __half* __restrict__ Y2,
    float* __restrict__ Yf)
{
    const int z = blockIdx.z;
    const __half* W = (z == 0) ? W0 : ((z == 1) ? W1 : W2);
    __half* Yh = (z == 0) ? Y0 : ((z == 1) ? Y1 : Y2);

    extern __shared__ char smc[];
    const uint32_t sb = smem_u32(smc);
    const int tid = threadIdx.x, wid = tid >> 5, lane = tid & 31;
    const int wm = wid & 3, wn = wid >> 2;
    const int qr = lane >> 2, qc = lane & 3;
    const int m0 = blockIdx.y * 128, n0 = blockIdx.x * 128;

    const int pr = tid >> 2, pp = tid & 3;
    const __half* Xp = X + (size_t)(m0 + pr) * 1024 + pp * 8;
    const __half* Wp = W + (size_t)(n0 + pr) * 1024 + pp * 8;
    const uint32_t s0 = (uint32_t)pr * SKP_B + pp * 16;
    const uint32_t s1 = (uint32_t)(pr + 64) * SKP_B + pp * 16;

    const uint32_t a_off = (uint32_t)(wm*32 + (lane&7) + ((lane>>3)&1)*8) * SKP_B
                         + (lane>>4)*16;
    const uint32_t b_off = (uint32_t)(wn*64 + (lane>>4)*8 + (lane&7)) * SKP_B
                         + ((lane>>3)&1)*16;

    float acc[2][8][4];
#pragma unroll
    for (int mf = 0; mf < 2; mf++)
#pragma unroll
        for (int nf = 0; nf < 8; nf++)
#pragma unroll
            for (int i = 0; i < 4; i++) acc[mf][nf][i] = 0.f;

#define LOAD_STAGE(kt, st) {                                         \
    uint32_t base = sb + (st) * GSTG;                                \
    const __half* xk = Xp + (kt) * 32;                               \
    const __half* wk = Wp + (kt) * 32;                               \
    cp16(base + s0, xk);                                             \
    cp16(base + s1, xk + (size_t)64 * 1024);                         \
    cp16(base + GA_B + s0, wk);                                      \
    cp16(base + GA_B + s1, wk + (size_t)64 * 1024); }

    LOAD_STAGE(0, 0); CP_COMMIT();
    LOAD_STAGE(1, 1); CP_COMMIT();
    LOAD_STAGE(2, 2); CP_COMMIT();

    for (int kt = 0; kt < 32; kt++) {
        const int st = kt & 3;
        CP_WAIT(2);
        __syncthreads();
        const uint32_t As = sb + st * GSTG, Bs = As + GA_B;
#pragma unroll
        for (int ks = 0; ks < 2; ks++) {
            uint32_t a[2][4];
            LDSM4(a[0], As + a_off + ks * 32);
            LDSM4(a[1], As + a_off + 16 * SKP_B + ks * 32);
#pragma unroll
            for (int np = 0; np < 4; np++) {
                uint32_t b[4];
                LDSM4(b, Bs + b_off + np * (16 * SKP_B) + ks * 32);
                mma_f16(acc[0][2*np],   a[0], b);
                mma_f16(acc[0][2*np+1], a[0], b + 2);
                mma_f16(acc[1][2*np],   a[1], b);
                mma_f16(acc[1][2*np+1], a[1], b + 2);
            }
        }
        if (kt + 3 < 32) LOAD_STAGE(kt + 3, (kt + 3) & 3);
        CP_COMMIT();
    }
#undef LOAD_STAGE

#pragma unroll
    for (int mf = 0; mf < 2; mf++) {
        const int r0 = m0 + wm * 32 + mf * 16 + qr;
#pragma unroll
        for (int nf = 0; nf < 8; nf++) {
            const int c0 = n0 + wn * 64 + nf * 8 + qc * 2;
            if (HALF) {
                *(uint32_t*)&Yh[(size_t)r0 * 1024 + c0] =
                    pack2(acc[mf][nf][0], acc[mf][nf][1]);
                *(uint32_t*)&Yh[(size_t)(r0 + 8) * 1024 + c0] =
                    pack2(acc[mf][nf][2], acc[mf][nf][3]);
            } else {
                *(float2*)&Yf[(size_t)r0 * 1024 + c0] =
                    make_float2(acc[mf][nf][0], acc[mf][nf][1]);
                *(float2*)&Yf[(size_t)(r0 + 8) * 1024 + c0] =
                    make_float2(acc[mf][nf][2], acc[mf][nf][3]);
            }
        }
    }
}

// ---------------------------------------------------------------------------
// Hedgehog softmax (matmul folded into the GEMM weights)
// ---------------------------------------------------------------------------
__global__ __launch_bounds__(256) void hh_soft(
    const float* __restrict__ biasq, const float* __restrict__ biask)
{
    const int z = blockIdx.z;
    const __half* src = z ? g_k : g_q;
    __half* dst = z ? g_kf : g_qf;
    const float* bias = z ? biask : biasq;
    const float scale = z ? 1.0f : 0.0625f;   // 256^-0.5 folded into qf

    const int wid = threadIdx.x >> 5, lane = threadIdx.x & 31;
    const int r = blockIdx.x * 8 + wid;
    const int t = r >> 3, h = r & 7;

    uint2 raw = *(const uint2*)(src + (size_t)t * HIDc + h * 128 + lane * 4);
    float2 p0 = __half22float2(*(__half2*)&raw.x);
    float2 p1 = __half22float2(*(__half2*)&raw.y);
    float4 bv = *(const float4*)(bias + lane * 4);

    float y[4];
    y[0] = 2.f * (p0.x + bv.x); y[1] = 2.f * (p0.y + bv.y);
    y[2] = 2.f * (p1.x + bv.z); y[3] = 2.f * (p1.y + bv.w);

    float m = fmaxf(fmaxf(fabsf(y[0]), fabsf(y[1])), fmaxf(fabsf(y[2]), fabsf(y[3])));
#pragma unroll
    for (int off = 16; off >= 1; off >>= 1)
        m = fmaxf(m, __shfl_xor_sync(0xffffffffu, m, off));

    float ep[4], en[4], zs = 0.f;
#pragma unroll
    for (int j = 0; j < 4; j++) {
        ep[j] = __expf( y[j] - m);
        en[j] = __expf(-y[j] - m);
        zs += ep[j] + en[j];
    }
#pragma unroll
    for (int off = 16; off >= 1; off >>= 1)
        zs += __shfl_xor_sync(0xffffffffu, zs, off);
    const float inv = scale / zs;

    __half* drow = dst + (size_t)r * Fc;
    *(uint2*)(drow + lane * 4) =
        make_uint2(pack2(ep[0]*inv, ep[1]*inv), pack2(ep[2]*inv, ep[3]*inv));
    *(uint2*)(drow + 128 + lane * 4) =
        make_uint2(pack2(en[0]*inv, en[1]*inv), pack2(en[2]*inv, en[3]*inv));
}

// ---------------------------------------------------------------------------
// KV per chunk (fp16 mma): KV[d,e] = sum_c kf[c,d] * v[c,e]  (256 x 128)
// ---------------------------------------------------------------------------
#define KVQ 0
#define KVV 33792
#define KV_SMEM 51200

__global__ __launch_bounds__(512) void kv_kernel()
{
    extern __shared__ char smc[];
    const uint32_t sb = smem_u32(smc);
    const int chunk = blockIdx.x, h = blockIdx.y, b = blockIdx.z;
    const int tid = threadIdx.x, wid = tid >> 5, lane = tid & 31;
    const int wm = wid & 3, wn = wid >> 2;
    const int g = lane >> 2, t4 = lane & 3;
    const int t0 = chunk * 64;

    const size_t kbase = ((size_t)(b*Tc + t0) * Hc + h) * Fc;
#pragma unroll
    for (int i = 0; i < 4; i++) {
        int l = tid + i * 512;
        int r = l >> 5, p = l & 31;
        *(uint4*)(smc + KVQ + ((uint32_t)r * 264 + p * 8) * 2) =
            *(const uint4*)(&g_kf[kbase + (size_t)r * (Hc*Fc) + p * 8]);
    }
#pragma unroll
    for (int i = 0; i < 2; i++) {
        int l = tid + i * 512;
        int r = l >> 4, p = l & 15;
        *(uint4*)(smc + KVV + ((uint32_t)r * 136 + p * 8) * 2) =
            *(const uint4*)(&g_v[(size_t)(b*Tc + t0 + r) * HIDc + h * 128 + p * 8]);
    }
    __syncthreads();

    float acc[4][4][4];
#pragma unroll
    for (int mf = 0; mf < 4; mf++)
#pragma unroll
        for (int nf = 0; nf < 4; nf++)
#pragma unroll
            for (int i = 0; i < 4; i++) acc[mf][nf][i] = 0.f;

    const uint32_t ca = (lane & 7) + ((lane >> 4) & 1) * 8;
    const uint32_t ma = ((lane >> 3) & 1) * 8;
    const uint32_t cb = (lane & 7) + ((lane >> 3) & 1) * 8;
    const uint32_t nb = (lane >> 4) * 8;

#pragma unroll
    for (int ks = 0; ks < 4; ks++) {
        uint32_t bb[2][4];
#pragma unroll
        for (int np = 0; np < 2; np++)
            LDSM4T(bb[np], sb + KVV + ((ks*16 + cb) * 136 + wn*32 + np*16 + nb) * 2);
#pragma unroll
        for (int mf = 0; mf < 4; mf++) {
            uint32_t a[4];
            LDSM4T(a, sb + KVQ + ((ks*16 + ca) * 264 + wm*64 + mf*16 + ma) * 2);
            mma_f16(acc[mf][0], a, bb[0]);
            mma_f16(acc[mf][1], a, bb[0] + 2);
            mma_f16(acc[mf][2], a, bb[1]);
            mma_f16(acc[mf][3], a, bb[1] + 2);
        }
    }

    const size_t base = (((size_t)(b*Hc + h)) * NCc + chunk) * (size_t)(Fc * Dc);
#pragma unroll
    for (int mf = 0; mf < 4; mf++)
#pragma unroll
        for (int nf = 0; nf < 4; nf++) {
            int d = wm * 64 + mf * 16 + g;
            int e = wn * 32 + nf * 8 + t4 * 2;
            *(uint32_t*)&g_kvh[base + (size_t)d * 128 + e] =
                pack2(acc[mf][nf][0], acc[mf][nf][1]);
            *(uint32_t*)&g_kvh[base + (size_t)(d + 8) * 128 + e] =
                pack2(acc[mf][nf][2], acc[mf][nf][3]);
        }
}

// ---------------------------------------------------------------------------
// Exclusive prefix over chunks, fp16 in, f32 accumulate, fp16 out.
// Software-pipelined: prefetch chunk i+1 while storing chunk i.
// ---------------------------------------------------------------------------
__global__ __launch_bounds__(256) void prefix_kernel()
{
    const int bh  = blockIdx.y;
    const int idx = (blockIdx.x * 256 + threadIdx.x) * 2;
    const size_t stride = (size_t)Fc * Dc;
    size_t p = (size_t)bh * NCc * stride + idx;
    float ax = 0.f, ay = 0.f;
    __half2 cur = *(const __half2*)&g_kvh[p];
    for (int i = 0; i < NCc; i++) {
        __half2 nxt;
        if (i + 1 < NCc) nxt = *(const __half2*)&g_kvh[p + stride];
        float2 t = __half22float2(cur);
        *(uint32_t*)&g_s[p] = pack2(ax, ay);
        ax += t.x; ay += t.y;
        cur = nxt;
        p += stride;
    }
}

// ---------------------------------------------------------------------------
// Output per chunk (fp16 mma): o = tril(qf @ kf^T) @ v + qf @ S  -> fp16
// ---------------------------------------------------------------------------
#define OQF 0
#define OKF 33792
#define OV  67584
#define OAT 84992
#define OS  94208
#define OUT_SMEM 163840

__global__ __launch_bounds__(256) void out_kernel()
{
    extern __shared__ char smc[];
    const uint32_t sb = smem_u32(smc);
    const int chunk = blockIdx.x, h = blockIdx.y, b = blockIdx.z;
    const int tid = threadIdx.x, wid = tid >> 5, lane = tid & 31;
    const int g = lane >> 2, t4 = lane & 3;
    const int t0 = chunk * 64;

    const size_t qbase = ((size_t)(b*Tc + t0) * Hc + h) * Fc;
#pragma unroll
    for (int i = 0; i < 8; i++) {
        int l = tid + i * 256;
        int r = l >> 5, p = l & 31;
        size_t gs = qbase + (size_t)r * (Hc*Fc) + p * 8;
        *(uint4*)(smc + OQF + ((uint32_t)r * 264 + p * 8) * 2) = *(const uint4*)(&g_qf[gs]);
        *(uint4*)(smc + OKF + ((uint32_t)r * 264 + p * 8) * 2) = *(const uint4*)(&g_kf[gs]);
    }
#pragma unroll
    for (int i = 0; i < 4; i++) {
        int l = tid + i * 256;
        int r = l >> 4, p = l & 15;
        *(uint4*)(smc + OV + ((uint32_t)r * 136 + p * 8) * 2) =
            *(const uint4*)(&g_v[(size_t)(b*Tc + t0 + r) * HIDc + h * 128 + p * 8]);
    }
    const size_t sbase = (((size_t)(b*Hc + h)) * NCc + chunk) * (size_t)(Fc * Dc);
#pragma unroll
    for (int i = 0; i < 16; i++) {
        int l = tid + i * 256;
        int f = l >> 4, p = l & 15;
        *(uint4*)(smc + OS + ((uint32_t)f * 136 + p * 8) * 2) =
            *(const uint4*)(&g_s[sbase + (size_t)f * 128 + p * 8]);
    }
    __syncthreads();

    // phase 1: scores = tril(qf @ kf^T)
    {
        const int wm = wid & 1, wn = wid >> 1;
        float sc[2][2][4];
#pragma unroll
        for (int mf = 0; mf < 2; mf++)
#pragma unroll
            for (int nf = 0; nf < 2; nf++)
#pragma unroll
                for (int i = 0; i < 4; i++) sc[mf][nf][i] = 0.f;

        const uint32_t aoff = OQF + (uint32_t)(wm*32 + (lane&7) + ((lane>>3)&1)*8) * 528
                            + (lane>>4)*16;
        const uint32_t boff = OKF + (uint32_t)(wn*16 + (lane>>4)*8 + (lane&7)) * 528
                            + ((lane>>3)&1)*16;
#pragma unroll
        for (int ks = 0; ks < 16; ks++) {
            uint32_t a[2][4], bbf[4];
            LDSM4(a[0], sb + aoff + ks * 32);
            LDSM4(a[1], sb + aoff + 16 * 528 + ks * 32);
            LDSM4(bbf, sb + boff + ks * 32);
            mma_f16(sc[0][0], a[0], bbf);
            mma_f16(sc[0][1], a[0], bbf + 2);
            mma_f16(sc[1][0], a[1], bbf);
            mma_f16(sc[1][1], a[1], bbf + 2);
        }
#pragma unroll
        for (int mf = 0; mf < 2; mf++)
#pragma unroll
            for (int nf = 0; nf < 2; nf++) {
                int ci = wm*32 + mf*16 + g;
                int cj = wn*16 + nf*8 + t4*2;
                float v0 = (cj     <= ci) ? sc[mf][nf][0] : 0.f;
                float v1 = (cj + 1 <= ci) ? sc[mf][nf][1] : 0.f;
                *(uint32_t*)(smc + OAT + ((uint32_t)ci * 72 + cj) * 2) = pack2(v0, v1);
                int ci2 = ci + 8;
                float v2 = (cj     <= ci2) ? sc[mf][nf][2] : 0.f;
                float v3 = (cj + 1 <= ci2) ? sc[mf][nf][3] : 0.f;
                *(uint32_t*)(smc + OAT + ((uint32_t)ci2 * 72 + cj) * 2) = pack2(v2, v3);
            }
    }
    __syncthreads();

    // phase 2: o = attn @ v + qf @ S
    {
        const int wm = wid & 1, wn = wid >> 1;
        float o[2][4][4];
#pragma unroll
        for (int mf = 0; mf < 2; mf++)
#pragma unroll
            for (int nf = 0; nf < 4; nf++)
#pragma unroll
                for (int i = 0; i < 4; i++) o[mf][nf][i] = 0.f;

        const uint32_t cb = (lane & 7) + ((lane >> 3) & 1) * 8;
        const uint32_t nb = (lane >> 4) * 8;

        const uint32_t a1 = OAT + (uint32_t)(wm*32 + (lane&7) + ((lane>>3)&1)*8) * 144
                          + (lane>>4)*16;
#pragma unroll
        for (int ks = 0; ks < 4; ks++) {
            uint32_t a[2][4];
            LDSM4(a[0], sb + a1 + ks * 32);
            LDSM4(a[1], sb + a1 + 16 * 144 + ks * 32);
#pragma unroll
            for (int np = 0; np < 2; np++) {
                uint32_t bbf[4];
                LDSM4T(bbf, sb + OV + ((ks*16 + cb) * 136 + wn*32 + np*16 + nb) * 2);
                mma_f16(o[0][2*np],   a[0], bbf);
                mma_f16(o[0][2*np+1], a[0], bbf + 2);
                mma_f16(o[1][2*np],   a[1], bbf);
                mma_f16(o[1][2*np+1], a[1], bbf + 2);
            }
        }
        const uint32_t a2 = OQF + (uint32_t)(wm*32 + (lane&7) + ((lane>>3)&1)*8) * 528
                          + (lane>>4)*16;
#pragma unroll
        for (int ks = 0; ks < 16; ks++) {
            uint32_t a[2][4];
            LDSM4(a[0], sb + a2 + ks * 32);
            LDSM4(a[1], sb + a2 + 16 * 528 + ks * 32);
#pragma unroll
            for (int np = 0; np < 2; np++) {
                uint32_t bbf[4];
                LDSM4T(bbf, sb + OS + ((ks*16 + cb) * 136 + wn*32 + np*16 + nb) * 2);
                mma_f16(o[0][2*np],   a[0], bbf);
                mma_f16(o[0][2*np+1], a[0], bbf + 2);
                mma_f16(o[1][2*np],   a[1], bbf);
                mma_f16(o[1][2*np+1], a[1], bbf + 2);
            }
        }
#pragma unroll
        for (int mf = 0; mf < 2; mf++)
#pragma unroll
            for (int nf = 0; nf < 4; nf++) {
                int r = t0 + wm*32 + mf*16 + g;
                int e = wn*32 + nf*8 + t4*2;
                size_t base = (size_t)(b*Tc + r) * HIDc + h * 128 + e;
                *(uint32_t*)&g_oh[base] = pack2(o[mf][nf][0], o[mf][nf][1]);
                *(uint32_t*)&g_oh[base + (size_t)8 * HIDc] =
                    pack2(o[mf][nf][2], o[mf][nf][3]);
            }
    }
}

// ---------------------------------------------------------------------------
// RMSNorm over last dim 1024, fp16 in-place in g_oh
// ---------------------------------------------------------------------------
__global__ __launch_bounds__(256) void rmsnorm_kernel()
{
    const int t = blockIdx.x;
    __half2* row = (__half2*)(g_oh + (size_t)t * HIDc);
    const int tid = threadIdx.x;

    float2 v0 = __half22float2(row[tid]);
    float2 v1 = __half22float2(row[tid + 256]);
    float s = v0.x*v0.x + v0.y*v0.y + v1.x*v1.x + v1.y*v1.y;
#pragma unroll
    for (int off = 16; off >= 1; off >>= 1)
        s += __shfl_xor_sync(0xffffffffu, s, off);

    __shared__ float wsum[8];
    if ((tid & 31) == 0) wsum[tid >> 5] = s;
    __syncthreads();
    float tot = 0.f;
#pragma unroll
    for (int w = 0; w < 8; w++) tot += wsum[w];

    const float r = rsqrtf(tot * (1.f / HIDc) + 1e-5f);
    row[tid]       = __floats2half2_rn(v0.x * r, v0.y * r);
    row[tid + 256] = __floats2half2_rn(v1.x * r, v1.y * r);
}

// ---------------------------------------------------------------------------
// Launch
// ---------------------------------------------------------------------------
extern "C" void kernel_launch(void* const* d_in, const int* in_sizes, int n_in,
                              void* d_out, int out_size)
{
    const float* x    = (const float*)d_in[0];
    const float* Wq   = (const float*)d_in[1];
    const float* Wk   = (const float*)d_in[2];
    const float* Wv   = (const float*)d_in[3];
    const float* Wo   = (const float*)d_in[4];
    const float* fmqw = (const float*)d_in[5];
    const float* fmqb = (const float*)d_in[6];
    const float* fmkw = (const float*)d_in[7];
    const float* fmkb = (const float*)d_in[8];
    float* out = (float*)d_out;

    __half *xh, *wvh, *woh, *wq2, *wk2, *qh, *kh, *vh, *oh;
    cudaGetSymbolAddress((void**)&xh,  g_xh);
    cudaGetSymbolAddress((void**)&wvh, g_wvh);
    cudaGetSymbolAddress((void**)&woh, g_woh);
    cudaGetSymbolAddress((void**)&wq2, g_wq2);
    cudaGetSymbolAddress((void**)&wk2, g_wk2);
    cudaGetSymbolAddress((void**)&qh,  g_q);
    cudaGetSymbolAddress((void**)&kh,  g_k);
    cudaGetSymbolAddress((void**)&vh,  g_v);
    cudaGetSymbolAddress((void**)&oh,  g_oh);

    cudaFuncSetAttribute(gemm_t<1>, cudaFuncAttributeMaxDynamicSharedMemorySize, GEMM_SMEM);
    cudaFuncSetAttribute(gemm_t<0>, cudaFuncAttributeMaxDynamicSharedMemorySize, GEMM_SMEM);
    cudaFuncSetAttribute(fold_w,    cudaFuncAttributeMaxDynamicSharedMemorySize, FOLD_SMEM);
    cudaFuncSetAttribute(kv_kernel, cudaFuncAttributeMaxDynamicSharedMemorySize, KV_SMEM);
    cudaFuncSetAttribute(out_kernel,cudaFuncAttributeMaxDynamicSharedMemorySize, OUT_SMEM);

    // conversions + weight folding
    f2h<<<MTOT*HIDc/2048, 256>>>(x, xh, MTOT*HIDc);
    wconv<<<dim3(HIDc*HIDc/2048, 1, 4), 256>>>(Wq, Wk, Wv, Wo);
    fold_w<<<dim3(8, 8, 2), 256, FOLD_SMEM>>>(fmqw, fmkw);

    // fused QKV GEMM (q,k use folded weights -> y directly)
    gemm_t<1><<<dim3(HIDc/128, MTOT/128, 3), 256, GEMM_SMEM>>>(
        xh, wq2, wk2, wvh, qh, kh, vh, nullptr);

    // softmax-only hedgehog
    hh_soft<<<dim3(MTOT*Hc/8, 1, 2), 256>>>(fmqb, fmkb);

    dim3 cg(NCc, Hc, Bc);
    kv_kernel<<<cg, 512, KV_SMEM>>>();
    prefix_kernel<<<dim3(64, Bc*Hc), 256>>>();
    out_kernel<<<cg, 256, OUT_SMEM>>>();

    rmsnorm_kernel<<<MTOT, 256>>>();
    gemm_t<0><<<dim3(HIDc/128, MTOT/128, 1), 256, GEMM_SMEM>>>(
        oh, woh, woh, woh, nullptr, nullptr, nullptr, out);
}

// round 9
// speedup vs baseline: 1.1914x; 1.0722x over previous
#include <cuda_runtime.h>
#include <cuda_fp16.h>
#include <cstdint>
#include <math.h>

// Problem constants
#define Bc   2
#define Tc   8192
#define Hc   8
#define Dc   128
#define HIDc 1024
#define NCc  128          // T / CHUNK
#define Fc   256          // hedgehog feature dim (2*DQK)
#define MTOT (Bc*Tc)      // 16384 tokens

// ---------------------------------------------------------------------------
// Scratch (device globals — no allocations allowed)
// ---------------------------------------------------------------------------
__device__ __half g_xh  [(size_t)MTOT*HIDc];      // 32 MB
__device__ __half g_wqh [HIDc*HIDc];
__device__ __half g_wkh [HIDc*HIDc];
__device__ __half g_wvh [HIDc*HIDc];
__device__ __half g_woh [HIDc*HIDc];
__device__ __half g_wq2 [HIDc*HIDc];              // folded fmq @ Wq (per head)
__device__ __half g_wk2 [HIDc*HIDc];              // folded fmk @ Wk
__device__ __half g_q   [(size_t)MTOT*HIDc];      // y_q = x @ Wq2^T
__device__ __half g_k   [(size_t)MTOT*HIDc];      // y_k
__device__ __half g_v   [(size_t)MTOT*HIDc];
__device__ __half g_qf  [(size_t)MTOT*Hc*Fc];     // 64 MB (pre-scaled)
__device__ __half g_kf  [(size_t)MTOT*Hc*Fc];     // 64 MB
__device__ __half g_kvh [(size_t)Bc*Hc*NCc*Fc*Dc]; // 128 MB per-chunk KV (fp16)
__device__ __half g_s   [(size_t)Bc*Hc*NCc*Fc*Dc]; // 128 MB exclusive prefix (fp16)
__device__ __half g_oh  [(size_t)MTOT*HIDc];      // attention out / rmsnorm in-place

// ---------------------------------------------------------------------------
// Helpers
// ---------------------------------------------------------------------------
__device__ __forceinline__ uint32_t smem_u32(const void* p) {
    uint32_t a;
    asm("{ .reg .u64 t; cvta.to.shared.u64 t, %1; cvt.u32.u64 %0, t; }" : "=r"(a) : "l"(p));
    return a;
}
__device__ __forceinline__ uint32_t pack2(float lo, float hi) {
    __half2 h = __floats2half2_rn(lo, hi);
    return *reinterpret_cast<uint32_t*>(&h);
}
__device__ __forceinline__ void mma_f16(float* c, const uint32_t* a, const uint32_t* b) {
    asm volatile(
        "mma.sync.aligned.m16n8k16.row.col.f32.f16.f16.f32 "
        "{%0,%1,%2,%3}, {%4,%5,%6,%7}, {%8,%9}, {%0,%1,%2,%3};"
        : "+f"(c[0]), "+f"(c[1]), "+f"(c[2]), "+f"(c[3])
        : "r"(a[0]), "r"(a[1]), "r"(a[2]), "r"(a[3]), "r"(b[0]), "r"(b[1]));
}
#define LDSM4(r, addr) \
    asm volatile("ldmatrix.sync.aligned.m8n8.x4.shared.b16 {%0,%1,%2,%3}, [%4];" \
        : "=r"((r)[0]), "=r"((r)[1]), "=r"((r)[2]), "=r"((r)[3]) : "r"(addr))
#define LDSM4T(r, addr) \
    asm volatile("ldmatrix.sync.aligned.m8n8.x4.trans.shared.b16 {%0,%1,%2,%3}, [%4];" \
        : "=r"((r)[0]), "=r"((r)[1]), "=r"((r)[2]), "=r"((r)[3]) : "r"(addr))
__device__ __forceinline__ void cp16(uint32_t dst, const void* src) {
    asm volatile("cp.async.cg.shared.global [%0], [%1], 16;" :: "r"(dst), "l"(src) : "memory");
}
#define CP_COMMIT() asm volatile("cp.async.commit_group;" ::: "memory")
#define CP_WAIT(n)  asm volatile("cp.async.wait_group %0;" :: "n"(n) : "memory")

// ---------------------------------------------------------------------------
// f32 -> f16 conversion (n multiple of 2048)
// ---------------------------------------------------------------------------
__global__ __launch_bounds__(256) void f2h(const float* __restrict__ s,
                                           __half* __restrict__ d, int n)
{
    int i = (blockIdx.x * 256 + threadIdx.x) * 8;
    if (i < n) {
        float4 a = *(const float4*)(s + i), b = *(const float4*)(s + i + 4);
        *(uint4*)(d + i) = make_uint4(pack2(a.x, a.y), pack2(a.z, a.w),
                                      pack2(b.x, b.y), pack2(b.z, b.w));
    }
}
// 4 weight matrices in one launch (grid.z selects)
__global__ __launch_bounds__(256) void wconv(
    const float* __restrict__ w0, const float* __restrict__ w1,
    const float* __restrict__ w2, const float* __restrict__ w3)
{
    const int z = blockIdx.z;
    const float* s = (z == 0) ? w0 : (z == 1) ? w1 : (z == 2) ? w2 : w3;
    __half* d = (z == 0) ? g_wqh : (z == 1) ? g_wkh : (z == 2) ? g_wvh : g_woh;
    int i = (blockIdx.x * 256 + threadIdx.x) * 8;
    float4 a = *(const float4*)(s + i), b = *(const float4*)(s + i + 4);
    *(uint4*)(d + i) = make_uint4(pack2(a.x, a.y), pack2(a.z, a.w),
                                  pack2(b.x, b.y), pack2(b.z, b.w));
}

// ---------------------------------------------------------------------------
// Fold: W2[h*128+i, c] = sum_j fm[i,j] * W[h*128+j, c]
// ---------------------------------------------------------------------------
#define FSKP 136
#define FD_A 0
#define FD_B (128*FSKP*2)               // 34816
#define FOLD_SMEM (2*128*FSKP*2)        // 69632

__global__ __launch_bounds__(256) void fold_w(
    const float* __restrict__ fmq, const float* __restrict__ fmk)
{
    const int z = blockIdx.z;
    const float* fm = z ? fmk : fmq;
    const __half* W = z ? g_wkh : g_wqh;
    __half* W2 = z ? g_wk2 : g_wq2;

    extern __shared__ char smc[];
    const uint32_t sb = smem_u32(smc);
    const int tid = threadIdx.x, wid = tid >> 5, lane = tid & 31;
    const int wm = wid & 3, wn = wid >> 2;
    const int qr = lane >> 2, qc = lane & 3;
    const int ct = blockIdx.x, h = blockIdx.y;

#pragma unroll
    for (int it = 0; it < 16; it++) {
        int e = tid + it * 256;
        int r = e >> 5, c4 = e & 31;
        float4 f = *(const float4*)(fm + r * 128 + c4 * 4);
        *(uint2*)(smc + FD_A + ((uint32_t)r * FSKP + c4 * 4) * 2) =
            make_uint2(pack2(f.x, f.y), pack2(f.z, f.w));
    }
#pragma unroll
    for (int it = 0; it < 8; it++) {
        int e = tid + it * 256;
        int r = e >> 4, p = e & 15;
        *(uint4*)(smc + FD_B + ((uint32_t)r * FSKP + p * 8) * 2) =
            *(const uint4*)(&W[(size_t)(h * 128 + r) * 1024 + ct * 128 + p * 8]);
    }
    __syncthreads();

    float acc[2][8][4];
#pragma unroll
    for (int mf = 0; mf < 2; mf++)
#pragma unroll
        for (int nf = 0; nf < 8; nf++)
#pragma unroll
            for (int i = 0; i < 4; i++) acc[mf][nf][i] = 0.f;

    const uint32_t a_off = FD_A + (uint32_t)(wm*32 + (lane&7) + ((lane>>3)&1)*8) * (FSKP*2)
                         + (lane>>4)*16;
    const uint32_t cb = (lane & 7) + ((lane >> 3) & 1) * 8;
    const uint32_t nb = (lane >> 4) * 8;

#pragma unroll
    for (int ks = 0; ks < 8; ks++) {
        uint32_t a[2][4];
        LDSM4(a[0], sb + a_off + ks * 32);
        LDSM4(a[1], sb + a_off + 16 * FSKP * 2 + ks * 32);
#pragma unroll
        for (int np = 0; np < 4; np++) {
            uint32_t b[4];
            LDSM4T(b, sb + FD_B + ((ks*16 + cb) * FSKP + wn*64 + np*16 + nb) * 2);
            mma_f16(acc[0][2*np],   a[0], b);
            mma_f16(acc[0][2*np+1], a[0], b + 2);
            mma_f16(acc[1][2*np],   a[1], b);
            mma_f16(acc[1][2*np+1], a[1], b + 2);
        }
    }

#pragma unroll
    for (int mf = 0; mf < 2; mf++) {
        const int i0 = h * 128 + wm * 32 + mf * 16 + qr;
#pragma unroll
        for (int nf = 0; nf < 8; nf++) {
            const int c0 = ct * 128 + wn * 64 + nf * 8 + qc * 2;
            *(uint32_t*)&W2[(size_t)i0 * 1024 + c0] = pack2(acc[mf][nf][0], acc[mf][nf][1]);
            *(uint32_t*)&W2[(size_t)(i0 + 8) * 1024 + c0] = pack2(acc[mf][nf][2], acc[mf][nf][3]);
        }
    }
}

// ---------------------------------------------------------------------------
// fp16 GEMM: Y[M,1024] = X[M,1024] @ W[1024,1024]^T
// CTA 128x128, BK=64, 3-stage cp.async, 8 warps 4x2, warp tile 32x64.
// 2 CTAs/SM. grid (8, M/128, nz); z selects (W, Y).
// ---------------------------------------------------------------------------
#define SKP_B   144                   // 64 halves + 8 pad = 144 bytes per row
#define GA_B    (128*SKP_B)           // 18432
#define GSTG    (2*GA_B)              // 36864
#define GEMM_SMEM (3*GSTG)            // 110592

template<int HALF>
__global__ __launch_bounds__(256, 2) void gemm_t(
    const __half* __restrict__ X,
    const __half* __restrict__ W0, const __half* __restrict__ W1,
    const __half* __restrict__ W2,
    __half* __restrict__ Y0, __half* __restrict__ Y1, __half* __restrict__ Y2,
    float* __restrict__ Yf)
{
    const int z = blockIdx.z;
    const __half* W = (z == 0) ? W0 : ((z == 1) ? W1 : W2);
    __half* Yh = (z == 0) ? Y0 : ((z == 1) ? Y1 : Y2);

    extern __shared__ char smc[];
    const uint32_t sb = smem_u32(smc);
    const int tid = threadIdx.x, wid = tid >> 5, lane = tid & 31;
    const int wm = wid & 3, wn = wid >> 2;
    const int qr = lane >> 2, qc = lane & 3;
    const int m0 = blockIdx.y * 128, n0 = blockIdx.x * 128;

    // producer: pr row base (0..31), pp 16B-chunk column (0..7)
    const int pr = tid >> 3, pp = tid & 7;
    const __half* Xp = X + (size_t)(m0 + pr) * 1024 + pp * 8;
    const __half* Wp = W + (size_t)(n0 + pr) * 1024 + pp * 8;

    const uint32_t a_off = (uint32_t)(wm*32 + (lane&7) + ((lane>>3)&1)*8) * SKP_B
                         + (lane>>4)*16;
    const uint32_t b_off = (uint32_t)(wn*64 + (lane>>4)*8 + (lane&7)) * SKP_B
                         + ((lane>>3)&1)*16;

    float acc[2][8][4];
#pragma unroll
    for (int mf = 0; mf < 2; mf++)
#pragma unroll
        for (int nf = 0; nf < 8; nf++)
#pragma unroll
            for (int i = 0; i < 4; i++) acc[mf][nf][i] = 0.f;

#define LOAD_STAGE(kt, st) {                                              \
    uint32_t base = sb + (st) * GSTG;                                     \
    const __half* xk = Xp + (kt) * 64;                                    \
    const __half* wk = Wp + (kt) * 64;                                    \
    _Pragma("unroll")                                                     \
    for (int i = 0; i < 4; i++) {                                         \
        uint32_t so = (uint32_t)(pr + 32*i) * SKP_B + pp * 16;            \
        cp16(base + so, xk + (size_t)(32*i) * 1024);                      \
        cp16(base + GA_B + so, wk + (size_t)(32*i) * 1024);               \
    } }

    LOAD_STAGE(0, 0); CP_COMMIT();
    LOAD_STAGE(1, 1); CP_COMMIT();

    for (int kt = 0; kt < 16; kt++) {
        const int st = kt % 3;
        CP_WAIT(1);
        __syncthreads();
        const uint32_t As = sb + st * GSTG, Bs = As + GA_B;
#pragma unroll
        for (int ks = 0; ks < 4; ks++) {
            uint32_t a[2][4];
            LDSM4(a[0], As + a_off + ks * 32);
            LDSM4(a[1], As + a_off + 16 * SKP_B + ks * 32);
#pragma unroll
            for (int np = 0; np < 4; np++) {
                uint32_t b[4];
                LDSM4(b, Bs + b_off + np * (16 * SKP_B) + ks * 32);
                mma_f16(acc[0][2*np],   a[0], b);
                mma_f16(acc[0][2*np+1], a[0], b + 2);
                mma_f16(acc[1][2*np],   a[1], b);
                mma_f16(acc[1][2*np+1], a[1], b + 2);
            }
        }
        if (kt + 2 < 16) LOAD_STAGE(kt + 2, (kt + 2) % 3);
        CP_COMMIT();
    }
#undef LOAD_STAGE

#pragma unroll
    for (int mf = 0; mf < 2; mf++) {
        const int r0 = m0 + wm * 32 + mf * 16 + qr;
#pragma unroll
        for (int nf = 0; nf < 8; nf++) {
            const int c0 = n0 + wn * 64 + nf * 8 + qc * 2;
            if (HALF) {
                *(uint32_t*)&Yh[(size_t)r0 * 1024 + c0] =
                    pack2(acc[mf][nf][0], acc[mf][nf][1]);
                *(uint32_t*)&Yh[(size_t)(r0 + 8) * 1024 + c0] =
                    pack2(acc[mf][nf][2], acc[mf][nf][3]);
            } else {
                *(float2*)&Yf[(size_t)r0 * 1024 + c0] =
                    make_float2(acc[mf][nf][0], acc[mf][nf][1]);
                *(float2*)&Yf[(size_t)(r0 + 8) * 1024 + c0] =
                    make_float2(acc[mf][nf][2], acc[mf][nf][3]);
            }
        }
    }
}

// ---------------------------------------------------------------------------
// Hedgehog softmax (matmul folded into the GEMM weights)
// ---------------------------------------------------------------------------
__global__ __launch_bounds__(256) void hh_soft(
    const float* __restrict__ biasq, const float* __restrict__ biask)
{
    const int z = blockIdx.z;
    const __half* src = z ? g_k : g_q;
    __half* dst = z ? g_kf : g_qf;
    const float* bias = z ? biask : biasq;
    const float scale = z ? 1.0f : 0.0625f;   // 256^-0.5 folded into qf

    const int wid = threadIdx.x >> 5, lane = threadIdx.x & 31;
    const int r = blockIdx.x * 8 + wid;
    const int t = r >> 3, h = r & 7;

    uint2 raw = *(const uint2*)(src + (size_t)t * HIDc + h * 128 + lane * 4);
    float2 p0 = __half22float2(*(__half2*)&raw.x);
    float2 p1 = __half22float2(*(__half2*)&raw.y);
    float4 bv = *(const float4*)(bias + lane * 4);

    float y[4];
    y[0] = 2.f * (p0.x + bv.x); y[1] = 2.f * (p0.y + bv.y);
    y[2] = 2.f * (p1.x + bv.z); y[3] = 2.f * (p1.y + bv.w);

    float m = fmaxf(fmaxf(fabsf(y[0]), fabsf(y[1])), fmaxf(fabsf(y[2]), fabsf(y[3])));
#pragma unroll
    for (int off = 16; off >= 1; off >>= 1)
        m = fmaxf(m, __shfl_xor_sync(0xffffffffu, m, off));

    float ep[4], en[4], zs = 0.f;
#pragma unroll
    for (int j = 0; j < 4; j++) {
        ep[j] = __expf( y[j] - m);
        en[j] = __expf(-y[j] - m);
        zs += ep[j] + en[j];
    }
#pragma unroll
    for (int off = 16; off >= 1; off >>= 1)
        zs += __shfl_xor_sync(0xffffffffu, zs, off);
    const float inv = scale / zs;

    __half* drow = dst + (size_t)r * Fc;
    *(uint2*)(drow + lane * 4) =
        make_uint2(pack2(ep[0]*inv, ep[1]*inv), pack2(ep[2]*inv, ep[3]*inv));
    *(uint2*)(drow + 128 + lane * 4) =
        make_uint2(pack2(en[0]*inv, en[1]*inv), pack2(en[2]*inv, en[3]*inv));
}

// ---------------------------------------------------------------------------
// KV per chunk (fp16 mma): KV[d,e] = sum_c kf[c,d] * v[c,e]  (256 x 128)
// ---------------------------------------------------------------------------
#define KVQ 0
#define KVV 33792
#define KV_SMEM 51200

__global__ __launch_bounds__(512) void kv_kernel()
{
    extern __shared__ char smc[];
    const uint32_t sb = smem_u32(smc);
    const int chunk = blockIdx.x, h = blockIdx.y, b = blockIdx.z;
    const int tid = threadIdx.x, wid = tid >> 5, lane = tid & 31;
    const int wm = wid & 3, wn = wid >> 2;
    const int g = lane >> 2, t4 = lane & 3;
    const int t0 = chunk * 64;

    const size_t kbase = ((size_t)(b*Tc + t0) * Hc + h) * Fc;
#pragma unroll
    for (int i = 0; i < 4; i++) {
        int l = tid + i * 512;
        int r = l >> 5, p = l & 31;
        *(uint4*)(smc + KVQ + ((uint32_t)r * 264 + p * 8) * 2) =
            *(const uint4*)(&g_kf[kbase + (size_t)r * (Hc*Fc) + p * 8]);
    }
#pragma unroll
    for (int i = 0; i < 2; i++) {
        int l = tid + i * 512;
        int r = l >> 4, p = l & 15;
        *(uint4*)(smc + KVV + ((uint32_t)r * 136 + p * 8) * 2) =
            *(const uint4*)(&g_v[(size_t)(b*Tc + t0 + r) * HIDc + h * 128 + p * 8]);
    }
    __syncthreads();

    float acc[4][4][4];
#pragma unroll
    for (int mf = 0; mf < 4; mf++)
#pragma unroll
        for (int nf = 0; nf < 4; nf++)
#pragma unroll
            for (int i = 0; i < 4; i++) acc[mf][nf][i] = 0.f;

    const uint32_t ca = (lane & 7) + ((lane >> 4) & 1) * 8;
    const uint32_t ma = ((lane >> 3) & 1) * 8;
    const uint32_t cb = (lane & 7) + ((lane >> 3) & 1) * 8;
    const uint32_t nb = (lane >> 4) * 8;

#pragma unroll
    for (int ks = 0; ks < 4; ks++) {
        uint32_t bb[2][4];
#pragma unroll
        for (int np = 0; np < 2; np++)
            LDSM4T(bb[np], sb + KVV + ((ks*16 + cb) * 136 + wn*32 + np*16 + nb) * 2);
#pragma unroll
        for (int mf = 0; mf < 4; mf++) {
            uint32_t a[4];
            LDSM4T(a, sb + KVQ + ((ks*16 + ca) * 264 + wm*64 + mf*16 + ma) * 2);
            mma_f16(acc[mf][0], a, bb[0]);
            mma_f16(acc[mf][1], a, bb[0] + 2);
            mma_f16(acc[mf][2], a, bb[1]);
            mma_f16(acc[mf][3], a, bb[1] + 2);
        }
    }

    const size_t base = (((size_t)(b*Hc + h)) * NCc + chunk) * (size_t)(Fc * Dc);
#pragma unroll
    for (int mf = 0; mf < 4; mf++)
#pragma unroll
        for (int nf = 0; nf < 4; nf++) {
            int d = wm * 64 + mf * 16 + g;
            int e = wn * 32 + nf * 8 + t4 * 2;
            *(uint32_t*)&g_kvh[base + (size_t)d * 128 + e] =
                pack2(acc[mf][nf][0], acc[mf][nf][1]);
            *(uint32_t*)&g_kvh[base + (size_t)(d + 8) * 128 + e] =
                pack2(acc[mf][nf][2], acc[mf][nf][3]);
        }
}

// ---------------------------------------------------------------------------
// Exclusive prefix over chunks, fp16 in, f32 accumulate, fp16 out.
// Software-pipelined: prefetch chunk i+1 while storing chunk i.
// ---------------------------------------------------------------------------
__global__ __launch_bounds__(256) void prefix_kernel()
{
    const int bh  = blockIdx.y;
    const int idx = (blockIdx.x * 256 + threadIdx.x) * 2;
    const size_t stride = (size_t)Fc * Dc;
    size_t p = (size_t)bh * NCc * stride + idx;
    float ax = 0.f, ay = 0.f;
    __half2 cur = *(const __half2*)&g_kvh[p];
    for (int i = 0; i < NCc; i++) {
        __half2 nxt;
        if (i + 1 < NCc) nxt = *(const __half2*)&g_kvh[p + stride];
        float2 t = __half22float2(cur);
        *(uint32_t*)&g_s[p] = pack2(ax, ay);
        ax += t.x; ay += t.y;
        cur = nxt;
        p += stride;
    }
}

// ---------------------------------------------------------------------------
// Output per chunk (fp16 mma): o = tril(qf @ kf^T) @ v + qf @ S  -> fp16
// S (256x128) streamed in two 128-row halves overlaid on the kf buffer
// (kf dead after phase 1). Smem 93 KB -> 2 CTAs/SM.
// ---------------------------------------------------------------------------
#define OQF 0
#define OKF 33792                     // kf (64x264) / S half (128x136)
#define OV  68608
#define OAT 86016
#define OUT_SMEM 95232

__global__ __launch_bounds__(256, 2) void out_kernel()
{
    extern __shared__ char smc[];
    const uint32_t sb = smem_u32(smc);
    const int chunk = blockIdx.x, h = blockIdx.y, b = blockIdx.z;
    const int tid = threadIdx.x, wid = tid >> 5, lane = tid & 31;
    const int g = lane >> 2, t4 = lane & 3;
    const int t0 = chunk * 64;
    const int wm = wid & 1, wn = wid >> 1;

    const size_t qbase = ((size_t)(b*Tc + t0) * Hc + h) * Fc;
#pragma unroll
    for (int i = 0; i < 8; i++) {
        int l = tid + i * 256;
        int r = l >> 5, p = l & 31;
        size_t gs = qbase + (size_t)r * (Hc*Fc) + p * 8;
        *(uint4*)(smc + OQF + ((uint32_t)r * 264 + p * 8) * 2) = *(const uint4*)(&g_qf[gs]);
        *(uint4*)(smc + OKF + ((uint32_t)r * 264 + p * 8) * 2) = *(const uint4*)(&g_kf[gs]);
    }
#pragma unroll
    for (int i = 0; i < 4; i++) {
        int l = tid + i * 256;
        int r = l >> 4, p = l & 15;
        *(uint4*)(smc + OV + ((uint32_t)r * 136 + p * 8) * 2) =
            *(const uint4*)(&g_v[(size_t)(b*Tc + t0 + r) * HIDc + h * 128 + p * 8]);
    }
    __syncthreads();

    // phase 1: scores = tril(qf @ kf^T)
    {
        float sc[2][2][4];
#pragma unroll
        for (int mf = 0; mf < 2; mf++)
#pragma unroll
            for (int nf = 0; nf < 2; nf++)
#pragma unroll
                for (int i = 0; i < 4; i++) sc[mf][nf][i] = 0.f;

        const uint32_t aoff = OQF + (uint32_t)(wm*32 + (lane&7) + ((lane>>3)&1)*8) * 528
                            + (lane>>4)*16;
        const uint32_t boff = OKF + (uint32_t)(wn*16 + (lane>>4)*8 + (lane&7)) * 528
                            + ((lane>>3)&1)*16;
#pragma unroll
        for (int ks = 0; ks < 16; ks++) {
            uint32_t a[2][4], bbf[4];
            LDSM4(a[0], sb + aoff + ks * 32);
            LDSM4(a[1], sb + aoff + 16 * 528 + ks * 32);
            LDSM4(bbf, sb + boff + ks * 32);
            mma_f16(sc[0][0], a[0], bbf);
            mma_f16(sc[0][1], a[0], bbf + 2);
            mma_f16(sc[1][0], a[1], bbf);
            mma_f16(sc[1][1], a[1], bbf + 2);
        }
#pragma unroll
        for (int mf = 0; mf < 2; mf++)
#pragma unroll
            for (int nf = 0; nf < 2; nf++) {
                int ci = wm*32 + mf*16 + g;
                int cj = wn*16 + nf*8 + t4*2;
                float v0 = (cj     <= ci) ? sc[mf][nf][0] : 0.f;
                float v1 = (cj + 1 <= ci) ? sc[mf][nf][1] : 0.f;
                *(uint32_t*)(smc + OAT + ((uint32_t)ci * 72 + cj) * 2) = pack2(v0, v1);
                int ci2 = ci + 8;
                float v2 = (cj     <= ci2) ? sc[mf][nf][2] : 0.f;
                float v3 = (cj + 1 <= ci2) ? sc[mf][nf][3] : 0.f;
                *(uint32_t*)(smc + OAT + ((uint32_t)ci2 * 72 + cj) * 2) = pack2(v2, v3);
            }
    }
    __syncthreads();

    // phase 2: o = attn @ v + qf @ S (S streamed in 2 halves over kf buffer)
    const size_t sbase = (((size_t)(b*Hc + h)) * NCc + chunk) * (size_t)(Fc * Dc);
    float o[2][4][4];
#pragma unroll
    for (int mf = 0; mf < 2; mf++)
#pragma unroll
        for (int nf = 0; nf < 4; nf++)
#pragma unroll
            for (int i = 0; i < 4; i++) o[mf][nf][i] = 0.f;

    const uint32_t cb = (lane & 7) + ((lane >> 3) & 1) * 8;
    const uint32_t nb = (lane >> 4) * 8;
    const uint32_t a2 = OQF + (uint32_t)(wm*32 + (lane&7) + ((lane>>3)&1)*8) * 528
                      + (lane>>4)*16;

    // load S half 0 (rows 0..127) into OKF region via cp.async
#pragma unroll
    for (int i = 0; i < 8; i++) {
        int l = tid + i * 256;
        int f = l >> 4, p = l & 15;
        cp16(sb + OKF + ((uint32_t)f * 136 + p * 8) * 2,
             &g_s[sbase + (size_t)f * 128 + p * 8]);
    }
    CP_COMMIT();

    // attn @ v (independent of S)
    {
        const uint32_t a1 = OAT + (uint32_t)(wm*32 + (lane&7) + ((lane>>3)&1)*8) * 144
                          + (lane>>4)*16;
#pragma unroll
        for (int ks = 0; ks < 4; ks++) {
            uint32_t a[2][4];
            LDSM4(a[0], sb + a1 + ks * 32);
            LDSM4(a[1], sb + a1 + 16 * 144 + ks * 32);
#pragma unroll
            for (int np = 0; np < 2; np++) {
                uint32_t bbf[4];
                LDSM4T(bbf, sb + OV + ((ks*16 + cb) * 136 + wn*32 + np*16 + nb) * 2);
                mma_f16(o[0][2*np],   a[0], bbf);
                mma_f16(o[0][2*np+1], a[0], bbf + 2);
                mma_f16(o[1][2*np],   a[1], bbf);
                mma_f16(o[1][2*np+1], a[1], bbf + 2);
            }
        }
    }

    CP_WAIT(0);
    __syncthreads();

    // qf @ S rows 0..127 (ks 0..7)
#pragma unroll
    for (int ks = 0; ks < 8; ks++) {
        uint32_t a[2][4];
        LDSM4(a[0], sb + a2 + ks * 32);
        LDSM4(a[1], sb + a2 + 16 * 528 + ks * 32);
#pragma unroll
        for (int np = 0; np < 2; np++) {
            uint32_t bbf[4];
            LDSM4T(bbf, sb + OKF + ((ks*16 + cb) * 136 + wn*32 + np*16 + nb) * 2);
            mma_f16(o[0][2*np],   a[0], bbf);
            mma_f16(o[0][2*np+1], a[0], bbf + 2);
            mma_f16(o[1][2*np],   a[1], bbf);
            mma_f16(o[1][2*np+1], a[1], bbf + 2);
        }
    }
    __syncthreads();

    // load S half 1 (rows 128..255)
#pragma unroll
    for (int i = 0; i < 8; i++) {
        int l = tid + i * 256;
        int f = l >> 4, p = l & 15;
        cp16(sb + OKF + ((uint32_t)f * 136 + p * 8) * 2,
             &g_s[sbase + (size_t)(f + 128) * 128 + p * 8]);
    }
    CP_COMMIT(); CP_WAIT(0);
    __syncthreads();

    // qf @ S rows 128..255 (ks 8..15)
#pragma unroll
    for (int ks = 8; ks < 16; ks++) {
        uint32_t a[2][4];
        LDSM4(a[0], sb + a2 + ks * 32);
        LDSM4(a[1], sb + a2 + 16 * 528 + ks * 32);
#pragma unroll
        for (int np = 0; np < 2; np++) {
            uint32_t bbf[4];
            LDSM4T(bbf, sb + OKF + (((ks-8)*16 + cb) * 136 + wn*32 + np*16 + nb) * 2);
            mma_f16(o[0][2*np],   a[0], bbf);
            mma_f16(o[0][2*np+1], a[0], bbf + 2);
            mma_f16(o[1][2*np],   a[1], bbf);
            mma_f16(o[1][2*np+1], a[1], bbf + 2);
        }
    }

#pragma unroll
    for (int mf = 0; mf < 2; mf++)
#pragma unroll
        for (int nf = 0; nf < 4; nf++) {
            int r = t0 + wm*32 + mf*16 + g;
            int e = wn*32 + nf*8 + t4*2;
            size_t base = (size_t)(b*Tc + r) * HIDc + h * 128 + e;
            *(uint32_t*)&g_oh[base] = pack2(o[mf][nf][0], o[mf][nf][1]);
            *(uint32_t*)&g_oh[base + (size_t)8 * HIDc] =
                pack2(o[mf][nf][2], o[mf][nf][3]);
        }
}

// ---------------------------------------------------------------------------
// RMSNorm over last dim 1024, fp16 in-place in g_oh
// ---------------------------------------------------------------------------
__global__ __launch_bounds__(256) void rmsnorm_kernel()
{
    const int t = blockIdx.x;
    __half2* row = (__half2*)(g_oh + (size_t)t * HIDc);
    const int tid = threadIdx.x;

    float2 v0 = __half22float2(row[tid]);
    float2 v1 = __half22float2(row[tid + 256]);
    float s = v0.x*v0.x + v0.y*v0.y + v1.x*v1.x + v1.y*v1.y;
#pragma unroll
    for (int off = 16; off >= 1; off >>= 1)
        s += __shfl_xor_sync(0xffffffffu, s, off);

    __shared__ float wsum[8];
    if ((tid & 31) == 0) wsum[tid >> 5] = s;
    __syncthreads();
    float tot = 0.f;
#pragma unroll
    for (int w = 0; w < 8; w++) tot += wsum[w];

    const float r = rsqrtf(tot * (1.f / HIDc) + 1e-5f);
    row[tid]       = __floats2half2_rn(v0.x * r, v0.y * r);
    row[tid + 256] = __floats2half2_rn(v1.x * r, v1.y * r);
}

// ---------------------------------------------------------------------------
// Launch
// ---------------------------------------------------------------------------
extern "C" void kernel_launch(void* const* d_in, const int* in_sizes, int n_in,
                              void* d_out, int out_size)
{
    const float* x    = (const float*)d_in[0];
    const float* Wq   = (const float*)d_in[1];
    const float* Wk   = (const float*)d_in[2];
    const float* Wv   = (const float*)d_in[3];
    const float* Wo   = (const float*)d_in[4];
    const float* fmqw = (const float*)d_in[5];
    const float* fmqb = (const float*)d_in[6];
    const float* fmkw = (const float*)d_in[7];
    const float* fmkb = (const float*)d_in[8];
    float* out = (float*)d_out;

    __half *xh, *wvh, *woh, *wq2, *wk2, *qh, *kh, *vh, *oh;
    cudaGetSymbolAddress((void**)&xh,  g_xh);
    cudaGetSymbolAddress((void**)&wvh, g_wvh);
    cudaGetSymbolAddress((void**)&woh, g_woh);
    cudaGetSymbolAddress((void**)&wq2, g_wq2);
    cudaGetSymbolAddress((void**)&wk2, g_wk2);
    cudaGetSymbolAddress((void**)&qh,  g_q);
    cudaGetSymbolAddress((void**)&kh,  g_k);
    cudaGetSymbolAddress((void**)&vh,  g_v);
    cudaGetSymbolAddress((void**)&oh,  g_oh);

    cudaFuncSetAttribute(gemm_t<1>, cudaFuncAttributeMaxDynamicSharedMemorySize, GEMM_SMEM);
    cudaFuncSetAttribute(gemm_t<0>, cudaFuncAttributeMaxDynamicSharedMemorySize, GEMM_SMEM);
    cudaFuncSetAttribute(fold_w,    cudaFuncAttributeMaxDynamicSharedMemorySize, FOLD_SMEM);
    cudaFuncSetAttribute(kv_kernel, cudaFuncAttributeMaxDynamicSharedMemorySize, KV_SMEM);
    cudaFuncSetAttribute(out_kernel,cudaFuncAttributeMaxDynamicSharedMemorySize, OUT_SMEM);

    // conversions + weight folding
    f2h<<<MTOT*HIDc/2048, 256>>>(x, xh, MTOT*HIDc);
    wconv<<<dim3(HIDc*HIDc/2048, 1, 4), 256>>>(Wq, Wk, Wv, Wo);
    fold_w<<<dim3(8, 8, 2), 256, FOLD_SMEM>>>(fmqw, fmkw);

    // fused QKV GEMM (q,k use folded weights -> y directly)
    gemm_t<1><<<dim3(HIDc/128, MTOT/128, 3), 256, GEMM_SMEM>>>(
        xh, wq2, wk2, wvh, qh, kh, vh, nullptr);

    // softmax-only hedgehog
    hh_soft<<<dim3(MTOT*Hc/8, 1, 2), 256>>>(fmqb, fmkb);

    dim3 cg(NCc, Hc, Bc);
    kv_kernel<<<cg, 512, KV_SMEM>>>();
    prefix_kernel<<<dim3(64, Bc*Hc), 256>>>();
    out_kernel<<<cg, 256, OUT_SMEM>>>();

    rmsnorm_kernel<<<MTOT, 256>>>();
    gemm_t<0><<<dim3(HIDc/128, MTOT/128, 1), 256, GEMM_SMEM>>>(
        oh, woh, woh, woh, nullptr, nullptr, nullptr, out);
}

// round 10
// speedup vs baseline: 1.2314x; 1.0336x over previous
#include <cuda_runtime.h>
#include <cuda_fp16.h>
#include <cstdint>
#include <math.h>

// Problem constants
#define Bc   2
#define Tc   8192
#define Hc   8
#define Dc   128
#define HIDc 1024
#define NCc  128          // T / CHUNK
#define Fc   256          // hedgehog feature dim (2*DQK)
#define MTOT (Bc*Tc)      // 16384 tokens

// ---------------------------------------------------------------------------
// Scratch (device globals — no allocations allowed)
// ---------------------------------------------------------------------------
__device__ __half g_xh  [(size_t)MTOT*HIDc];      // 32 MB
__device__ __half g_wvh [HIDc*HIDc];
__device__ __half g_woh [HIDc*HIDc];
__device__ __half g_wq2 [HIDc*HIDc];              // folded fmq @ Wq (per head)
__device__ __half g_wk2 [HIDc*HIDc];              // folded fmk @ Wk
__device__ __half g_v   [(size_t)MTOT*HIDc];
__device__ __half g_qf  [(size_t)MTOT*Hc*Fc];     // 64 MB (pre-scaled)
__device__ __half g_kf  [(size_t)MTOT*Hc*Fc];     // 64 MB
__device__ __half g_kvh [(size_t)Bc*Hc*NCc*Fc*Dc]; // 128 MB per-chunk KV (fp16)
__device__ __half g_s   [(size_t)Bc*Hc*NCc*Fc*Dc]; // 128 MB exclusive prefix (fp16)
__device__ __half g_oh  [(size_t)MTOT*HIDc];      // attention out (unnormalized)
__device__ float  g_rs  [MTOT];                   // rmsnorm row scales

// ---------------------------------------------------------------------------
// Helpers
// ---------------------------------------------------------------------------
__device__ __forceinline__ uint32_t smem_u32(const void* p) {
    uint32_t a;
    asm("{ .reg .u64 t; cvta.to.shared.u64 t, %1; cvt.u32.u64 %0, t; }" : "=r"(a) : "l"(p));
    return a;
}
__device__ __forceinline__ uint32_t pack2(float lo, float hi) {
    __half2 h = __floats2half2_rn(lo, hi);
    return *reinterpret_cast<uint32_t*>(&h);
}
__device__ __forceinline__ void mma_f16(float* c, const uint32_t* a, const uint32_t* b) {
    asm volatile(
        "mma.sync.aligned.m16n8k16.row.col.f32.f16.f16.f32 "
        "{%0,%1,%2,%3}, {%4,%5,%6,%7}, {%8,%9}, {%0,%1,%2,%3};"
        : "+f"(c[0]), "+f"(c[1]), "+f"(c[2]), "+f"(c[3])
        : "r"(a[0]), "r"(a[1]), "r"(a[2]), "r"(a[3]), "r"(b[0]), "r"(b[1]));
}
#define LDSM4(r, addr) \
    asm volatile("ldmatrix.sync.aligned.m8n8.x4.shared.b16 {%0,%1,%2,%3}, [%4];" \
        : "=r"((r)[0]), "=r"((r)[1]), "=r"((r)[2]), "=r"((r)[3]) : "r"(addr))
#define LDSM4T(r, addr) \
    asm volatile("ldmatrix.sync.aligned.m8n8.x4.trans.shared.b16 {%0,%1,%2,%3}, [%4];" \
        : "=r"((r)[0]), "=r"((r)[1]), "=r"((r)[2]), "=r"((r)[3]) : "r"(addr))
__device__ __forceinline__ void cp16(uint32_t dst, const void* src) {
    asm volatile("cp.async.cg.shared.global [%0], [%1], 16;" :: "r"(dst), "l"(src) : "memory");
}
#define CP_COMMIT() asm volatile("cp.async.commit_group;" ::: "memory")
#define CP_WAIT(n)  asm volatile("cp.async.wait_group %0;" :: "n"(n) : "memory")

// ---------------------------------------------------------------------------
// f32 -> f16 conversion (n multiple of 2048)
// ---------------------------------------------------------------------------
__global__ __launch_bounds__(256) void f2h(const float* __restrict__ s,
                                           __half* __restrict__ d, int n)
{
    int i = (blockIdx.x * 256 + threadIdx.x) * 8;
    if (i < n) {
        float4 a = *(const float4*)(s + i), b = *(const float4*)(s + i + 4);
        *(uint4*)(d + i) = make_uint4(pack2(a.x, a.y), pack2(a.z, a.w),
                                      pack2(b.x, b.y), pack2(b.z, b.w));
    }
}
// Wv, Wo conversion (grid.z selects)
__global__ __launch_bounds__(256) void wconv(
    const float* __restrict__ w0, const float* __restrict__ w1)
{
    const int z = blockIdx.z;
    const float* s = z ? w1 : w0;
    __half* d = z ? g_woh : g_wvh;
    int i = (blockIdx.x * 256 + threadIdx.x) * 8;
    float4 a = *(const float4*)(s + i), b = *(const float4*)(s + i + 4);
    *(uint4*)(d + i) = make_uint4(pack2(a.x, a.y), pack2(a.z, a.w),
                                  pack2(b.x, b.y), pack2(b.z, b.w));
}

// ---------------------------------------------------------------------------
// Fold: W2[h*128+i, c] = sum_j fm[i,j] * W[h*128+j, c]   (reads f32 W directly)
// ---------------------------------------------------------------------------
#define FSKP 136
#define FD_A 0
#define FD_B (128*FSKP*2)               // 34816
#define FOLD_SMEM (2*128*FSKP*2)        // 69632

__global__ __launch_bounds__(256) void fold_w(
    const float* __restrict__ fmq, const float* __restrict__ fmk,
    const float* __restrict__ Wq,  const float* __restrict__ Wk)
{
    const int z = blockIdx.z;
    const float* fm = z ? fmk : fmq;
    const float* Wf = z ? Wk : Wq;
    __half* W2 = z ? g_wk2 : g_wq2;

    extern __shared__ char smc[];
    const uint32_t sb = smem_u32(smc);
    const int tid = threadIdx.x, wid = tid >> 5, lane = tid & 31;
    const int wm = wid & 3, wn = wid >> 2;
    const int qr = lane >> 2, qc = lane & 3;
    const int ct = blockIdx.x, h = blockIdx.y;

#pragma unroll
    for (int it = 0; it < 16; it++) {
        int e = tid + it * 256;
        int r = e >> 5, c4 = e & 31;
        float4 f = *(const float4*)(fm + r * 128 + c4 * 4);
        *(uint2*)(smc + FD_A + ((uint32_t)r * FSKP + c4 * 4) * 2) =
            make_uint2(pack2(f.x, f.y), pack2(f.z, f.w));
    }
#pragma unroll
    for (int it = 0; it < 16; it++) {
        int e = tid + it * 256;
        int r = e >> 5, c4 = e & 31;
        float4 f = *(const float4*)(Wf + (size_t)(h * 128 + r) * 1024 + ct * 128 + c4 * 4);
        *(uint2*)(smc + FD_B + ((uint32_t)r * FSKP + c4 * 4) * 2) =
            make_uint2(pack2(f.x, f.y), pack2(f.z, f.w));
    }
    __syncthreads();

    float acc[2][8][4];
#pragma unroll
    for (int mf = 0; mf < 2; mf++)
#pragma unroll
        for (int nf = 0; nf < 8; nf++)
#pragma unroll
            for (int i = 0; i < 4; i++) acc[mf][nf][i] = 0.f;

    const uint32_t a_off = FD_A + (uint32_t)(wm*32 + (lane&7) + ((lane>>3)&1)*8) * (FSKP*2)
                         + (lane>>4)*16;
    const uint32_t cb = (lane & 7) + ((lane >> 3) & 1) * 8;
    const uint32_t nb = (lane >> 4) * 8;

#pragma unroll
    for (int ks = 0; ks < 8; ks++) {
        uint32_t a[2][4];
        LDSM4(a[0], sb + a_off + ks * 32);
        LDSM4(a[1], sb + a_off + 16 * FSKP * 2 + ks * 32);
#pragma unroll
        for (int np = 0; np < 4; np++) {
            uint32_t b[4];
            LDSM4T(b, sb + FD_B + ((ks*16 + cb) * FSKP + wn*64 + np*16 + nb) * 2);
            mma_f16(acc[0][2*np],   a[0], b);
            mma_f16(acc[0][2*np+1], a[0], b + 2);
            mma_f16(acc[1][2*np],   a[1], b);
            mma_f16(acc[1][2*np+1], a[1], b + 2);
        }
    }

#pragma unroll
    for (int mf = 0; mf < 2; mf++) {
        const int i0 = h * 128 + wm * 32 + mf * 16 + qr;
#pragma unroll
        for (int nf = 0; nf < 8; nf++) {
            const int c0 = ct * 128 + wn * 64 + nf * 8 + qc * 2;
            *(uint32_t*)&W2[(size_t)i0 * 1024 + c0] = pack2(acc[mf][nf][0], acc[mf][nf][1]);
            *(uint32_t*)&W2[(size_t)(i0 + 8) * 1024 + c0] = pack2(acc[mf][nf][2], acc[mf][nf][3]);
        }
    }
}

// ---------------------------------------------------------------------------
// GEMM core macros (CTA 128x128, BK=64, 3-stage, 8 warps 4x2, 2 CTAs/SM)
// ---------------------------------------------------------------------------
#define SKP_B   144                   // 64 halves + 8 pad = 144 bytes per row
#define GA_B    (128*SKP_B)           // 18432
#define GSTG    (2*GA_B)              // 36864
#define GEMM_SMEM (3*GSTG)            // 110592

#define GEMM_MAIN(X, W)                                                    \
    const int pr = tid >> 3, pp = tid & 7;                                 \
    const __half* Xp = (X) + (size_t)(m0 + pr) * 1024 + pp * 8;            \
    const __half* Wp = (W) + (size_t)(n0 + pr) * 1024 + pp * 8;            \
    const uint32_t a_off = (uint32_t)(wm*32 + (lane&7) + ((lane>>3)&1)*8) * SKP_B \
                         + (lane>>4)*16;                                   \
    const uint32_t b_off = (uint32_t)(wn*64 + (lane>>4)*8 + (lane&7)) * SKP_B \
                         + ((lane>>3)&1)*16;                               \
    float acc[2][8][4];                                                    \
    _Pragma("unroll")                                                      \
    for (int mf = 0; mf < 2; mf++)                                         \
        _Pragma("unroll")                                                  \
        for (int nf = 0; nf < 8; nf++)                                     \
            _Pragma("unroll")                                              \
            for (int i = 0; i < 4; i++) acc[mf][nf][i] = 0.f;              \
    LOAD_STAGE(0, 0); CP_COMMIT();                                         \
    LOAD_STAGE(1, 1); CP_COMMIT();                                         \
    for (int kt = 0; kt < 16; kt++) {                                      \
        const int st = kt % 3;                                             \
        CP_WAIT(1);                                                        \
        __syncthreads();                                                   \
        const uint32_t As = sb + st * GSTG, Bs = As + GA_B;                \
        _Pragma("unroll")                                                  \
        for (int ks = 0; ks < 4; ks++) {                                   \
            uint32_t a[2][4];                                              \
            LDSM4(a[0], As + a_off + ks * 32);                             \
            LDSM4(a[1], As + a_off + 16 * SKP_B + ks * 32);                \
            _Pragma("unroll")                                              \
            for (int np = 0; np < 4; np++) {                               \
                uint32_t b[4];                                             \
                LDSM4(b, Bs + b_off + np * (16 * SKP_B) + ks * 32);        \
                mma_f16(acc[0][2*np],   a[0], b);                          \
                mma_f16(acc[0][2*np+1], a[0], b + 2);                      \
                mma_f16(acc[1][2*np],   a[1], b);                          \
                mma_f16(acc[1][2*np+1], a[1], b + 2);                      \
            }                                                              \
        }                                                                  \
        if (kt + 2 < 16) LOAD_STAGE(kt + 2, (kt + 2) % 3);                 \
        CP_COMMIT();                                                       \
    }

#define LOAD_STAGE(kt, st) {                                              \
    uint32_t base = sb + (st) * GSTG;                                     \
    const __half* xk = Xp + (kt) * 64;                                    \
    const __half* wk = Wp + (kt) * 64;                                    \
    _Pragma("unroll")                                                     \
    for (int i = 0; i < 4; i++) {                                         \
        uint32_t so = (uint32_t)(pr + 32*i) * SKP_B + pp * 16;            \
        cp16(base + so, xk + (size_t)(32*i) * 1024);                      \
        cp16(base + GA_B + so, wk + (size_t)(32*i) * 1024);               \
    } }

// ---------------------------------------------------------------------------
// Fused QKV GEMM. z=0: q (softmax epilogue, scale 1/16), z=1: k (softmax),
// z=2: v (fp16 write). For z<2, CTA n-tile = one head's full 128 dims, so
// the hedgehog softmax is CTA-local (acc -> smem -> warp-per-row softmax).
// ---------------------------------------------------------------------------
__global__ __launch_bounds__(256, 2) void gemm_qkv(
    const float* __restrict__ biasq, const float* __restrict__ biask)
{
    const int z = blockIdx.z;
    const __half* W = (z == 0) ? g_wq2 : ((z == 1) ? g_wk2 : g_wvh);

    extern __shared__ char smc[];
    const uint32_t sb = smem_u32(smc);
    const int tid = threadIdx.x, wid = tid >> 5, lane = tid & 31;
    const int wm = wid & 3, wn = wid >> 2;
    const int qr = lane >> 2, qc = lane & 3;
    const int m0 = blockIdx.y * 128, n0 = blockIdx.x * 128;

    GEMM_MAIN(g_xh, W)

    if (z == 2) {
        // v: fp16 store
#pragma unroll
        for (int mf = 0; mf < 2; mf++) {
            const int r0 = m0 + wm * 32 + mf * 16 + qr;
#pragma unroll
            for (int nf = 0; nf < 8; nf++) {
                const int c0 = n0 + wn * 64 + nf * 8 + qc * 2;
                *(uint32_t*)&g_v[(size_t)r0 * 1024 + c0] =
                    pack2(acc[mf][nf][0], acc[mf][nf][1]);
                *(uint32_t*)&g_v[(size_t)(r0 + 8) * 1024 + c0] =
                    pack2(acc[mf][nf][2], acc[mf][nf][3]);
            }
        }
        return;
    }

    // q/k: hedgehog softmax epilogue. Reuse stage smem as f32 ys[128][132].
    __syncthreads();
    float* ys = (float*)smc;
#pragma unroll
    for (int mf = 0; mf < 2; mf++) {
        const int r0 = wm * 32 + mf * 16 + qr;
#pragma unroll
        for (int nf = 0; nf < 8; nf++) {
            const int c0 = wn * 64 + nf * 8 + qc * 2;
            *(float2*)(ys + r0 * 132 + c0) = make_float2(acc[mf][nf][0], acc[mf][nf][1]);
            *(float2*)(ys + (r0 + 8) * 132 + c0) = make_float2(acc[mf][nf][2], acc[mf][nf][3]);
        }
    }
    __syncthreads();

    const float* bias = z ? biask : biasq;
    const float scale = z ? 1.0f : 0.0625f;   // 256^-0.5 folded into qf
    __half* dst = z ? g_kf : g_qf;
    const int h = blockIdx.x;
    float4 bv = *(const float4*)(bias + lane * 4);

    for (int rr = 0; rr < 16; rr++) {
        const int r = wid * 16 + rr;
        float4 v4 = *(const float4*)(ys + r * 132 + lane * 4);
        float y[4];
        y[0] = 2.f * (v4.x + bv.x); y[1] = 2.f * (v4.y + bv.y);
        y[2] = 2.f * (v4.z + bv.z); y[3] = 2.f * (v4.w + bv.w);

        float m = fmaxf(fmaxf(fabsf(y[0]), fabsf(y[1])), fmaxf(fabsf(y[2]), fabsf(y[3])));
#pragma unroll
        for (int off = 16; off >= 1; off >>= 1)
            m = fmaxf(m, __shfl_xor_sync(0xffffffffu, m, off));

        float ep[4], en[4], zs = 0.f;
#pragma unroll
        for (int j = 0; j < 4; j++) {
            ep[j] = __expf( y[j] - m);
            en[j] = __expf(-y[j] - m);
            zs += ep[j] + en[j];
        }
#pragma unroll
        for (int off = 16; off >= 1; off >>= 1)
            zs += __shfl_xor_sync(0xffffffffu, zs, off);
        const float inv = scale / zs;

        __half* drow = dst + ((size_t)(m0 + r) * Hc + h) * Fc;
        *(uint2*)(drow + lane * 4) =
            make_uint2(pack2(ep[0]*inv, ep[1]*inv), pack2(ep[2]*inv, ep[3]*inv));
        *(uint2*)(drow + 128 + lane * 4) =
            make_uint2(pack2(en[0]*inv, en[1]*inv), pack2(en[2]*inv, en[3]*inv));
    }
}

// ---------------------------------------------------------------------------
// Wo GEMM with rmsnorm row-scale epilogue: out[r][c] = rs[r] * (o @ Wo^T)
// ---------------------------------------------------------------------------
__global__ __launch_bounds__(256, 2) void gemm_o(float* __restrict__ out)
{
    extern __shared__ char smc[];
    const uint32_t sb = smem_u32(smc);
    const int tid = threadIdx.x, wid = tid >> 5, lane = tid & 31;
    const int wm = wid & 3, wn = wid >> 2;
    const int qr = lane >> 2, qc = lane & 3;
    const int m0 = blockIdx.y * 128, n0 = blockIdx.x * 128;

    GEMM_MAIN(g_oh, g_woh)

#pragma unroll
    for (int mf = 0; mf < 2; mf++) {
        const int r0 = m0 + wm * 32 + mf * 16 + qr;
        const float s0 = g_rs[r0], s1 = g_rs[r0 + 8];
#pragma unroll
        for (int nf = 0; nf < 8; nf++) {
            const int c0 = n0 + wn * 64 + nf * 8 + qc * 2;
            *(float2*)&out[(size_t)r0 * 1024 + c0] =
                make_float2(acc[mf][nf][0] * s0, acc[mf][nf][1] * s0);
            *(float2*)&out[(size_t)(r0 + 8) * 1024 + c0] =
                make_float2(acc[mf][nf][2] * s1, acc[mf][nf][3] * s1);
        }
    }
}

// ---------------------------------------------------------------------------
// KV per chunk (fp16 mma): KV[d,e] = sum_c kf[c,d] * v[c,e]  (256 x 128)
// ---------------------------------------------------------------------------
#define KVQ 0
#define KVV 33792
#define KV_SMEM 51200

__global__ __launch_bounds__(512) void kv_kernel()
{
    extern __shared__ char smc[];
    const uint32_t sb = smem_u32(smc);
    const int chunk = blockIdx.x, h = blockIdx.y, b = blockIdx.z;
    const int tid = threadIdx.x, wid = tid >> 5, lane = tid & 31;
    const int wm = wid & 3, wn = wid >> 2;
    const int g = lane >> 2, t4 = lane & 3;
    const int t0 = chunk * 64;

    const size_t kbase = ((size_t)(b*Tc + t0) * Hc + h) * Fc;
#pragma unroll
    for (int i = 0; i < 4; i++) {
        int l = tid + i * 512;
        int r = l >> 5, p = l & 31;
        *(uint4*)(smc + KVQ + ((uint32_t)r * 264 + p * 8) * 2) =
            *(const uint4*)(&g_kf[kbase + (size_t)r * (Hc*Fc) + p * 8]);
    }
#pragma unroll
    for (int i = 0; i < 2; i++) {
        int l = tid + i * 512;
        int r = l >> 4, p = l & 15;
        *(uint4*)(smc + KVV + ((uint32_t)r * 136 + p * 8) * 2) =
            *(const uint4*)(&g_v[(size_t)(b*Tc + t0 + r) * HIDc + h * 128 + p * 8]);
    }
    __syncthreads();

    float acc[4][4][4];
#pragma unroll
    for (int mf = 0; mf < 4; mf++)
#pragma unroll
        for (int nf = 0; nf < 4; nf++)
#pragma unroll
            for (int i = 0; i < 4; i++) acc[mf][nf][i] = 0.f;

    const uint32_t ca = (lane & 7) + ((lane >> 4) & 1) * 8;
    const uint32_t ma = ((lane >> 3) & 1) * 8;
    const uint32_t cb = (lane & 7) + ((lane >> 3) & 1) * 8;
    const uint32_t nb = (lane >> 4) * 8;

#pragma unroll
    for (int ks = 0; ks < 4; ks++) {
        uint32_t bb[2][4];
#pragma unroll
        for (int np = 0; np < 2; np++)
            LDSM4T(bb[np], sb + KVV + ((ks*16 + cb) * 136 + wn*32 + np*16 + nb) * 2);
#pragma unroll
        for (int mf = 0; mf < 4; mf++) {
            uint32_t a[4];
            LDSM4T(a, sb + KVQ + ((ks*16 + ca) * 264 + wm*64 + mf*16 + ma) * 2);
            mma_f16(acc[mf][0], a, bb[0]);
            mma_f16(acc[mf][1], a, bb[0] + 2);
            mma_f16(acc[mf][2], a, bb[1]);
            mma_f16(acc[mf][3], a, bb[1] + 2);
        }
    }

    const size_t base = (((size_t)(b*Hc + h)) * NCc + chunk) * (size_t)(Fc * Dc);
#pragma unroll
    for (int mf = 0; mf < 4; mf++)
#pragma unroll
        for (int nf = 0; nf < 4; nf++) {
            int d = wm * 64 + mf * 16 + g;
            int e = wn * 32 + nf * 8 + t4 * 2;
            *(uint32_t*)&g_kvh[base + (size_t)d * 128 + e] =
                pack2(acc[mf][nf][0], acc[mf][nf][1]);
            *(uint32_t*)&g_kvh[base + (size_t)(d + 8) * 128 + e] =
                pack2(acc[mf][nf][2], acc[mf][nf][3]);
        }
}

// ---------------------------------------------------------------------------
// Exclusive prefix over chunks, fp16 in, f32 accumulate, fp16 out.
// ---------------------------------------------------------------------------
__global__ __launch_bounds__(256) void prefix_kernel()
{
    const int bh  = blockIdx.y;
    const int idx = (blockIdx.x * 256 + threadIdx.x) * 2;
    const size_t stride = (size_t)Fc * Dc;
    size_t p = (size_t)bh * NCc * stride + idx;
    float ax = 0.f, ay = 0.f;
    __half2 cur = *(const __half2*)&g_kvh[p];
    for (int i = 0; i < NCc; i++) {
        __half2 nxt;
        if (i + 1 < NCc) nxt = *(const __half2*)&g_kvh[p + stride];
        float2 t = __half22float2(cur);
        *(uint32_t*)&g_s[p] = pack2(ax, ay);
        ax += t.x; ay += t.y;
        cur = nxt;
        p += stride;
    }
}

// ---------------------------------------------------------------------------
// Output per chunk (fp16 mma): o = tril(qf @ kf^T) @ v + qf @ S  -> fp16
// S streamed in two 128-row halves over the kf buffer. 2 CTAs/SM.
// ---------------------------------------------------------------------------
#define OQF 0
#define OKF 33792                     // kf (64x264) / S half (128x136)
#define OV  68608
#define OAT 86016
#define OUT_SMEM 95232

__global__ __launch_bounds__(256, 2) void out_kernel()
{
    extern __shared__ char smc[];
    const uint32_t sb = smem_u32(smc);
    const int chunk = blockIdx.x, h = blockIdx.y, b = blockIdx.z;
    const int tid = threadIdx.x, wid = tid >> 5, lane = tid & 31;
    const int g = lane >> 2, t4 = lane & 3;
    const int t0 = chunk * 64;
    const int wm = wid & 1, wn = wid >> 1;

    const size_t qbase = ((size_t)(b*Tc + t0) * Hc + h) * Fc;
#pragma unroll
    for (int i = 0; i < 8; i++) {
        int l = tid + i * 256;
        int r = l >> 5, p = l & 31;
        size_t gs = qbase + (size_t)r * (Hc*Fc) + p * 8;
        *(uint4*)(smc + OQF + ((uint32_t)r * 264 + p * 8) * 2) = *(const uint4*)(&g_qf[gs]);
        *(uint4*)(smc + OKF + ((uint32_t)r * 264 + p * 8) * 2) = *(const uint4*)(&g_kf[gs]);
    }
#pragma unroll
    for (int i = 0; i < 4; i++) {
        int l = tid + i * 256;
        int r = l >> 4, p = l & 15;
        *(uint4*)(smc + OV + ((uint32_t)r * 136 + p * 8) * 2) =
            *(const uint4*)(&g_v[(size_t)(b*Tc + t0 + r) * HIDc + h * 128 + p * 8]);
    }
    __syncthreads();

    // phase 1: scores = tril(qf @ kf^T)
    {
        float sc[2][2][4];
#pragma unroll
        for (int mf = 0; mf < 2; mf++)
#pragma unroll
            for (int nf = 0; nf < 2; nf++)
#pragma unroll
                for (int i = 0; i < 4; i++) sc[mf][nf][i] = 0.f;

        const uint32_t aoff = OQF + (uint32_t)(wm*32 + (lane&7) + ((lane>>3)&1)*8) * 528
                            + (lane>>4)*16;
        const uint32_t boff = OKF + (uint32_t)(wn*16 + (lane>>4)*8 + (lane&7)) * 528
                            + ((lane>>3)&1)*16;
#pragma unroll
        for (int ks = 0; ks < 16; ks++) {
            uint32_t a[2][4], bbf[4];
            LDSM4(a[0], sb + aoff + ks * 32);
            LDSM4(a[1], sb + aoff + 16 * 528 + ks * 32);
            LDSM4(bbf, sb + boff + ks * 32);
            mma_f16(sc[0][0], a[0], bbf);
            mma_f16(sc[0][1], a[0], bbf + 2);
            mma_f16(sc[1][0], a[1], bbf);
            mma_f16(sc[1][1], a[1], bbf + 2);
        }
#pragma unroll
        for (int mf = 0; mf < 2; mf++)
#pragma unroll
            for (int nf = 0; nf < 2; nf++) {
                int ci = wm*32 + mf*16 + g;
                int cj = wn*16 + nf*8 + t4*2;
                float v0 = (cj     <= ci) ? sc[mf][nf][0] : 0.f;
                float v1 = (cj + 1 <= ci) ? sc[mf][nf][1] : 0.f;
                *(uint32_t*)(smc + OAT + ((uint32_t)ci * 72 + cj) * 2) = pack2(v0, v1);
                int ci2 = ci + 8;
                float v2 = (cj     <= ci2) ? sc[mf][nf][2] : 0.f;
                float v3 = (cj + 1 <= ci2) ? sc[mf][nf][3] : 0.f;
                *(uint32_t*)(smc + OAT + ((uint32_t)ci2 * 72 + cj) * 2) = pack2(v2, v3);
            }
    }
    __syncthreads();

    // phase 2: o = attn @ v + qf @ S (S streamed in 2 halves over kf buffer)
    const size_t sbase = (((size_t)(b*Hc + h)) * NCc + chunk) * (size_t)(Fc * Dc);
    float o[2][4][4];
#pragma unroll
    for (int mf = 0; mf < 2; mf++)
#pragma unroll
        for (int nf = 0; nf < 4; nf++)
#pragma unroll
            for (int i = 0; i < 4; i++) o[mf][nf][i] = 0.f;

    const uint32_t cb = (lane & 7) + ((lane >> 3) & 1) * 8;
    const uint32_t nb = (lane >> 4) * 8;
    const uint32_t a2 = OQF + (uint32_t)(wm*32 + (lane&7) + ((lane>>3)&1)*8) * 528
                      + (lane>>4)*16;

#pragma unroll
    for (int i = 0; i < 8; i++) {
        int l = tid + i * 256;
        int f = l >> 4, p = l & 15;
        cp16(sb + OKF + ((uint32_t)f * 136 + p * 8) * 2,
             &g_s[sbase + (size_t)f * 128 + p * 8]);
    }
    CP_COMMIT();

    // attn @ v (independent of S)
    {
        const uint32_t a1 = OAT + (uint32_t)(wm*32 + (lane&7) + ((lane>>3)&1)*8) * 144
                          + (lane>>4)*16;
#pragma unroll
        for (int ks = 0; ks < 4; ks++) {
            uint32_t a[2][4];
            LDSM4(a[0], sb + a1 + ks * 32);
            LDSM4(a[1], sb + a1 + 16 * 144 + ks * 32);
#pragma unroll
            for (int np = 0; np < 2; np++) {
                uint32_t bbf[4];
                LDSM4T(bbf, sb + OV + ((ks*16 + cb) * 136 + wn*32 + np*16 + nb) * 2);
                mma_f16(o[0][2*np],   a[0], bbf);
                mma_f16(o[0][2*np+1], a[0], bbf + 2);
                mma_f16(o[1][2*np],   a[1], bbf);
                mma_f16(o[1][2*np+1], a[1], bbf + 2);
            }
        }
    }

    CP_WAIT(0);
    __syncthreads();

#pragma unroll
    for (int ks = 0; ks < 8; ks++) {
        uint32_t a[2][4];
        LDSM4(a[0], sb + a2 + ks * 32);
        LDSM4(a[1], sb + a2 + 16 * 528 + ks * 32);
#pragma unroll
        for (int np = 0; np < 2; np++) {
            uint32_t bbf[4];
            LDSM4T(bbf, sb + OKF + ((ks*16 + cb) * 136 + wn*32 + np*16 + nb) * 2);
            mma_f16(o[0][2*np],   a[0], bbf);
            mma_f16(o[0][2*np+1], a[0], bbf + 2);
            mma_f16(o[1][2*np],   a[1], bbf);
            mma_f16(o[1][2*np+1], a[1], bbf + 2);
        }
    }
    __syncthreads();

#pragma unroll
    for (int i = 0; i < 8; i++) {
        int l = tid + i * 256;
        int f = l >> 4, p = l & 15;
        cp16(sb + OKF + ((uint32_t)f * 136 + p * 8) * 2,
             &g_s[sbase + (size_t)(f + 128) * 128 + p * 8]);
    }
    CP_COMMIT(); CP_WAIT(0);
    __syncthreads();

#pragma unroll
    for (int ks = 8; ks < 16; ks++) {
        uint32_t a[2][4];
        LDSM4(a[0], sb + a2 + ks * 32);
        LDSM4(a[1], sb + a2 + 16 * 528 + ks * 32);
#pragma unroll
        for (int np = 0; np < 2; np++) {
            uint32_t bbf[4];
            LDSM4T(bbf, sb + OKF + (((ks-8)*16 + cb) * 136 + wn*32 + np*16 + nb) * 2);
            mma_f16(o[0][2*np],   a[0], bbf);
            mma_f16(o[0][2*np+1], a[0], bbf + 2);
            mma_f16(o[1][2*np],   a[1], bbf);
            mma_f16(o[1][2*np+1], a[1], bbf + 2);
        }
    }

#pragma unroll
    for (int mf = 0; mf < 2; mf++)
#pragma unroll
        for (int nf = 0; nf < 4; nf++) {
            int r = t0 + wm*32 + mf*16 + g;
            int e = wn*32 + nf*8 + t4*2;
            size_t base = (size_t)(b*Tc + r) * HIDc + h * 128 + e;
            *(uint32_t*)&g_oh[base] = pack2(o[mf][nf][0], o[mf][nf][1]);
            *(uint32_t*)&g_oh[base + (size_t)8 * HIDc] =
                pack2(o[mf][nf][2], o[mf][nf][3]);
        }
}

// ---------------------------------------------------------------------------
// Row-scale: rs[t] = rsqrt(mean(o[t]^2) + eps). One warp per token.
// ---------------------------------------------------------------------------
__global__ __launch_bounds__(256) void rowscale_kernel()
{
    const int wid = threadIdx.x >> 5, lane = threadIdx.x & 31;
    const int t = blockIdx.x * 8 + wid;
    const __half2* row = (const __half2*)(g_oh + (size_t)t * HIDc);

    float s = 0.f;
#pragma unroll
    for (int i = 0; i < 16; i++) {
        float2 v = __half22float2(row[lane + i * 32]);
        s += v.x * v.x + v.y * v.y;
    }
#pragma unroll
    for (int off = 16; off >= 1; off >>= 1)
        s += __shfl_xor_sync(0xffffffffu, s, off);

    if (lane == 0)
        g_rs[t] = rsqrtf(s * (1.f / HIDc) + 1e-5f);
}

// ---------------------------------------------------------------------------
// Launch
// ---------------------------------------------------------------------------
extern "C" void kernel_launch(void* const* d_in, const int* in_sizes, int n_in,
                              void* d_out, int out_size)
{
    const float* x    = (const float*)d_in[0];
    const float* Wq   = (const float*)d_in[1];
    const float* Wk   = (const float*)d_in[2];
    const float* Wv   = (const float*)d_in[3];
    const float* Wo   = (const float*)d_in[4];
    const float* fmqw = (const float*)d_in[5];
    const float* fmqb = (const float*)d_in[6];
    const float* fmkw = (const float*)d_in[7];
    const float* fmkb = (const float*)d_in[8];
    float* out = (float*)d_out;

    __half* xh;
    cudaGetSymbolAddress((void**)&xh, g_xh);

    cudaFuncSetAttribute(gemm_qkv,  cudaFuncAttributeMaxDynamicSharedMemorySize, GEMM_SMEM);
    cudaFuncSetAttribute(gemm_o,    cudaFuncAttributeMaxDynamicSharedMemorySize, GEMM_SMEM);
    cudaFuncSetAttribute(fold_w,    cudaFuncAttributeMaxDynamicSharedMemorySize, FOLD_SMEM);
    cudaFuncSetAttribute(kv_kernel, cudaFuncAttributeMaxDynamicSharedMemorySize, KV_SMEM);
    cudaFuncSetAttribute(out_kernel,cudaFuncAttributeMaxDynamicSharedMemorySize, OUT_SMEM);

    // conversions + weight folding
    f2h<<<MTOT*HIDc/2048, 256>>>(x, xh, MTOT*HIDc);
    wconv<<<dim3(HIDc*HIDc/2048, 1, 2), 256>>>(Wv, Wo);
    fold_w<<<dim3(8, 8, 2), 256, FOLD_SMEM>>>(fmqw, fmkw, Wq, Wk);

    // fused QKV GEMM + hedgehog softmax epilogue
    gemm_qkv<<<dim3(HIDc/128, MTOT/128, 3), 256, GEMM_SMEM>>>(fmqb, fmkb);

    dim3 cg(NCc, Hc, Bc);
    kv_kernel<<<cg, 512, KV_SMEM>>>();
    prefix_kernel<<<dim3(64, Bc*Hc), 256>>>();
    out_kernel<<<cg, 256, OUT_SMEM>>>();

    rowscale_kernel<<<MTOT/8, 256>>>();
    gemm_o<<<dim3(HIDc/128, MTOT/128, 1), 256, GEMM_SMEM>>>(out);
}

// round 11
// speedup vs baseline: 1.2545x; 1.0187x over previous
#include <cuda_runtime.h>
#include <cuda_fp16.h>
#include <cstdint>
#include <math.h>

// Problem constants
#define Bc   2
#define Tc   8192
#define Hc   8
#define Dc   128
#define HIDc 1024
#define NCc  128          // T / CHUNK
#define Fc   256          // hedgehog feature dim (2*DQK)
#define MTOT (Bc*Tc)      // 16384 tokens

// ---------------------------------------------------------------------------
// Scratch (device globals — no allocations allowed)
// ---------------------------------------------------------------------------
__device__ __half g_xh  [(size_t)MTOT*HIDc];      // 32 MB
__device__ __half g_wvh [HIDc*HIDc];
__device__ __half g_woh [HIDc*HIDc];
__device__ __half g_wq2 [HIDc*HIDc];              // folded fmq @ Wq (per head)
__device__ __half g_wk2 [HIDc*HIDc];              // folded fmk @ Wk
__device__ __half g_v   [(size_t)MTOT*HIDc];
__device__ __half g_qf  [(size_t)MTOT*Hc*Fc];     // 64 MB (pre-scaled)
__device__ __half g_kf  [(size_t)MTOT*Hc*Fc];     // 64 MB
__device__ __half g_kvh [(size_t)Bc*Hc*NCc*Fc*Dc]; // 128 MB per-chunk KV (fp16)
__device__ __half g_s   [(size_t)Bc*Hc*NCc*Fc*Dc]; // 128 MB exclusive prefix (fp16)
__device__ __half g_oh  [(size_t)MTOT*HIDc];      // attention out (unnormalized)
__device__ float  g_rs  [MTOT];                   // rmsnorm row scales

// ---------------------------------------------------------------------------
// Helpers
// ---------------------------------------------------------------------------
__device__ __forceinline__ uint32_t smem_u32(const void* p) {
    uint32_t a;
    asm("{ .reg .u64 t; cvta.to.shared.u64 t, %1; cvt.u32.u64 %0, t; }" : "=r"(a) : "l"(p));
    return a;
}
__device__ __forceinline__ uint32_t pack2(float lo, float hi) {
    __half2 h = __floats2half2_rn(lo, hi);
    return *reinterpret_cast<uint32_t*>(&h);
}
__device__ __forceinline__ void mma_f16(float* c, const uint32_t* a, const uint32_t* b) {
    asm volatile(
        "mma.sync.aligned.m16n8k16.row.col.f32.f16.f16.f32 "
        "{%0,%1,%2,%3}, {%4,%5,%6,%7}, {%8,%9}, {%0,%1,%2,%3};"
        : "+f"(c[0]), "+f"(c[1]), "+f"(c[2]), "+f"(c[3])
        : "r"(a[0]), "r"(a[1]), "r"(a[2]), "r"(a[3]), "r"(b[0]), "r"(b[1]));
}
#define LDSM4(r, addr) \
    asm volatile("ldmatrix.sync.aligned.m8n8.x4.shared.b16 {%0,%1,%2,%3}, [%4];" \
        : "=r"((r)[0]), "=r"((r)[1]), "=r"((r)[2]), "=r"((r)[3]) : "r"(addr))
#define LDSM4T(r, addr) \
    asm volatile("ldmatrix.sync.aligned.m8n8.x4.trans.shared.b16 {%0,%1,%2,%3}, [%4];" \
        : "=r"((r)[0]), "=r"((r)[1]), "=r"((r)[2]), "=r"((r)[3]) : "r"(addr))
__device__ __forceinline__ void cp16(uint32_t dst, const void* src) {
    asm volatile("cp.async.cg.shared.global [%0], [%1], 16;" :: "r"(dst), "l"(src) : "memory");
}
#define CP_COMMIT() asm volatile("cp.async.commit_group;" ::: "memory")
#define CP_WAIT(n)  asm volatile("cp.async.wait_group %0;" :: "n"(n) : "memory")

// ---------------------------------------------------------------------------
// f32 -> f16 conversion (n multiple of 2048)
// ---------------------------------------------------------------------------
__global__ __launch_bounds__(256) void f2h(const float* __restrict__ s,
                                           __half* __restrict__ d, int n)
{
    int i = (blockIdx.x * 256 + threadIdx.x) * 8;
    if (i < n) {
        float4 a = *(const float4*)(s + i), b = *(const float4*)(s + i + 4);
        *(uint4*)(d + i) = make_uint4(pack2(a.x, a.y), pack2(a.z, a.w),
                                      pack2(b.x, b.y), pack2(b.z, b.w));
    }
}
// Wv, Wo conversion (grid.z selects)
__global__ __launch_bounds__(256) void wconv(
    const float* __restrict__ w0, const float* __restrict__ w1)
{
    const int z = blockIdx.z;
    const float* s = z ? w1 : w0;
    __half* d = z ? g_woh : g_wvh;
    int i = (blockIdx.x * 256 + threadIdx.x) * 8;
    float4 a = *(const float4*)(s + i), b = *(const float4*)(s + i + 4);
    *(uint4*)(d + i) = make_uint4(pack2(a.x, a.y), pack2(a.z, a.w),
                                  pack2(b.x, b.y), pack2(b.z, b.w));
}

// ---------------------------------------------------------------------------
// Fold: W2[h*128+i, c] = sum_j fm[i,j] * W[h*128+j, c]   (reads f32 W directly)
// ---------------------------------------------------------------------------
#define FSKP 136
#define FD_A 0
#define FD_B (128*FSKP*2)               // 34816
#define FOLD_SMEM (2*128*FSKP*2)        // 69632

__global__ __launch_bounds__(256) void fold_w(
    const float* __restrict__ fmq, const float* __restrict__ fmk,
    const float* __restrict__ Wq,  const float* __restrict__ Wk)
{
    const int z = blockIdx.z;
    const float* fm = z ? fmk : fmq;
    const float* Wf = z ? Wk : Wq;
    __half* W2 = z ? g_wk2 : g_wq2;

    extern __shared__ char smc[];
    const uint32_t sb = smem_u32(smc);
    const int tid = threadIdx.x, wid = tid >> 5, lane = tid & 31;
    const int wm = wid & 3, wn = wid >> 2;
    const int qr = lane >> 2, qc = lane & 3;
    const int ct = blockIdx.x, h = blockIdx.y;

#pragma unroll
    for (int it = 0; it < 16; it++) {
        int e = tid + it * 256;
        int r = e >> 5, c4 = e & 31;
        float4 f = *(const float4*)(fm + r * 128 + c4 * 4);
        *(uint2*)(smc + FD_A + ((uint32_t)r * FSKP + c4 * 4) * 2) =
            make_uint2(pack2(f.x, f.y), pack2(f.z, f.w));
    }
#pragma unroll
    for (int it = 0; it < 16; it++) {
        int e = tid + it * 256;
        int r = e >> 5, c4 = e & 31;
        float4 f = *(const float4*)(Wf + (size_t)(h * 128 + r) * 1024 + ct * 128 + c4 * 4);
        *(uint2*)(smc + FD_B + ((uint32_t)r * FSKP + c4 * 4) * 2) =
            make_uint2(pack2(f.x, f.y), pack2(f.z, f.w));
    }
    __syncthreads();

    float acc[2][8][4];
#pragma unroll
    for (int mf = 0; mf < 2; mf++)
#pragma unroll
        for (int nf = 0; nf < 8; nf++)
#pragma unroll
            for (int i = 0; i < 4; i++) acc[mf][nf][i] = 0.f;

    const uint32_t a_off = FD_A + (uint32_t)(wm*32 + (lane&7) + ((lane>>3)&1)*8) * (FSKP*2)
                         + (lane>>4)*16;
    const uint32_t cb = (lane & 7) + ((lane >> 3) & 1) * 8;
    const uint32_t nb = (lane >> 4) * 8;

#pragma unroll
    for (int ks = 0; ks < 8; ks++) {
        uint32_t a[2][4];
        LDSM4(a[0], sb + a_off + ks * 32);
        LDSM4(a[1], sb + a_off + 16 * FSKP * 2 + ks * 32);
#pragma unroll
        for (int np = 0; np < 4; np++) {
            uint32_t b[4];
            LDSM4T(b, sb + FD_B + ((ks*16 + cb) * FSKP + wn*64 + np*16 + nb) * 2);
            mma_f16(acc[0][2*np],   a[0], b);
            mma_f16(acc[0][2*np+1], a[0], b + 2);
            mma_f16(acc[1][2*np],   a[1], b);
            mma_f16(acc[1][2*np+1], a[1], b + 2);
        }
    }

#pragma unroll
    for (int mf = 0; mf < 2; mf++) {
        const int i0 = h * 128 + wm * 32 + mf * 16 + qr;
#pragma unroll
        for (int nf = 0; nf < 8; nf++) {
            const int c0 = ct * 128 + wn * 64 + nf * 8 + qc * 2;
            *(uint32_t*)&W2[(size_t)i0 * 1024 + c0] = pack2(acc[mf][nf][0], acc[mf][nf][1]);
            *(uint32_t*)&W2[(size_t)(i0 + 8) * 1024 + c0] = pack2(acc[mf][nf][2], acc[mf][nf][3]);
        }
    }
}

// ---------------------------------------------------------------------------
// GEMM core macros (CTA 128x128, BK=64, 3-stage, 8 warps 4x2, 2 CTAs/SM)
// ---------------------------------------------------------------------------
#define SKP_B   144                   // 64 halves + 8 pad = 144 bytes per row
#define GA_B    (128*SKP_B)           // 18432
#define GSTG    (2*GA_B)              // 36864
#define GEMM_SMEM (3*GSTG)            // 110592

#define GEMM_MAIN(X, W)                                                    \
    const int pr = tid >> 3, pp = tid & 7;                                 \
    const __half* Xp = (X) + (size_t)(m0 + pr) * 1024 + pp * 8;            \
    const __half* Wp = (W) + (size_t)(n0 + pr) * 1024 + pp * 8;            \
    const uint32_t a_off = (uint32_t)(wm*32 + (lane&7) + ((lane>>3)&1)*8) * SKP_B \
                         + (lane>>4)*16;                                   \
    const uint32_t b_off = (uint32_t)(wn*64 + (lane>>4)*8 + (lane&7)) * SKP_B \
                         + ((lane>>3)&1)*16;                               \
    float acc[2][8][4];                                                    \
    _Pragma("unroll")                                                      \
    for (int mf = 0; mf < 2; mf++)                                         \
        _Pragma("unroll")                                                  \
        for (int nf = 0; nf < 8; nf++)                                     \
            _Pragma("unroll")                                              \
            for (int i = 0; i < 4; i++) acc[mf][nf][i] = 0.f;              \
    LOAD_STAGE(0, 0); CP_COMMIT();                                         \
    LOAD_STAGE(1, 1); CP_COMMIT();                                         \
    for (int kt = 0; kt < 16; kt++) {                                      \
        const int st = kt % 3;                                             \
        CP_WAIT(1);                                                        \
        __syncthreads();                                                   \
        const uint32_t As = sb + st * GSTG, Bs = As + GA_B;                \
        _Pragma("unroll")                                                  \
        for (int ks = 0; ks < 4; ks++) {                                   \
            uint32_t a[2][4];                                              \
            LDSM4(a[0], As + a_off + ks * 32);                             \
            LDSM4(a[1], As + a_off + 16 * SKP_B + ks * 32);                \
            _Pragma("unroll")                                              \
            for (int np = 0; np < 4; np++) {                               \
                uint32_t b[4];                                             \
                LDSM4(b, Bs + b_off + np * (16 * SKP_B) + ks * 32);        \
                mma_f16(acc[0][2*np],   a[0], b);                          \
                mma_f16(acc[0][2*np+1], a[0], b + 2);                      \
                mma_f16(acc[1][2*np],   a[1], b);                          \
                mma_f16(acc[1][2*np+1], a[1], b + 2);                      \
            }                                                              \
        }                                                                  \
        if (kt + 2 < 16) LOAD_STAGE(kt + 2, (kt + 2) % 3);                 \
        CP_COMMIT();                                                       \
    }

#define LOAD_STAGE(kt, st) {                                              \
    uint32_t base = sb + (st) * GSTG;                                     \
    const __half* xk = Xp + (kt) * 64;                                    \
    const __half* wk = Wp + (kt) * 64;                                    \
    _Pragma("unroll")                                                     \
    for (int i = 0; i < 4; i++) {                                         \
        uint32_t so = (uint32_t)(pr + 32*i) * SKP_B + pp * 16;            \
        cp16(base + so, xk + (size_t)(32*i) * 1024);                      \
        cp16(base + GA_B + so, wk + (size_t)(32*i) * 1024);               \
    } }

// ---------------------------------------------------------------------------
// Fused QKV GEMM. z=0: q (softmax epilogue, scale 1/16), z=1: k (softmax),
// z=2: v (fp16 write).
// ---------------------------------------------------------------------------
__global__ __launch_bounds__(256, 2) void gemm_qkv(
    const float* __restrict__ biasq, const float* __restrict__ biask)
{
    const int z = blockIdx.z;
    const __half* W = (z == 0) ? g_wq2 : ((z == 1) ? g_wk2 : g_wvh);

    extern __shared__ char smc[];
    const uint32_t sb = smem_u32(smc);
    const int tid = threadIdx.x, wid = tid >> 5, lane = tid & 31;
    const int wm = wid & 3, wn = wid >> 2;
    const int qr = lane >> 2, qc = lane & 3;
    const int m0 = blockIdx.y * 128, n0 = blockIdx.x * 128;

    GEMM_MAIN(g_xh, W)

    if (z == 2) {
#pragma unroll
        for (int mf = 0; mf < 2; mf++) {
            const int r0 = m0 + wm * 32 + mf * 16 + qr;
#pragma unroll
            for (int nf = 0; nf < 8; nf++) {
                const int c0 = n0 + wn * 64 + nf * 8 + qc * 2;
                *(uint32_t*)&g_v[(size_t)r0 * 1024 + c0] =
                    pack2(acc[mf][nf][0], acc[mf][nf][1]);
                *(uint32_t*)&g_v[(size_t)(r0 + 8) * 1024 + c0] =
                    pack2(acc[mf][nf][2], acc[mf][nf][3]);
            }
        }
        return;
    }

    // q/k: hedgehog softmax epilogue. Reuse stage smem as f32 ys[128][132].
    __syncthreads();
    float* ys = (float*)smc;
#pragma unroll
    for (int mf = 0; mf < 2; mf++) {
        const int r0 = wm * 32 + mf * 16 + qr;
#pragma unroll
        for (int nf = 0; nf < 8; nf++) {
            const int c0 = wn * 64 + nf * 8 + qc * 2;
            *(float2*)(ys + r0 * 132 + c0) = make_float2(acc[mf][nf][0], acc[mf][nf][1]);
            *(float2*)(ys + (r0 + 8) * 132 + c0) = make_float2(acc[mf][nf][2], acc[mf][nf][3]);
        }
    }
    __syncthreads();

    const float* bias = z ? biask : biasq;
    const float scale = z ? 1.0f : 0.0625f;   // 256^-0.5 folded into qf
    __half* dst = z ? g_kf : g_qf;
    const int h = blockIdx.x;
    float4 bv = *(const float4*)(bias + lane * 4);

    // two rows per iteration: independent reduction chains overlap
    for (int rr = 0; rr < 16; rr += 2) {
        const int r0 = wid * 16 + rr;
        float y[2][4], m[2];
#pragma unroll
        for (int u = 0; u < 2; u++) {
            float4 v4 = *(const float4*)(ys + (r0 + u) * 132 + lane * 4);
            y[u][0] = 2.f * (v4.x + bv.x); y[u][1] = 2.f * (v4.y + bv.y);
            y[u][2] = 2.f * (v4.z + bv.z); y[u][3] = 2.f * (v4.w + bv.w);
            m[u] = fmaxf(fmaxf(fabsf(y[u][0]), fabsf(y[u][1])),
                         fmaxf(fabsf(y[u][2]), fabsf(y[u][3])));
        }
#pragma unroll
        for (int off = 16; off >= 1; off >>= 1) {
            m[0] = fmaxf(m[0], __shfl_xor_sync(0xffffffffu, m[0], off));
            m[1] = fmaxf(m[1], __shfl_xor_sync(0xffffffffu, m[1], off));
        }
        float ep[2][4], en[2][4], zs[2] = {0.f, 0.f};
#pragma unroll
        for (int u = 0; u < 2; u++)
#pragma unroll
            for (int j = 0; j < 4; j++) {
                ep[u][j] = __expf( y[u][j] - m[u]);
                en[u][j] = __expf(-y[u][j] - m[u]);
                zs[u] += ep[u][j] + en[u][j];
            }
#pragma unroll
        for (int off = 16; off >= 1; off >>= 1) {
            zs[0] += __shfl_xor_sync(0xffffffffu, zs[0], off);
            zs[1] += __shfl_xor_sync(0xffffffffu, zs[1], off);
        }
#pragma unroll
        for (int u = 0; u < 2; u++) {
            const float inv = scale / zs[u];
            __half* drow = dst + ((size_t)(m0 + r0 + u) * Hc + h) * Fc;
            *(uint2*)(drow + lane * 4) =
                make_uint2(pack2(ep[u][0]*inv, ep[u][1]*inv),
                           pack2(ep[u][2]*inv, ep[u][3]*inv));
            *(uint2*)(drow + 128 + lane * 4) =
                make_uint2(pack2(en[u][0]*inv, en[u][1]*inv),
                           pack2(en[u][2]*inv, en[u][3]*inv));
        }
    }
}

// ---------------------------------------------------------------------------
// Wo GEMM with rmsnorm row-scale epilogue: out[r][c] = rs[r] * (o @ Wo^T)
// ---------------------------------------------------------------------------
__global__ __launch_bounds__(256, 2) void gemm_o(float* __restrict__ out)
{
    extern __shared__ char smc[];
    const uint32_t sb = smem_u32(smc);
    const int tid = threadIdx.x, wid = tid >> 5, lane = tid & 31;
    const int wm = wid & 3, wn = wid >> 2;
    const int qr = lane >> 2, qc = lane & 3;
    const int m0 = blockIdx.y * 128, n0 = blockIdx.x * 128;

    GEMM_MAIN(g_oh, g_woh)

#pragma unroll
    for (int mf = 0; mf < 2; mf++) {
        const int r0 = m0 + wm * 32 + mf * 16 + qr;
        const float s0 = g_rs[r0], s1 = g_rs[r0 + 8];
#pragma unroll
        for (int nf = 0; nf < 8; nf++) {
            const int c0 = n0 + wn * 64 + nf * 8 + qc * 2;
            *(float2*)&out[(size_t)r0 * 1024 + c0] =
                make_float2(acc[mf][nf][0] * s0, acc[mf][nf][1] * s0);
            *(float2*)&out[(size_t)(r0 + 8) * 1024 + c0] =
                make_float2(acc[mf][nf][2] * s1, acc[mf][nf][3] * s1);
        }
    }
}

// ---------------------------------------------------------------------------
// KV per chunk (fp16 mma): KV[d,e] = sum_c kf[c,d] * v[c,e]  (256 x 128)
// Output staged through smem for coalesced 16B stores.
// ---------------------------------------------------------------------------
#define KVQ 0
#define KVV 33792
#define KV_SMEM 69632                 // staging 256x136 fp16 overlays kf+v

__global__ __launch_bounds__(512) void kv_kernel()
{
    extern __shared__ char smc[];
    const uint32_t sb = smem_u32(smc);
    const int chunk = blockIdx.x, h = blockIdx.y, b = blockIdx.z;
    const int tid = threadIdx.x, wid = tid >> 5, lane = tid & 31;
    const int wm = wid & 3, wn = wid >> 2;
    const int g = lane >> 2, t4 = lane & 3;
    const int t0 = chunk * 64;

    const size_t kbase = ((size_t)(b*Tc + t0) * Hc + h) * Fc;
#pragma unroll
    for (int i = 0; i < 4; i++) {
        int l = tid + i * 512;
        int r = l >> 5, p = l & 31;
        *(uint4*)(smc + KVQ + ((uint32_t)r * 264 + p * 8) * 2) =
            *(const uint4*)(&g_kf[kbase + (size_t)r * (Hc*Fc) + p * 8]);
    }
#pragma unroll
    for (int i = 0; i < 2; i++) {
        int l = tid + i * 512;
        int r = l >> 4, p = l & 15;
        *(uint4*)(smc + KVV + ((uint32_t)r * 136 + p * 8) * 2) =
            *(const uint4*)(&g_v[(size_t)(b*Tc + t0 + r) * HIDc + h * 128 + p * 8]);
    }
    __syncthreads();

    float acc[4][4][4];
#pragma unroll
    for (int mf = 0; mf < 4; mf++)
#pragma unroll
        for (int nf = 0; nf < 4; nf++)
#pragma unroll
            for (int i = 0; i < 4; i++) acc[mf][nf][i] = 0.f;

    const uint32_t ca = (lane & 7) + ((lane >> 4) & 1) * 8;
    const uint32_t ma = ((lane >> 3) & 1) * 8;
    const uint32_t cb = (lane & 7) + ((lane >> 3) & 1) * 8;
    const uint32_t nb = (lane >> 4) * 8;

#pragma unroll
    for (int ks = 0; ks < 4; ks++) {
        uint32_t bb[2][4];
#pragma unroll
        for (int np = 0; np < 2; np++)
            LDSM4T(bb[np], sb + KVV + ((ks*16 + cb) * 136 + wn*32 + np*16 + nb) * 2);
#pragma unroll
        for (int mf = 0; mf < 4; mf++) {
            uint32_t a[4];
            LDSM4T(a, sb + KVQ + ((ks*16 + ca) * 264 + wm*64 + mf*16 + ma) * 2);
            mma_f16(acc[mf][0], a, bb[0]);
            mma_f16(acc[mf][1], a, bb[0] + 2);
            mma_f16(acc[mf][2], a, bb[1]);
            mma_f16(acc[mf][3], a, bb[1] + 2);
        }
    }

    // stage 256x128 fp16 result in smem (rows padded to 136 halves)
    __syncthreads();
#pragma unroll
    for (int mf = 0; mf < 4; mf++)
#pragma unroll
        for (int nf = 0; nf < 4; nf++) {
            int d = wm * 64 + mf * 16 + g;
            int e = wn * 32 + nf * 8 + t4 * 2;
            *(uint32_t*)(smc + ((uint32_t)d * 136 + e) * 2) =
                pack2(acc[mf][nf][0], acc[mf][nf][1]);
            *(uint32_t*)(smc + ((uint32_t)(d + 8) * 136 + e) * 2) =
                pack2(acc[mf][nf][2], acc[mf][nf][3]);
        }
    __syncthreads();

    // linear coalesced writes: half-warp per 256 B row
    const size_t base = (((size_t)(b*Hc + h)) * NCc + chunk) * (size_t)(Fc * Dc);
#pragma unroll
    for (int i = 0; i < 8; i++) {
        int l = tid + i * 512;
        int r = l >> 4, p = l & 15;
        *(uint4*)(&g_kvh[base + (size_t)r * 128 + p * 8]) =
            *(const uint4*)(smc + ((uint32_t)r * 136 + p * 8) * 2);
    }
}

// ---------------------------------------------------------------------------
// Exclusive prefix over chunks, fp16 in, f32 accumulate, fp16 out.
// ---------------------------------------------------------------------------
__global__ __launch_bounds__(256) void prefix_kernel()
{
    const int bh  = blockIdx.y;
    const int idx = (blockIdx.x * 256 + threadIdx.x) * 2;
    const size_t stride = (size_t)Fc * Dc;
    size_t p = (size_t)bh * NCc * stride + idx;
    float ax = 0.f, ay = 0.f;
    __half2 cur = *(const __half2*)&g_kvh[p];
    for (int i = 0; i < NCc; i++) {
        __half2 nxt;
        if (i + 1 < NCc) nxt = *(const __half2*)&g_kvh[p + stride];
        float2 t = __half22float2(cur);
        *(uint32_t*)&g_s[p] = pack2(ax, ay);
        ax += t.x; ay += t.y;
        cur = nxt;
        p += stride;
    }
}

// ---------------------------------------------------------------------------
// Output per chunk (fp16 mma): o = tril(qf @ kf^T) @ v + qf @ S  -> fp16
// S streamed in two 128-row halves over kf buffer; o staged through v buffer
// for coalesced stores. 2 CTAs/SM.
// ---------------------------------------------------------------------------
#define OQF 0
#define OKF 33792                     // kf (64x264) / S half (128x136)
#define OV  68608                     // v (64x136) / o staging (64x136)
#define OAT 86016
#define OUT_SMEM 95232

__global__ __launch_bounds__(256, 2) void out_kernel()
{
    extern __shared__ char smc[];
    const uint32_t sb = smem_u32(smc);
    const int chunk = blockIdx.x, h = blockIdx.y, b = blockIdx.z;
    const int tid = threadIdx.x, wid = tid >> 5, lane = tid & 31;
    const int g = lane >> 2, t4 = lane & 3;
    const int t0 = chunk * 64;
    const int wm = wid & 1, wn = wid >> 1;

    const size_t qbase = ((size_t)(b*Tc + t0) * Hc + h) * Fc;
#pragma unroll
    for (int i = 0; i < 8; i++) {
        int l = tid + i * 256;
        int r = l >> 5, p = l & 31;
        size_t gs = qbase + (size_t)r * (Hc*Fc) + p * 8;
        *(uint4*)(smc + OQF + ((uint32_t)r * 264 + p * 8) * 2) = *(const uint4*)(&g_qf[gs]);
        *(uint4*)(smc + OKF + ((uint32_t)r * 264 + p * 8) * 2) = *(const uint4*)(&g_kf[gs]);
    }
#pragma unroll
    for (int i = 0; i < 4; i++) {
        int l = tid + i * 256;
        int r = l >> 4, p = l & 15;
        *(uint4*)(smc + OV + ((uint32_t)r * 136 + p * 8) * 2) =
            *(const uint4*)(&g_v[(size_t)(b*Tc + t0 + r) * HIDc + h * 128 + p * 8]);
    }
    __syncthreads();

    // phase 1: scores = tril(qf @ kf^T)
    {
        float sc[2][2][4];
#pragma unroll
        for (int mf = 0; mf < 2; mf++)
#pragma unroll
            for (int nf = 0; nf < 2; nf++)
#pragma unroll
                for (int i = 0; i < 4; i++) sc[mf][nf][i] = 0.f;

        const uint32_t aoff = OQF + (uint32_t)(wm*32 + (lane&7) + ((lane>>3)&1)*8) * 528
                            + (lane>>4)*16;
        const uint32_t boff = OKF + (uint32_t)(wn*16 + (lane>>4)*8 + (lane&7)) * 528
                            + ((lane>>3)&1)*16;
#pragma unroll
        for (int ks = 0; ks < 16; ks++) {
            uint32_t a[2][4], bbf[4];
            LDSM4(a[0], sb + aoff + ks * 32);
            LDSM4(a[1], sb + aoff + 16 * 528 + ks * 32);
            LDSM4(bbf, sb + boff + ks * 32);
            mma_f16(sc[0][0], a[0], bbf);
            mma_f16(sc[0][1], a[0], bbf + 2);
            mma_f16(sc[1][0], a[1], bbf);
            mma_f16(sc[1][1], a[1], bbf + 2);
        }
#pragma unroll
        for (int mf = 0; mf < 2; mf++)
#pragma unroll
            for (int nf = 0; nf < 2; nf++) {
                int ci = wm*32 + mf*16 + g;
                int cj = wn*16 + nf*8 + t4*2;
                float v0 = (cj     <= ci) ? sc[mf][nf][0] : 0.f;
                float v1 = (cj + 1 <= ci) ? sc[mf][nf][1] : 0.f;
                *(uint32_t*)(smc + OAT + ((uint32_t)ci * 72 + cj) * 2) = pack2(v0, v1);
                int ci2 = ci + 8;
                float v2 = (cj     <= ci2) ? sc[mf][nf][2] : 0.f;
                float v3 = (cj + 1 <= ci2) ? sc[mf][nf][3] : 0.f;
                *(uint32_t*)(smc + OAT + ((uint32_t)ci2 * 72 + cj) * 2) = pack2(v2, v3);
            }
    }
    __syncthreads();

    // phase 2: o = attn @ v + qf @ S (S streamed in 2 halves over kf buffer)
    const size_t sbase = (((size_t)(b*Hc + h)) * NCc + chunk) * (size_t)(Fc * Dc);
    float o[2][4][4];
#pragma unroll
    for (int mf = 0; mf < 2; mf++)
#pragma unroll
        for (int nf = 0; nf < 4; nf++)
#pragma unroll
            for (int i = 0; i < 4; i++) o[mf][nf][i] = 0.f;

    const uint32_t cb = (lane & 7) + ((lane >> 3) & 1) * 8;
    const uint32_t nb = (lane >> 4) * 8;
    const uint32_t a2 = OQF + (uint32_t)(wm*32 + (lane&7) + ((lane>>3)&1)*8) * 528
                      + (lane>>4)*16;

#pragma unroll
    for (int i = 0; i < 8; i++) {
        int l = tid + i * 256;
        int f = l >> 4, p = l & 15;
        cp16(sb + OKF + ((uint32_t)f * 136 + p * 8) * 2,
             &g_s[sbase + (size_t)f * 128 + p * 8]);
    }
    CP_COMMIT();

    // attn @ v (independent of S)
    {
        const uint32_t a1 = OAT + (uint32_t)(wm*32 + (lane&7) + ((lane>>3)&1)*8) * 144
                          + (lane>>4)*16;
#pragma unroll
        for (int ks = 0; ks < 4; ks++) {
            uint32_t a[2][4];
            LDSM4(a[0], sb + a1 + ks * 32);
            LDSM4(a[1], sb + a1 + 16 * 144 + ks * 32);
#pragma unroll
            for (int np = 0; np < 2; np++) {
                uint32_t bbf[4];
                LDSM4T(bbf, sb + OV + ((ks*16 + cb) * 136 + wn*32 + np*16 + nb) * 2);
                mma_f16(o[0][2*np],   a[0], bbf);
                mma_f16(o[0][2*np+1], a[0], bbf + 2);
                mma_f16(o[1][2*np],   a[1], bbf);
                mma_f16(o[1][2*np+1], a[1], bbf + 2);
            }
        }
    }

    CP_WAIT(0);
    __syncthreads();

#pragma unroll
    for (int ks = 0; ks < 8; ks++) {
        uint32_t a[2][4];
        LDSM4(a[0], sb + a2 + ks * 32);
        LDSM4(a[1], sb + a2 + 16 * 528 + ks * 32);
#pragma unroll
        for (int np = 0; np < 2; np++) {
            uint32_t bbf[4];
            LDSM4T(bbf, sb + OKF + ((ks*16 + cb) * 136 + wn*32 + np*16 + nb) * 2);
            mma_f16(o[0][2*np],   a[0], bbf);
            mma_f16(o[0][2*np+1], a[0], bbf + 2);
            mma_f16(o[1][2*np],   a[1], bbf);
            mma_f16(o[1][2*np+1], a[1], bbf + 2);
        }
    }
    __syncthreads();

#pragma unroll
    for (int i = 0; i < 8; i++) {
        int l = tid + i * 256;
        int f = l >> 4, p = l & 15;
        cp16(sb + OKF + ((uint32_t)f * 136 + p * 8) * 2,
             &g_s[sbase + (size_t)(f + 128) * 128 + p * 8]);
    }
    CP_COMMIT(); CP_WAIT(0);
    __syncthreads();

#pragma unroll
    for (int ks = 8; ks < 16; ks++) {
        uint32_t a[2][4];
        LDSM4(a[0], sb + a2 + ks * 32);
        LDSM4(a[1], sb + a2 + 16 * 528 + ks * 32);
#pragma unroll
        for (int np = 0; np < 2; np++) {
            uint32_t bbf[4];
            LDSM4T(bbf, sb + OKF + (((ks-8)*16 + cb) * 136 + wn*32 + np*16 + nb) * 2);
            mma_f16(o[0][2*np],   a[0], bbf);
            mma_f16(o[0][2*np+1], a[0], bbf + 2);
            mma_f16(o[1][2*np],   a[1], bbf);
            mma_f16(o[1][2*np+1], a[1], bbf + 2);
        }
    }

    // stage o through the dead v buffer, then coalesced 16B writes
    __syncthreads();
#pragma unroll
    for (int mf = 0; mf < 2; mf++)
#pragma unroll
        for (int nf = 0; nf < 4; nf++) {
            int r = wm*32 + mf*16 + g;
            int e = wn*32 + nf*8 + t4*2;
            *(uint32_t*)(smc + OV + ((uint32_t)r * 136 + e) * 2) =
                pack2(o[mf][nf][0], o[mf][nf][1]);
            *(uint32_t*)(smc + OV + ((uint32_t)(r + 8) * 136 + e) * 2) =
                pack2(o[mf][nf][2], o[mf][nf][3]);
        }
    __syncthreads();
#pragma unroll
    for (int i = 0; i < 4; i++) {
        int l = tid + i * 256;
        int r = l >> 4, p = l & 15;
        *(uint4*)(&g_oh[(size_t)(b*Tc + t0 + r) * HIDc + h * 128 + p * 8]) =
            *(const uint4*)(smc + OV + ((uint32_t)r * 136 + p * 8) * 2);
    }
}

// ---------------------------------------------------------------------------
// Row-scale: rs[t] = rsqrt(mean(o[t]^2) + eps). One warp per token.
// ---------------------------------------------------------------------------
__global__ __launch_bounds__(256) void rowscale_kernel()
{
    const int wid = threadIdx.x >> 5, lane = threadIdx.x & 31;
    const int t = blockIdx.x * 8 + wid;
    const __half2* row = (const __half2*)(g_oh + (size_t)t * HIDc);

    float s = 0.f;
#pragma unroll
    for (int i = 0; i < 16; i++) {
        float2 v = __half22float2(row[lane + i * 32]);
        s += v.x * v.x + v.y * v.y;
    }
#pragma unroll
    for (int off = 16; off >= 1; off >>= 1)
        s += __shfl_xor_sync(0xffffffffu, s, off);

    if (lane == 0)
        g_rs[t] = rsqrtf(s * (1.f / HIDc) + 1e-5f);
}

// ---------------------------------------------------------------------------
// Launch
// ---------------------------------------------------------------------------
extern "C" void kernel_launch(void* const* d_in, const int* in_sizes, int n_in,
                              void* d_out, int out_size)
{
    const float* x    = (const float*)d_in[0];
    const float* Wq   = (const float*)d_in[1];
    const float* Wk   = (const float*)d_in[2];
    const float* Wv   = (const float*)d_in[3];
    const float* Wo   = (const float*)d_in[4];
    const float* fmqw = (const float*)d_in[5];
    const float* fmqb = (const float*)d_in[6];
    const float* fmkw = (const float*)d_in[7];
    const float* fmkb = (const float*)d_in[8];
    float* out = (float*)d_out;

    __half* xh;
    cudaGetSymbolAddress((void**)&xh, g_xh);

    cudaFuncSetAttribute(gemm_qkv,  cudaFuncAttributeMaxDynamicSharedMemorySize, GEMM_SMEM);
    cudaFuncSetAttribute(gemm_o,    cudaFuncAttributeMaxDynamicSharedMemorySize, GEMM_SMEM);
    cudaFuncSetAttribute(fold_w,    cudaFuncAttributeMaxDynamicSharedMemorySize, FOLD_SMEM);
    cudaFuncSetAttribute(kv_kernel, cudaFuncAttributeMaxDynamicSharedMemorySize, KV_SMEM);
    cudaFuncSetAttribute(out_kernel,cudaFuncAttributeMaxDynamicSharedMemorySize, OUT_SMEM);

    // conversions + weight folding
    f2h<<<MTOT*HIDc/2048, 256>>>(x, xh, MTOT*HIDc);
    wconv<<<dim3(HIDc*HIDc/2048, 1, 2), 256>>>(Wv, Wo);
    fold_w<<<dim3(8, 8, 2), 256, FOLD_SMEM>>>(fmqw, fmkw, Wq, Wk);

    // fused QKV GEMM + hedgehog softmax epilogue
    gemm_qkv<<<dim3(HIDc/128, MTOT/128, 3), 256, GEMM_SMEM>>>(fmqb, fmkb);

    dim3 cg(NCc, Hc, Bc);
    kv_kernel<<<cg, 512, KV_SMEM>>>();
    prefix_kernel<<<dim3(64, Bc*Hc), 256>>>();
    out_kernel<<<cg, 256, OUT_SMEM>>>();

    rowscale_kernel<<<MTOT/8, 256>>>();
    gemm_o<<<dim3(HIDc/128, MTOT/128, 1), 256, GEMM_SMEM>>>(out);
}

// round 12
// speedup vs baseline: 1.2713x; 1.0134x over previous
#include <cuda_runtime.h>
#include <cuda_fp16.h>
#include <cstdint>
#include <math.h>

// Problem constants
#define Bc   2
#define Tc   8192
#define Hc   8
#define Dc   128
#define HIDc 1024
#define NCc  128          // T / CHUNK
#define Fc   256          // hedgehog feature dim (2*DQK)
#define MTOT (Bc*Tc)      // 16384 tokens

// ---------------------------------------------------------------------------
// Scratch (device globals — no allocations allowed)
// ---------------------------------------------------------------------------
__device__ __half g_xh  [(size_t)MTOT*HIDc];      // 32 MB
__device__ __half g_wvh [HIDc*HIDc];
__device__ __half g_woh [HIDc*HIDc];
__device__ __half g_wq2 [HIDc*HIDc];              // folded fmq @ Wq (per head)
__device__ __half g_wk2 [HIDc*HIDc];              // folded fmk @ Wk
__device__ __half g_v   [(size_t)MTOT*HIDc];
__device__ __half g_qf  [(size_t)MTOT*Hc*Fc];     // 64 MB (pre-scaled)
__device__ __half g_kf  [(size_t)MTOT*Hc*Fc];     // 64 MB
__device__ __half g_kvh [(size_t)Bc*Hc*NCc*Fc*Dc]; // 128 MB per-chunk KV (fp16)
__device__ __half g_s   [(size_t)Bc*Hc*NCc*Fc*Dc]; // 128 MB exclusive prefix (fp16)
__device__ __half g_oh  [(size_t)MTOT*HIDc];      // attention out (unnormalized)
__device__ float  g_prs [MTOT*Hc];                // per-(token,head) partial sumsq
__device__ float  g_rs  [MTOT];                   // rmsnorm row scales

// ---------------------------------------------------------------------------
// Helpers
// ---------------------------------------------------------------------------
__device__ __forceinline__ uint32_t smem_u32(const void* p) {
    uint32_t a;
    asm("{ .reg .u64 t; cvta.to.shared.u64 t, %1; cvt.u32.u64 %0, t; }" : "=r"(a) : "l"(p));
    return a;
}
__device__ __forceinline__ uint32_t pack2(float lo, float hi) {
    __half2 h = __floats2half2_rn(lo, hi);
    return *reinterpret_cast<uint32_t*>(&h);
}
__device__ __forceinline__ void mma_f16(float* c, const uint32_t* a, const uint32_t* b) {
    asm volatile(
        "mma.sync.aligned.m16n8k16.row.col.f32.f16.f16.f32 "
        "{%0,%1,%2,%3}, {%4,%5,%6,%7}, {%8,%9}, {%0,%1,%2,%3};"
        : "+f"(c[0]), "+f"(c[1]), "+f"(c[2]), "+f"(c[3])
        : "r"(a[0]), "r"(a[1]), "r"(a[2]), "r"(a[3]), "r"(b[0]), "r"(b[1]));
}
#define LDSM4(r, addr) \
    asm volatile("ldmatrix.sync.aligned.m8n8.x4.shared.b16 {%0,%1,%2,%3}, [%4];" \
        : "=r"((r)[0]), "=r"((r)[1]), "=r"((r)[2]), "=r"((r)[3]) : "r"(addr))
#define LDSM4T(r, addr) \
    asm volatile("ldmatrix.sync.aligned.m8n8.x4.trans.shared.b16 {%0,%1,%2,%3}, [%4];" \
        : "=r"((r)[0]), "=r"((r)[1]), "=r"((r)[2]), "=r"((r)[3]) : "r"(addr))
__device__ __forceinline__ void cp16(uint32_t dst, const void* src) {
    asm volatile("cp.async.cg.shared.global [%0], [%1], 16;" :: "r"(dst), "l"(src) : "memory");
}
#define CP_COMMIT() asm volatile("cp.async.commit_group;" ::: "memory")
#define CP_WAIT(n)  asm volatile("cp.async.wait_group %0;" :: "n"(n) : "memory")

// ---------------------------------------------------------------------------
// f32 -> f16 conversion (n multiple of 2048)
// ---------------------------------------------------------------------------
__global__ __launch_bounds__(256) void f2h(const float* __restrict__ s,
                                           __half* __restrict__ d, int n)
{
    int i = (blockIdx.x * 256 + threadIdx.x) * 8;
    if (i < n) {
        float4 a = *(const float4*)(s + i), b = *(const float4*)(s + i + 4);
        *(uint4*)(d + i) = make_uint4(pack2(a.x, a.y), pack2(a.z, a.w),
                                      pack2(b.x, b.y), pack2(b.z, b.w));
    }
}
// Wv, Wo conversion (grid.z selects)
__global__ __launch_bounds__(256) void wconv(
    const float* __restrict__ w0, const float* __restrict__ w1)
{
    const int z = blockIdx.z;
    const float* s = z ? w1 : w0;
    __half* d = z ? g_woh : g_wvh;
    int i = (blockIdx.x * 256 + threadIdx.x) * 8;
    float4 a = *(const float4*)(s + i), b = *(const float4*)(s + i + 4);
    *(uint4*)(d + i) = make_uint4(pack2(a.x, a.y), pack2(a.z, a.w),
                                  pack2(b.x, b.y), pack2(b.z, b.w));
}

// ---------------------------------------------------------------------------
// Fold: W2[h*128+i, c] = sum_j fm[i,j] * W[h*128+j, c]   (reads f32 W directly)
// ---------------------------------------------------------------------------
#define FSKP 136
#define FD_A 0
#define FD_B (128*FSKP*2)               // 34816
#define FOLD_SMEM (2*128*FSKP*2)        // 69632

__global__ __launch_bounds__(256) void fold_w(
    const float* __restrict__ fmq, const float* __restrict__ fmk,
    const float* __restrict__ Wq,  const float* __restrict__ Wk)
{
    const int z = blockIdx.z;
    const float* fm = z ? fmk : fmq;
    const float* Wf = z ? Wk : Wq;
    __half* W2 = z ? g_wk2 : g_wq2;

    extern __shared__ char smc[];
    const uint32_t sb = smem_u32(smc);
    const int tid = threadIdx.x, wid = tid >> 5, lane = tid & 31;
    const int wm = wid & 3, wn = wid >> 2;
    const int qr = lane >> 2, qc = lane & 3;
    const int ct = blockIdx.x, h = blockIdx.y;

#pragma unroll
    for (int it = 0; it < 16; it++) {
        int e = tid + it * 256;
        int r = e >> 5, c4 = e & 31;
        float4 f = *(const float4*)(fm + r * 128 + c4 * 4);
        *(uint2*)(smc + FD_A + ((uint32_t)r * FSKP + c4 * 4) * 2) =
            make_uint2(pack2(f.x, f.y), pack2(f.z, f.w));
    }
#pragma unroll
    for (int it = 0; it < 16; it++) {
        int e = tid + it * 256;
        int r = e >> 5, c4 = e & 31;
        float4 f = *(const float4*)(Wf + (size_t)(h * 128 + r) * 1024 + ct * 128 + c4 * 4);
        *(uint2*)(smc + FD_B + ((uint32_t)r * FSKP + c4 * 4) * 2) =
            make_uint2(pack2(f.x, f.y), pack2(f.z, f.w));
    }
    __syncthreads();

    float acc[2][8][4];
#pragma unroll
    for (int mf = 0; mf < 2; mf++)
#pragma unroll
        for (int nf = 0; nf < 8; nf++)
#pragma unroll
            for (int i = 0; i < 4; i++) acc[mf][nf][i] = 0.f;

    const uint32_t a_off = FD_A + (uint32_t)(wm*32 + (lane&7) + ((lane>>3)&1)*8) * (FSKP*2)
                         + (lane>>4)*16;
    const uint32_t cb = (lane & 7) + ((lane >> 3) & 1) * 8;
    const uint32_t nb = (lane >> 4) * 8;

#pragma unroll
    for (int ks = 0; ks < 8; ks++) {
        uint32_t a[2][4];
        LDSM4(a[0], sb + a_off + ks * 32);
        LDSM4(a[1], sb + a_off + 16 * FSKP * 2 + ks * 32);
#pragma unroll
        for (int np = 0; np < 4; np++) {
            uint32_t b[4];
            LDSM4T(b, sb + FD_B + ((ks*16 + cb) * FSKP + wn*64 + np*16 + nb) * 2);
            mma_f16(acc[0][2*np],   a[0], b);
            mma_f16(acc[0][2*np+1], a[0], b + 2);
            mma_f16(acc[1][2*np],   a[1], b);
            mma_f16(acc[1][2*np+1], a[1], b + 2);
        }
    }

#pragma unroll
    for (int mf = 0; mf < 2; mf++) {
        const int i0 = h * 128 + wm * 32 + mf * 16 + qr;
#pragma unroll
        for (int nf = 0; nf < 8; nf++) {
            const int c0 = ct * 128 + wn * 64 + nf * 8 + qc * 2;
            *(uint32_t*)&W2[(size_t)i0 * 1024 + c0] = pack2(acc[mf][nf][0], acc[mf][nf][1]);
            *(uint32_t*)&W2[(size_t)(i0 + 8) * 1024 + c0] = pack2(acc[mf][nf][2], acc[mf][nf][3]);
        }
    }
}

// ---------------------------------------------------------------------------
// GEMM core macros (CTA 128x128, BK=64, 3-stage, 8 warps 4x2, 2 CTAs/SM)
// ---------------------------------------------------------------------------
#define SKP_B   144                   // 64 halves + 8 pad = 144 bytes per row
#define GA_B    (128*SKP_B)           // 18432
#define GSTG    (2*GA_B)              // 36864
#define GEMM_SMEM (3*GSTG)            // 110592

#define GEMM_MAIN(X, W)                                                    \
    const int pr = tid >> 3, pp = tid & 7;                                 \
    const __half* Xp = (X) + (size_t)(m0 + pr) * 1024 + pp * 8;            \
    const __half* Wp = (W) + (size_t)(n0 + pr) * 1024 + pp * 8;            \
    const uint32_t a_off = (uint32_t)(wm*32 + (lane&7) + ((lane>>3)&1)*8) * SKP_B \
                         + (lane>>4)*16;                                   \
    const uint32_t b_off = (uint32_t)(wn*64 + (lane>>4)*8 + (lane&7)) * SKP_B \
                         + ((lane>>3)&1)*16;                               \
    float acc[2][8][4];                                                    \
    _Pragma("unroll")                                                      \
    for (int mf = 0; mf < 2; mf++)                                         \
        _Pragma("unroll")                                                  \
        for (int nf = 0; nf < 8; nf++)                                     \
            _Pragma("unroll")                                              \
            for (int i = 0; i < 4; i++) acc[mf][nf][i] = 0.f;              \
    LOAD_STAGE(0, 0); CP_COMMIT();                                         \
    LOAD_STAGE(1, 1); CP_COMMIT();                                         \
    for (int kt = 0; kt < 16; kt++) {                                      \
        const int st = kt % 3;                                             \
        CP_WAIT(1);                                                        \
        __syncthreads();                                                   \
        const uint32_t As = sb + st * GSTG, Bs = As + GA_B;                \
        _Pragma("unroll")                                                  \
        for (int ks = 0; ks < 4; ks++) {                                   \
            uint32_t a[2][4];                                              \
            LDSM4(a[0], As + a_off + ks * 32);                             \
            LDSM4(a[1], As + a_off + 16 * SKP_B + ks * 32);                \
            _Pragma("unroll")                                              \
            for (int np = 0; np < 4; np++) {                               \
                uint32_t b[4];                                             \
                LDSM4(b, Bs + b_off + np * (16 * SKP_B) + ks * 32);        \
                mma_f16(acc[0][2*np],   a[0], b);                          \
                mma_f16(acc[0][2*np+1], a[0], b + 2);                      \
                mma_f16(acc[1][2*np],   a[1], b);                          \
                mma_f16(acc[1][2*np+1], a[1], b + 2);                      \
            }                                                              \
        }                                                                  \
        if (kt + 2 < 16) LOAD_STAGE(kt + 2, (kt + 2) % 3);                 \
        CP_COMMIT();                                                       \
    }

#define LOAD_STAGE(kt, st) {                                              \
    uint32_t base = sb + (st) * GSTG;                                     \
    const __half* xk = Xp + (kt) * 64;                                    \
    const __half* wk = Wp + (kt) * 64;                                    \
    _Pragma("unroll")                                                     \
    for (int i = 0; i < 4; i++) {                                         \
        uint32_t so = (uint32_t)(pr + 32*i) * SKP_B + pp * 16;            \
        cp16(base + so, xk + (size_t)(32*i) * 1024);                      \
        cp16(base + GA_B + so, wk + (size_t)(32*i) * 1024);               \
    } }

// ---------------------------------------------------------------------------
// Fused QKV GEMM. z=0: q (softmax epilogue, scale 1/16), z=1: k (softmax),
// z=2: v (fp16 write).
// ---------------------------------------------------------------------------
__global__ __launch_bounds__(256, 2) void gemm_qkv(
    const float* __restrict__ biasq, const float* __restrict__ biask)
{
    const int z = blockIdx.z;
    const __half* W = (z == 0) ? g_wq2 : ((z == 1) ? g_wk2 : g_wvh);

    extern __shared__ char smc[];
    const uint32_t sb = smem_u32(smc);
    const int tid = threadIdx.x, wid = tid >> 5, lane = tid & 31;
    const int wm = wid & 3, wn = wid >> 2;
    const int qr = lane >> 2, qc = lane & 3;
    const int m0 = blockIdx.y * 128, n0 = blockIdx.x * 128;

    GEMM_MAIN(g_xh, W)

    if (z == 2) {
#pragma unroll
        for (int mf = 0; mf < 2; mf++) {
            const int r0 = m0 + wm * 32 + mf * 16 + qr;
#pragma unroll
            for (int nf = 0; nf < 8; nf++) {
                const int c0 = n0 + wn * 64 + nf * 8 + qc * 2;
                *(uint32_t*)&g_v[(size_t)r0 * 1024 + c0] =
                    pack2(acc[mf][nf][0], acc[mf][nf][1]);
                *(uint32_t*)&g_v[(size_t)(r0 + 8) * 1024 + c0] =
                    pack2(acc[mf][nf][2], acc[mf][nf][3]);
            }
        }
        return;
    }

    // q/k: hedgehog softmax epilogue. Reuse stage smem as f32 ys[128][132].
    __syncthreads();
    float* ys = (float*)smc;
#pragma unroll
    for (int mf = 0; mf < 2; mf++) {
        const int r0 = wm * 32 + mf * 16 + qr;
#pragma unroll
        for (int nf = 0; nf < 8; nf++) {
            const int c0 = wn * 64 + nf * 8 + qc * 2;
            *(float2*)(ys + r0 * 132 + c0) = make_float2(acc[mf][nf][0], acc[mf][nf][1]);
            *(float2*)(ys + (r0 + 8) * 132 + c0) = make_float2(acc[mf][nf][2], acc[mf][nf][3]);
        }
    }
    __syncthreads();

    const float* bias = z ? biask : biasq;
    const float scale = z ? 1.0f : 0.0625f;   // 256^-0.5 folded into qf
    __half* dst = z ? g_kf : g_qf;
    const int h = blockIdx.x;
    float4 bv = *(const float4*)(bias + lane * 4);

    for (int rr = 0; rr < 16; rr += 2) {
        const int r0 = wid * 16 + rr;
        float y[2][4], m[2];
#pragma unroll
        for (int u = 0; u < 2; u++) {
            float4 v4 = *(const float4*)(ys + (r0 + u) * 132 + lane * 4);
            y[u][0] = 2.f * (v4.x + bv.x); y[u][1] = 2.f * (v4.y + bv.y);
            y[u][2] = 2.f * (v4.z + bv.z); y[u][3] = 2.f * (v4.w + bv.w);
            m[u] = fmaxf(fmaxf(fabsf(y[u][0]), fabsf(y[u][1])),
                         fmaxf(fabsf(y[u][2]), fabsf(y[u][3])));
        }
#pragma unroll
        for (int off = 16; off >= 1; off >>= 1) {
            m[0] = fmaxf(m[0], __shfl_xor_sync(0xffffffffu, m[0], off));
            m[1] = fmaxf(m[1], __shfl_xor_sync(0xffffffffu, m[1], off));
        }
        float ep[2][4], en[2][4], zs[2] = {0.f, 0.f};
#pragma unroll
        for (int u = 0; u < 2; u++)
#pragma unroll
            for (int j = 0; j < 4; j++) {
                ep[u][j] = __expf( y[u][j] - m[u]);
                en[u][j] = __expf(-y[u][j] - m[u]);
                zs[u] += ep[u][j] + en[u][j];
            }
#pragma unroll
        for (int off = 16; off >= 1; off >>= 1) {
            zs[0] += __shfl_xor_sync(0xffffffffu, zs[0], off);
            zs[1] += __shfl_xor_sync(0xffffffffu, zs[1], off);
        }
#pragma unroll
        for (int u = 0; u < 2; u++) {
            const float inv = scale / zs[u];
            __half* drow = dst + ((size_t)(m0 + r0 + u) * Hc + h) * Fc;
            *(uint2*)(drow + lane * 4) =
                make_uint2(pack2(ep[u][0]*inv, ep[u][1]*inv),
                           pack2(ep[u][2]*inv, ep[u][3]*inv));
            *(uint2*)(drow + 128 + lane * 4) =
                make_uint2(pack2(en[u][0]*inv, en[u][1]*inv),
                           pack2(en[u][2]*inv, en[u][3]*inv));
        }
    }
}

// ---------------------------------------------------------------------------
// Wo GEMM with rmsnorm row-scale epilogue: out[r][c] = rs[r] * (o @ Wo^T)
// ---------------------------------------------------------------------------
__global__ __launch_bounds__(256, 2) void gemm_o(float* __restrict__ out)
{
    extern __shared__ char smc[];
    const uint32_t sb = smem_u32(smc);
    const int tid = threadIdx.x, wid = tid >> 5, lane = tid & 31;
    const int wm = wid & 3, wn = wid >> 2;
    const int qr = lane >> 2, qc = lane & 3;
    const int m0 = blockIdx.y * 128, n0 = blockIdx.x * 128;

    GEMM_MAIN(g_oh, g_woh)

#pragma unroll
    for (int mf = 0; mf < 2; mf++) {
        const int r0 = m0 + wm * 32 + mf * 16 + qr;
        const float s0 = g_rs[r0], s1 = g_rs[r0 + 8];
#pragma unroll
        for (int nf = 0; nf < 8; nf++) {
            const int c0 = n0 + wn * 64 + nf * 8 + qc * 2;
            *(float2*)&out[(size_t)r0 * 1024 + c0] =
                make_float2(acc[mf][nf][0] * s0, acc[mf][nf][1] * s0);
            *(float2*)&out[(size_t)(r0 + 8) * 1024 + c0] =
                make_float2(acc[mf][nf][2] * s1, acc[mf][nf][3] * s1);
        }
    }
}

// ---------------------------------------------------------------------------
// KV per chunk (fp16 mma): KV[d,e] = sum_c kf[c,d] * v[c,e]  (256 x 128)
// Output staged through smem for coalesced 16B stores.
// ---------------------------------------------------------------------------
#define KVQ 0
#define KVV 33792
#define KV_SMEM 69632                 // staging 256x136 fp16 overlays kf+v

__global__ __launch_bounds__(512) void kv_kernel()
{
    extern __shared__ char smc[];
    const uint32_t sb = smem_u32(smc);
    const int chunk = blockIdx.x, h = blockIdx.y, b = blockIdx.z;
    const int tid = threadIdx.x, wid = tid >> 5, lane = tid & 31;
    const int wm = wid & 3, wn = wid >> 2;
    const int g = lane >> 2, t4 = lane & 3;
    const int t0 = chunk * 64;

    const size_t kbase = ((size_t)(b*Tc + t0) * Hc + h) * Fc;
#pragma unroll
    for (int i = 0; i < 4; i++) {
        int l = tid + i * 512;
        int r = l >> 5, p = l & 31;
        *(uint4*)(smc + KVQ + ((uint32_t)r * 264 + p * 8) * 2) =
            *(const uint4*)(&g_kf[kbase + (size_t)r * (Hc*Fc) + p * 8]);
    }
#pragma unroll
    for (int i = 0; i < 2; i++) {
        int l = tid + i * 512;
        int r = l >> 4, p = l & 15;
        *(uint4*)(smc + KVV + ((uint32_t)r * 136 + p * 8) * 2) =
            *(const uint4*)(&g_v[(size_t)(b*Tc + t0 + r) * HIDc + h * 128 + p * 8]);
    }
    __syncthreads();

    float acc[4][4][4];
#pragma unroll
    for (int mf = 0; mf < 4; mf++)
#pragma unroll
        for (int nf = 0; nf < 4; nf++)
#pragma unroll
            for (int i = 0; i < 4; i++) acc[mf][nf][i] = 0.f;

    const uint32_t ca = (lane & 7) + ((lane >> 4) & 1) * 8;
    const uint32_t ma = ((lane >> 3) & 1) * 8;
    const uint32_t cb = (lane & 7) + ((lane >> 3) & 1) * 8;
    const uint32_t nb = (lane >> 4) * 8;

#pragma unroll
    for (int ks = 0; ks < 4; ks++) {
        uint32_t bb[2][4];
#pragma unroll
        for (int np = 0; np < 2; np++)
            LDSM4T(bb[np], sb + KVV + ((ks*16 + cb) * 136 + wn*32 + np*16 + nb) * 2);
#pragma unroll
        for (int mf = 0; mf < 4; mf++) {
            uint32_t a[4];
            LDSM4T(a, sb + KVQ + ((ks*16 + ca) * 264 + wm*64 + mf*16 + ma) * 2);
            mma_f16(acc[mf][0], a, bb[0]);
            mma_f16(acc[mf][1], a, bb[0] + 2);
            mma_f16(acc[mf][2], a, bb[1]);
            mma_f16(acc[mf][3], a, bb[1] + 2);
        }
    }

    // stage 256x128 fp16 result in smem (rows padded to 136 halves)
    __syncthreads();
#pragma unroll
    for (int mf = 0; mf < 4; mf++)
#pragma unroll
        for (int nf = 0; nf < 4; nf++) {
            int d = wm * 64 + mf * 16 + g;
            int e = wn * 32 + nf * 8 + t4 * 2;
            *(uint32_t*)(smc + ((uint32_t)d * 136 + e) * 2) =
                pack2(acc[mf][nf][0], acc[mf][nf][1]);
            *(uint32_t*)(smc + ((uint32_t)(d + 8) * 136 + e) * 2) =
                pack2(acc[mf][nf][2], acc[mf][nf][3]);
        }
    __syncthreads();

    const size_t base = (((size_t)(b*Hc + h)) * NCc + chunk) * (size_t)(Fc * Dc);
#pragma unroll
    for (int i = 0; i < 8; i++) {
        int l = tid + i * 512;
        int r = l >> 4, p = l & 15;
        *(uint4*)(&g_kvh[base + (size_t)r * 128 + p * 8]) =
            *(const uint4*)(smc + ((uint32_t)r * 136 + p * 8) * 2);
    }
}

// ---------------------------------------------------------------------------
// Exclusive prefix over chunks, fp16 in, f32 accumulate, fp16 out.
// Unrolled x2 with prefetch (MLP 4).
// ---------------------------------------------------------------------------
__global__ __launch_bounds__(256) void prefix_kernel()
{
    const int bh  = blockIdx.y;
    const int idx = (blockIdx.x * 256 + threadIdx.x) * 2;
    const size_t stride = (size_t)Fc * Dc;
    size_t p = (size_t)bh * NCc * stride + idx;
    float ax = 0.f, ay = 0.f;
    __half2 c0 = *(const __half2*)&g_kvh[p];
    __half2 c1 = *(const __half2*)&g_kvh[p + stride];
    for (int i = 0; i < NCc; i += 2) {
        __half2 n0, n1;
        if (i + 2 < NCc) {
            n0 = *(const __half2*)&g_kvh[p + 2 * stride];
            n1 = *(const __half2*)&g_kvh[p + 3 * stride];
        }
        float2 t0 = __half22float2(c0);
        *(uint32_t*)&g_s[p] = pack2(ax, ay);
        ax += t0.x; ay += t0.y;
        float2 t1 = __half22float2(c1);
        *(uint32_t*)&g_s[p + stride] = pack2(ax, ay);
        ax += t1.x; ay += t1.y;
        c0 = n0; c1 = n1;
        p += 2 * stride;
    }
}

// ---------------------------------------------------------------------------
// Output per chunk (fp16 mma): o = tril(qf @ kf^T) @ v + qf @ S  -> fp16
// S streamed in 4x64-row quarters, double-buffered in the dead kf region.
// o staged through v buffer for coalesced stores + per-token sumsq partials.
// 2 CTAs/SM.
// ---------------------------------------------------------------------------
#define OQF 0
#define OKF 33792                     // kf (64x264) / S quarter bufs (2 x 64x136)
#define OSQ(i) (OKF + (i)*17408)
#define OV  68608                     // v (64x136) / o staging (64x136)
#define OAT 86016
#define OUT_SMEM 95232

__global__ __launch_bounds__(256, 2) void out_kernel()
{
    extern __shared__ char smc[];
    const uint32_t sb = smem_u32(smc);
    const int chunk = blockIdx.x, h = blockIdx.y, b = blockIdx.z;
    const int tid = threadIdx.x, wid = tid >> 5, lane = tid & 31;
    const int g = lane >> 2, t4 = lane & 3;
    const int t0 = chunk * 64;
    const int wm = wid & 1, wn = wid >> 1;

    const size_t qbase = ((size_t)(b*Tc + t0) * Hc + h) * Fc;
#pragma unroll
    for (int i = 0; i < 8; i++) {
        int l = tid + i * 256;
        int r = l >> 5, p = l & 31;
        size_t gs = qbase + (size_t)r * (Hc*Fc) + p * 8;
        *(uint4*)(smc + OQF + ((uint32_t)r * 264 + p * 8) * 2) = *(const uint4*)(&g_qf[gs]);
        *(uint4*)(smc + OKF + ((uint32_t)r * 264 + p * 8) * 2) = *(const uint4*)(&g_kf[gs]);
    }
#pragma unroll
    for (int i = 0; i < 4; i++) {
        int l = tid + i * 256;
        int r = l >> 4, p = l & 15;
        *(uint4*)(smc + OV + ((uint32_t)r * 136 + p * 8) * 2) =
            *(const uint4*)(&g_v[(size_t)(b*Tc + t0 + r) * HIDc + h * 128 + p * 8]);
    }
    __syncthreads();

    // phase 1: scores = tril(qf @ kf^T)
    {
        float sc[2][2][4];
#pragma unroll
        for (int mf = 0; mf < 2; mf++)
#pragma unroll
            for (int nf = 0; nf < 2; nf++)
#pragma unroll
                for (int i = 0; i < 4; i++) sc[mf][nf][i] = 0.f;

        const uint32_t aoff = OQF + (uint32_t)(wm*32 + (lane&7) + ((lane>>3)&1)*8) * 528
                            + (lane>>4)*16;
        const uint32_t boff = OKF + (uint32_t)(wn*16 + (lane>>4)*8 + (lane&7)) * 528
                            + ((lane>>3)&1)*16;
#pragma unroll
        for (int ks = 0; ks < 16; ks++) {
            uint32_t a[2][4], bbf[4];
            LDSM4(a[0], sb + aoff + ks * 32);
            LDSM4(a[1], sb + aoff + 16 * 528 + ks * 32);
            LDSM4(bbf, sb + boff + ks * 32);
            mma_f16(sc[0][0], a[0], bbf);
            mma_f16(sc[0][1], a[0], bbf + 2);
            mma_f16(sc[1][0], a[1], bbf);
            mma_f16(sc[1][1], a[1], bbf + 2);
        }
#pragma unroll
        for (int mf = 0; mf < 2; mf++)
#pragma unroll
            for (int nf = 0; nf < 2; nf++) {
                int ci = wm*32 + mf*16 + g;
                int cj = wn*16 + nf*8 + t4*2;
                float v0 = (cj     <= ci) ? sc[mf][nf][0] : 0.f;
                float v1 = (cj + 1 <= ci) ? sc[mf][nf][1] : 0.f;
                *(uint32_t*)(smc + OAT + ((uint32_t)ci * 72 + cj) * 2) = pack2(v0, v1);
                int ci2 = ci + 8;
                float v2 = (cj     <= ci2) ? sc[mf][nf][2] : 0.f;
                float v3 = (cj + 1 <= ci2) ? sc[mf][nf][3] : 0.f;
                *(uint32_t*)(smc + OAT + ((uint32_t)ci2 * 72 + cj) * 2) = pack2(v2, v3);
            }
    }
    __syncthreads();

    // phase 2: o = attn @ v + qf @ S, S in 4 quarters double-buffered
    const size_t sbase = (((size_t)(b*Hc + h)) * NCc + chunk) * (size_t)(Fc * Dc);
    float o[2][4][4];
#pragma unroll
    for (int mf = 0; mf < 2; mf++)
#pragma unroll
        for (int nf = 0; nf < 4; nf++)
#pragma unroll
            for (int i = 0; i < 4; i++) o[mf][nf][i] = 0.f;

    const uint32_t cb = (lane & 7) + ((lane >> 3) & 1) * 8;
    const uint32_t nb = (lane >> 4) * 8;
    const uint32_t a2 = OQF + (uint32_t)(wm*32 + (lane&7) + ((lane>>3)&1)*8) * 528
                      + (lane>>4)*16;

    // issue S quarters 0 and 1 (each: 64 rows x 128 halves = 4 cp16/thread)
#pragma unroll
    for (int qq = 0; qq < 2; qq++) {
#pragma unroll
        for (int i = 0; i < 4; i++) {
            int l = tid + i * 256;
            int f = l >> 4, p = l & 15;
            cp16(sb + OSQ(qq) + ((uint32_t)f * 136 + p * 8) * 2,
                 &g_s[sbase + (size_t)(qq * 64 + f) * 128 + p * 8]);
        }
        CP_COMMIT();
    }

    // attn @ v (independent of S; overlaps S loads)
    {
        const uint32_t a1 = OAT + (uint32_t)(wm*32 + (lane&7) + ((lane>>3)&1)*8) * 144
                          + (lane>>4)*16;
#pragma unroll
        for (int ks = 0; ks < 4; ks++) {
            uint32_t a[2][4];
            LDSM4(a[0], sb + a1 + ks * 32);
            LDSM4(a[1], sb + a1 + 16 * 144 + ks * 32);
#pragma unroll
            for (int np = 0; np < 2; np++) {
                uint32_t bbf[4];
                LDSM4T(bbf, sb + OV + ((ks*16 + cb) * 136 + wn*32 + np*16 + nb) * 2);
                mma_f16(o[0][2*np],   a[0], bbf);
                mma_f16(o[0][2*np+1], a[0], bbf + 2);
                mma_f16(o[1][2*np],   a[1], bbf);
                mma_f16(o[1][2*np+1], a[1], bbf + 2);
            }
        }
    }

    // quarters loop
#pragma unroll
    for (int qq = 0; qq < 4; qq++) {
        if (qq < 3) { CP_WAIT(1); } else { CP_WAIT(0); }
        __syncthreads();
        const uint32_t sq = sb + OSQ(qq & 1);
#pragma unroll
        for (int kss = 0; kss < 4; kss++) {
            const int ks = qq * 4 + kss;
            uint32_t a[2][4];
            LDSM4(a[0], sb + a2 + ks * 32);
            LDSM4(a[1], sb + a2 + 16 * 528 + ks * 32);
#pragma unroll
            for (int np = 0; np < 2; np++) {
                uint32_t bbf[4];
                LDSM4T(bbf, sq + ((kss*16 + cb) * 136 + wn*32 + np*16 + nb) * 2);
                mma_f16(o[0][2*np],   a[0], bbf);
                mma_f16(o[0][2*np+1], a[0], bbf + 2);
                mma_f16(o[1][2*np],   a[1], bbf);
                mma_f16(o[1][2*np+1], a[1], bbf + 2);
            }
        }
        __syncthreads();   // done reading buf (qq&1) before refill
        if (qq + 2 < 4) {
#pragma unroll
            for (int i = 0; i < 4; i++) {
                int l = tid + i * 256;
                int f = l >> 4, p = l & 15;
                cp16(sb + OSQ(qq & 1) + ((uint32_t)f * 136 + p * 8) * 2,
                     &g_s[sbase + (size_t)((qq + 2) * 64 + f) * 128 + p * 8]);
            }
            CP_COMMIT();
        }
    }

    // stage o through the dead v buffer, then coalesced 16B writes + sumsq
#pragma unroll
    for (int mf = 0; mf < 2; mf++)
#pragma unroll
        for (int nf = 0; nf < 4; nf++) {
            int r = wm*32 + mf*16 + g;
            int e = wn*32 + nf*8 + t4*2;
            *(uint32_t*)(smc + OV + ((uint32_t)r * 136 + e) * 2) =
                pack2(o[mf][nf][0], o[mf][nf][1]);
            *(uint32_t*)(smc + OV + ((uint32_t)(r + 8) * 136 + e) * 2) =
                pack2(o[mf][nf][2], o[mf][nf][3]);
        }
    __syncthreads();
#pragma unroll
    for (int i = 0; i < 4; i++) {
        int l = tid + i * 256;
        int r = l >> 4, p = l & 15;
        *(uint4*)(&g_oh[(size_t)(b*Tc + t0 + r) * HIDc + h * 128 + p * 8]) =
            *(const uint4*)(smc + OV + ((uint32_t)r * 136 + p * 8) * 2);
    }

    // per-token sumsq partial (rmsnorm): 4 threads per token, 32 dims each
    {
        const int r = tid >> 2, part = tid & 3;
        float s = 0.f;
        const __half2* row = (const __half2*)(smc + OV + (uint32_t)r * 136 * 2);
#pragma unroll
        for (int j = 0; j < 16; j++) {
            float2 v = __half22float2(row[part * 16 + j]);
            s += v.x * v.x + v.y * v.y;
        }
        s += __shfl_xor_sync(0xffffffffu, s, 1);
        s += __shfl_xor_sync(0xffffffffu, s, 2);
        if (part == 0)
            g_prs[(size_t)(b*Tc + t0 + r) * Hc + h] = s;
    }
}

// ---------------------------------------------------------------------------
// Combine per-head sumsq partials -> row scales
// ---------------------------------------------------------------------------
__global__ __launch_bounds__(256) void rowscale_combine()
{
    const int t = blockIdx.x * 256 + threadIdx.x;
    float4 a = *(const float4*)&g_prs[(size_t)t * Hc];
    float4 b = *(const float4*)&g_prs[(size_t)t * Hc + 4];
    float s = a.x + a.y + a.z + a.w + b.x + b.y + b.z + b.w;
    g_rs[t] = rsqrtf(s * (1.f / HIDc) + 1e-5f);
}

// ---------------------------------------------------------------------------
// Launch
// ---------------------------------------------------------------------------
extern "C" void kernel_launch(void* const* d_in, const int* in_sizes, int n_in,
                              void* d_out, int out_size)
{
    const float* x    = (const float*)d_in[0];
    const float* Wq   = (const float*)d_in[1];
    const float* Wk   = (const float*)d_in[2];
    const float* Wv   = (const float*)d_in[3];
    const float* Wo   = (const float*)d_in[4];
    const float* fmqw = (const float*)d_in[5];
    const float* fmqb = (const float*)d_in[6];
    const float* fmkw = (const float*)d_in[7];
    const float* fmkb = (const float*)d_in[8];
    float* out = (float*)d_out;

    __half* xh;
    cudaGetSymbolAddress((void**)&xh, g_xh);

    cudaFuncSetAttribute(gemm_qkv,  cudaFuncAttributeMaxDynamicSharedMemorySize, GEMM_SMEM);
    cudaFuncSetAttribute(gemm_o,    cudaFuncAttributeMaxDynamicSharedMemorySize, GEMM_SMEM);
    cudaFuncSetAttribute(fold_w,    cudaFuncAttributeMaxDynamicSharedMemorySize, FOLD_SMEM);
    cudaFuncSetAttribute(kv_kernel, cudaFuncAttributeMaxDynamicSharedMemorySize, KV_SMEM);
    cudaFuncSetAttribute(out_kernel,cudaFuncAttributeMaxDynamicSharedMemorySize, OUT_SMEM);

    // conversions + weight folding
    f2h<<<MTOT*HIDc/2048, 256>>>(x, xh, MTOT*HIDc);
    wconv<<<dim3(HIDc*HIDc/2048, 1, 2), 256>>>(Wv, Wo);
    fold_w<<<dim3(8, 8, 2), 256, FOLD_SMEM>>>(fmqw, fmkw, Wq, Wk);

    // fused QKV GEMM + hedgehog softmax epilogue
    gemm_qkv<<<dim3(HIDc/128, MTOT/128, 3), 256, GEMM_SMEM>>>(fmqb, fmkb);

    dim3 cg(NCc, Hc, Bc);
    kv_kernel<<<cg, 512, KV_SMEM>>>();
    prefix_kernel<<<dim3(64, Bc*Hc), 256>>>();
    out_kernel<<<cg, 256, OUT_SMEM>>>();

    rowscale_combine<<<MTOT/256, 256>>>();
    gemm_o<<<dim3(HIDc/128, MTOT/128, 1), 256, GEMM_SMEM>>>(out);
}

// round 13
// speedup vs baseline: 1.3353x; 1.0504x over previous
#include <cuda_runtime.h>
#include <cuda_fp16.h>
#include <cstdint>
#include <math.h>

// Problem constants
#define Bc   2
#define Tc   8192
#define Hc   8
#define Dc   128
#define HIDc 1024
#define NCc  128          // T / CHUNK
#define Fc   256          // hedgehog feature dim (2*DQK)
#define MTOT (Bc*Tc)      // 16384 tokens

// ---------------------------------------------------------------------------
// Scratch (device globals — no allocations allowed)
// ---------------------------------------------------------------------------
__device__ __half g_xh  [(size_t)MTOT*HIDc];      // 32 MB
__device__ __half g_wvh [HIDc*HIDc];
__device__ __half g_woh [HIDc*HIDc];
__device__ __half g_wq2 [HIDc*HIDc];              // folded fmq @ Wq (per head)
__device__ __half g_wk2 [HIDc*HIDc];              // folded fmk @ Wk
__device__ __half g_v   [(size_t)MTOT*HIDc];
__device__ __half g_qf  [(size_t)MTOT*Hc*Fc];     // 64 MB (pre-scaled)
__device__ __half g_kf  [(size_t)MTOT*Hc*Fc];     // 64 MB
__device__ __half g_s   [(size_t)Bc*Hc*NCc*Fc*Dc]; // 128 MB exclusive prefix (fp16)
__device__ __half g_oh  [(size_t)MTOT*HIDc];      // attention out (unnormalized)
__device__ float  g_prs [MTOT*Hc];                // per-(token,head) partial sumsq

// ---------------------------------------------------------------------------
// Helpers
// ---------------------------------------------------------------------------
__device__ __forceinline__ uint32_t smem_u32(const void* p) {
    uint32_t a;
    asm("{ .reg .u64 t; cvta.to.shared.u64 t, %1; cvt.u32.u64 %0, t; }" : "=r"(a) : "l"(p));
    return a;
}
__device__ __forceinline__ uint32_t pack2(float lo, float hi) {
    __half2 h = __floats2half2_rn(lo, hi);
    return *reinterpret_cast<uint32_t*>(&h);
}
__device__ __forceinline__ void mma_f16(float* c, const uint32_t* a, const uint32_t* b) {
    asm volatile(
        "mma.sync.aligned.m16n8k16.row.col.f32.f16.f16.f32 "
        "{%0,%1,%2,%3}, {%4,%5,%6,%7}, {%8,%9}, {%0,%1,%2,%3};"
        : "+f"(c[0]), "+f"(c[1]), "+f"(c[2]), "+f"(c[3])
        : "r"(a[0]), "r"(a[1]), "r"(a[2]), "r"(a[3]), "r"(b[0]), "r"(b[1]));
}
#define LDSM4(r, addr) \
    asm volatile("ldmatrix.sync.aligned.m8n8.x4.shared.b16 {%0,%1,%2,%3}, [%4];" \
        : "=r"((r)[0]), "=r"((r)[1]), "=r"((r)[2]), "=r"((r)[3]) : "r"(addr))
#define LDSM4T(r, addr) \
    asm volatile("ldmatrix.sync.aligned.m8n8.x4.trans.shared.b16 {%0,%1,%2,%3}, [%4];" \
        : "=r"((r)[0]), "=r"((r)[1]), "=r"((r)[2]), "=r"((r)[3]) : "r"(addr))
__device__ __forceinline__ void cp16(uint32_t dst, const void* src) {
    asm volatile("cp.async.cg.shared.global [%0], [%1], 16;" :: "r"(dst), "l"(src) : "memory");
}
#define CP_COMMIT() asm volatile("cp.async.commit_group;" ::: "memory")
#define CP_WAIT(n)  asm volatile("cp.async.wait_group %0;" :: "n"(n) : "memory")

// ---------------------------------------------------------------------------
// f32 -> f16 conversion (n multiple of 2048)
// ---------------------------------------------------------------------------
__global__ __launch_bounds__(256) void f2h(const float* __restrict__ s,
                                           __half* __restrict__ d, int n)
{
    int i = (blockIdx.x * 256 + threadIdx.x) * 8;
    if (i < n) {
        float4 a = *(const float4*)(s + i), b = *(const float4*)(s + i + 4);
        *(uint4*)(d + i) = make_uint4(pack2(a.x, a.y), pack2(a.z, a.w),
                                      pack2(b.x, b.y), pack2(b.z, b.w));
    }
}
// Wv, Wo conversion (grid.z selects)
__global__ __launch_bounds__(256) void wconv(
    const float* __restrict__ w0, const float* __restrict__ w1)
{
    const int z = blockIdx.z;
    const float* s = z ? w1 : w0;
    __half* d = z ? g_woh : g_wvh;
    int i = (blockIdx.x * 256 + threadIdx.x) * 8;
    float4 a = *(const float4*)(s + i), b = *(const float4*)(s + i + 4);
    *(uint4*)(d + i) = make_uint4(pack2(a.x, a.y), pack2(a.z, a.w),
                                  pack2(b.x, b.y), pack2(b.z, b.w));
}

// ---------------------------------------------------------------------------
// Fold: W2[h*128+i, c] = sum_j fm[i,j] * W[h*128+j, c]   (reads f32 W directly)
// ---------------------------------------------------------------------------
#define FSKP 136
#define FD_A 0
#define FD_B (128*FSKP*2)               // 34816
#define FOLD_SMEM (2*128*FSKP*2)        // 69632

__global__ __launch_bounds__(256) void fold_w(
    const float* __restrict__ fmq, const float* __restrict__ fmk,
    const float* __restrict__ Wq,  const float* __restrict__ Wk)
{
    const int z = blockIdx.z;
    const float* fm = z ? fmk : fmq;
    const float* Wf = z ? Wk : Wq;
    __half* W2 = z ? g_wk2 : g_wq2;

    extern __shared__ char smc[];
    const uint32_t sb = smem_u32(smc);
    const int tid = threadIdx.x, wid = tid >> 5, lane = tid & 31;
    const int wm = wid & 3, wn = wid >> 2;
    const int qr = lane >> 2, qc = lane & 3;
    const int ct = blockIdx.x, h = blockIdx.y;

#pragma unroll
    for (int it = 0; it < 16; it++) {
        int e = tid + it * 256;
        int r = e >> 5, c4 = e & 31;
        float4 f = *(const float4*)(fm + r * 128 + c4 * 4);
        *(uint2*)(smc + FD_A + ((uint32_t)r * FSKP + c4 * 4) * 2) =
            make_uint2(pack2(f.x, f.y), pack2(f.z, f.w));
    }
#pragma unroll
    for (int it = 0; it < 16; it++) {
        int e = tid + it * 256;
        int r = e >> 5, c4 = e & 31;
        float4 f = *(const float4*)(Wf + (size_t)(h * 128 + r) * 1024 + ct * 128 + c4 * 4);
        *(uint2*)(smc + FD_B + ((uint32_t)r * FSKP + c4 * 4) * 2) =
            make_uint2(pack2(f.x, f.y), pack2(f.z, f.w));
    }
    __syncthreads();

    float acc[2][8][4];
#pragma unroll
    for (int mf = 0; mf < 2; mf++)
#pragma unroll
        for (int nf = 0; nf < 8; nf++)
#pragma unroll
            for (int i = 0; i < 4; i++) acc[mf][nf][i] = 0.f;

    const uint32_t a_off = FD_A + (uint32_t)(wm*32 + (lane&7) + ((lane>>3)&1)*8) * (FSKP*2)
                         + (lane>>4)*16;
    const uint32_t cb = (lane & 7) + ((lane >> 3) & 1) * 8;
    const uint32_t nb = (lane >> 4) * 8;

#pragma unroll
    for (int ks = 0; ks < 8; ks++) {
        uint32_t a[2][4];
        LDSM4(a[0], sb + a_off + ks * 32);
        LDSM4(a[1], sb + a_off + 16 * FSKP * 2 + ks * 32);
#pragma unroll
        for (int np = 0; np < 4; np++) {
            uint32_t b[4];
            LDSM4T(b, sb + FD_B + ((ks*16 + cb) * FSKP + wn*64 + np*16 + nb) * 2);
            mma_f16(acc[0][2*np],   a[0], b);
            mma_f16(acc[0][2*np+1], a[0], b + 2);
            mma_f16(acc[1][2*np],   a[1], b);
            mma_f16(acc[1][2*np+1], a[1], b + 2);
        }
    }

#pragma unroll
    for (int mf = 0; mf < 2; mf++) {
        const int i0 = h * 128 + wm * 32 + mf * 16 + qr;
#pragma unroll
        for (int nf = 0; nf < 8; nf++) {
            const int c0 = ct * 128 + wn * 64 + nf * 8 + qc * 2;
            *(uint32_t*)&W2[(size_t)i0 * 1024 + c0] = pack2(acc[mf][nf][0], acc[mf][nf][1]);
            *(uint32_t*)&W2[(size_t)(i0 + 8) * 1024 + c0] = pack2(acc[mf][nf][2], acc[mf][nf][3]);
        }
    }
}

// ---------------------------------------------------------------------------
// GEMM core macros (CTA 128x128, BK=64, 3-stage, 8 warps 4x2, 2 CTAs/SM)
// ---------------------------------------------------------------------------
#define SKP_B   144                   // 64 halves + 8 pad = 144 bytes per row
#define GA_B    (128*SKP_B)           // 18432
#define GSTG    (2*GA_B)              // 36864
#define GEMM_SMEM (3*GSTG)            // 110592

#define GEMM_MAIN(X, W)                                                    \
    const int pr = tid >> 3, pp = tid & 7;                                 \
    const __half* Xp = (X) + (size_t)(m0 + pr) * 1024 + pp * 8;            \
    const __half* Wp = (W) + (size_t)(n0 + pr) * 1024 + pp * 8;            \
    const uint32_t a_off = (uint32_t)(wm*32 + (lane&7) + ((lane>>3)&1)*8) * SKP_B \
                         + (lane>>4)*16;                                   \
    const uint32_t b_off = (uint32_t)(wn*64 + (lane>>4)*8 + (lane&7)) * SKP_B \
                         + ((lane>>3)&1)*16;                               \
    float acc[2][8][4];                                                    \
    _Pragma("unroll")                                                      \
    for (int mf = 0; mf < 2; mf++)                                         \
        _Pragma("unroll")                                                  \
        for (int nf = 0; nf < 8; nf++)                                     \
            _Pragma("unroll")                                              \
            for (int i = 0; i < 4; i++) acc[mf][nf][i] = 0.f;              \
    LOAD_STAGE(0, 0); CP_COMMIT();                                         \
    LOAD_STAGE(1, 1); CP_COMMIT();                                         \
    for (int kt = 0; kt < 16; kt++) {                                      \
        const int st = kt % 3;                                             \
        CP_WAIT(1);                                                        \
        __syncthreads();                                                   \
        const uint32_t As = sb + st * GSTG, Bs = As + GA_B;                \
        _Pragma("unroll")                                                  \
        for (int ks = 0; ks < 4; ks++) {                                   \
            uint32_t a[2][4];                                              \
            LDSM4(a[0], As + a_off + ks * 32);                             \
            LDSM4(a[1], As + a_off + 16 * SKP_B + ks * 32);                \
            _Pragma("unroll")                                              \
            for (int np = 0; np < 4; np++) {                               \
                uint32_t b[4];                                             \
                LDSM4(b, Bs + b_off + np * (16 * SKP_B) + ks * 32);        \
                mma_f16(acc[0][2*np],   a[0], b);                          \
                mma_f16(acc[0][2*np+1], a[0], b + 2);                      \
                mma_f16(acc[1][2*np],   a[1], b);                          \
                mma_f16(acc[1][2*np+1], a[1], b + 2);                      \
            }                                                              \
        }                                                                  \
        if (kt + 2 < 16) LOAD_STAGE(kt + 2, (kt + 2) % 3);                 \
        CP_COMMIT();                                                       \
    }

#define LOAD_STAGE(kt, st) {                                              \
    uint32_t base = sb + (st) * GSTG;                                     \
    const __half* xk = Xp + (kt) * 64;                                    \
    const __half* wk = Wp + (kt) * 64;                                    \
    _Pragma("unroll")                                                     \
    for (int i = 0; i < 4; i++) {                                         \
        uint32_t so = (uint32_t)(pr + 32*i) * SKP_B + pp * 16;            \
        cp16(base + so, xk + (size_t)(32*i) * 1024);                      \
        cp16(base + GA_B + so, wk + (size_t)(32*i) * 1024);               \
    } }

// ---------------------------------------------------------------------------
// Fused QKV GEMM. z=0: q (softmax epilogue, scale 1/16), z=1: k (softmax),
// z=2: v (fp16 write).
// ---------------------------------------------------------------------------
__global__ __launch_bounds__(256, 2) void gemm_qkv(
    const float* __restrict__ biasq, const float* __restrict__ biask)
{
    const int z = blockIdx.z;
    const __half* W = (z == 0) ? g_wq2 : ((z == 1) ? g_wk2 : g_wvh);

    extern __shared__ char smc[];
    const uint32_t sb = smem_u32(smc);
    const int tid = threadIdx.x, wid = tid >> 5, lane = tid & 31;
    const int wm = wid & 3, wn = wid >> 2;
    const int qr = lane >> 2, qc = lane & 3;
    const int m0 = blockIdx.y * 128, n0 = blockIdx.x * 128;

    GEMM_MAIN(g_xh, W)

    if (z == 2) {
#pragma unroll
        for (int mf = 0; mf < 2; mf++) {
            const int r0 = m0 + wm * 32 + mf * 16 + qr;
#pragma unroll
            for (int nf = 0; nf < 8; nf++) {
                const int c0 = n0 + wn * 64 + nf * 8 + qc * 2;
                *(uint32_t*)&g_v[(size_t)r0 * 1024 + c0] =
                    pack2(acc[mf][nf][0], acc[mf][nf][1]);
                *(uint32_t*)&g_v[(size_t)(r0 + 8) * 1024 + c0] =
                    pack2(acc[mf][nf][2], acc[mf][nf][3]);
            }
        }
        return;
    }

    // q/k: hedgehog softmax epilogue. Reuse stage smem as f32 ys[128][132].
    __syncthreads();
    float* ys = (float*)smc;
#pragma unroll
    for (int mf = 0; mf < 2; mf++) {
        const int r0 = wm * 32 + mf * 16 + qr;
#pragma unroll
        for (int nf = 0; nf < 8; nf++) {
            const int c0 = wn * 64 + nf * 8 + qc * 2;
            *(float2*)(ys + r0 * 132 + c0) = make_float2(acc[mf][nf][0], acc[mf][nf][1]);
            *(float2*)(ys + (r0 + 8) * 132 + c0) = make_float2(acc[mf][nf][2], acc[mf][nf][3]);
        }
    }
    __syncthreads();

    const float* bias = z ? biask : biasq;
    const float scale = z ? 1.0f : 0.0625f;   // 256^-0.5 folded into qf
    __half* dst = z ? g_kf : g_qf;
    const int h = blockIdx.x;
    float4 bv = *(const float4*)(bias + lane * 4);

    for (int rr = 0; rr < 16; rr += 2) {
        const int r0 = wid * 16 + rr;
        float y[2][4], m[2];
#pragma unroll
        for (int u = 0; u < 2; u++) {
            float4 v4 = *(const float4*)(ys + (r0 + u) * 132 + lane * 4);
            y[u][0] = 2.f * (v4.x + bv.x); y[u][1] = 2.f * (v4.y + bv.y);
            y[u][2] = 2.f * (v4.z + bv.z); y[u][3] = 2.f * (v4.w + bv.w);
            m[u] = fmaxf(fmaxf(fabsf(y[u][0]), fabsf(y[u][1])),
                         fmaxf(fabsf(y[u][2]), fabsf(y[u][3])));
        }
#pragma unroll
        for (int off = 16; off >= 1; off >>= 1) {
            m[0] = fmaxf(m[0], __shfl_xor_sync(0xffffffffu, m[0], off));
            m[1] = fmaxf(m[1], __shfl_xor_sync(0xffffffffu, m[1], off));
        }
        float ep[2][4], en[2][4], zs[2] = {0.f, 0.f};
#pragma unroll
        for (int u = 0; u < 2; u++)
#pragma unroll
            for (int j = 0; j < 4; j++) {
                ep[u][j] = __expf( y[u][j] - m[u]);
                en[u][j] = __expf(-y[u][j] - m[u]);
                zs[u] += ep[u][j] + en[u][j];
            }
#pragma unroll
        for (int off = 16; off >= 1; off >>= 1) {
            zs[0] += __shfl_xor_sync(0xffffffffu, zs[0], off);
            zs[1] += __shfl_xor_sync(0xffffffffu, zs[1], off);
        }
#pragma unroll
        for (int u = 0; u < 2; u++) {
            const float inv = scale / zs[u];
            __half* drow = dst + ((size_t)(m0 + r0 + u) * Hc + h) * Fc;
            *(uint2*)(drow + lane * 4) =
                make_uint2(pack2(ep[u][0]*inv, ep[u][1]*inv),
                           pack2(ep[u][2]*inv, ep[u][3]*inv));
            *(uint2*)(drow + 128 + lane * 4) =
                make_uint2(pack2(en[u][0]*inv, en[u][1]*inv),
                           pack2(en[u][2]*inv, en[u][3]*inv));
        }
    }
}

// ---------------------------------------------------------------------------
// Wo GEMM with rmsnorm row-scale epilogue (rs computed inline from g_prs):
// out[r][c] = rs[r] * (o @ Wo^T)
// ---------------------------------------------------------------------------
__global__ __launch_bounds__(256, 2) void gemm_o(float* __restrict__ out)
{
    extern __shared__ char smc[];
    __shared__ float rs_s[128];
    const uint32_t sb = smem_u32(smc);
    const int tid = threadIdx.x, wid = tid >> 5, lane = tid & 31;
    const int wm = wid & 3, wn = wid >> 2;
    const int qr = lane >> 2, qc = lane & 3;
    const int m0 = blockIdx.y * 128, n0 = blockIdx.x * 128;

    if (tid < 128) {
        float4 a = *(const float4*)&g_prs[(size_t)(m0 + tid) * Hc];
        float4 b4 = *(const float4*)&g_prs[(size_t)(m0 + tid) * Hc + 4];
        float s = a.x + a.y + a.z + a.w + b4.x + b4.y + b4.z + b4.w;
        rs_s[tid] = rsqrtf(s * (1.f / HIDc) + 1e-5f);
    }

    GEMM_MAIN(g_oh, g_woh)

#pragma unroll
    for (int mf = 0; mf < 2; mf++) {
        const int rl = wm * 32 + mf * 16 + qr;
        const int r0 = m0 + rl;
        const float s0 = rs_s[rl], s1 = rs_s[rl + 8];
#pragma unroll
        for (int nf = 0; nf < 8; nf++) {
            const int c0 = n0 + wn * 64 + nf * 8 + qc * 2;
            *(float2*)&out[(size_t)r0 * 1024 + c0] =
                make_float2(acc[mf][nf][0] * s0, acc[mf][nf][1] * s0);
            *(float2*)&out[(size_t)(r0 + 8) * 1024 + c0] =
                make_float2(acc[mf][nf][2] * s1, acc[mf][nf][3] * s1);
        }
    }
}

// ---------------------------------------------------------------------------
// Fused KV scan: per (b, h, d-slice 64, e-slice 64) CTA walks 128 chunks,
// keeping the 64x64 f32 state in mma accumulators. Writes the exclusive
// prefix S (fp16) per chunk; never materializes per-chunk KV in global.
// 8 warps 2(d)x4(e), warp tile 32x16. 3-stage cp.async on kf/v slices.
// grid (2, 4, 16), 256 threads.
// ---------------------------------------------------------------------------
#define KP_ROW 144                    // 72 halves per smem row
#define KP_V   (64*KP_ROW)            // 9216: v slice offset within stage
#define KP_STG (2*64*KP_ROW)          // 18432 per stage
#define KP_SS  (3*KP_STG)             // 55296: S staging
#define KP_SMEM (KP_SS + 64*KP_ROW)   // 64512

__global__ __launch_bounds__(256) void kvscan_kernel()
{
    extern __shared__ char smc[];
    const uint32_t sb = smem_u32(smc);
    const int e0 = blockIdx.x * 64, d0 = blockIdx.y * 64;
    const int b = blockIdx.z >> 3, h = blockIdx.z & 7;
    const int tid = threadIdx.x, wid = tid >> 5, lane = tid & 31;
    const int wm = wid & 1, wn = wid >> 1;
    const int g = lane >> 2, t4 = lane & 3;
    const int lr = tid >> 3, lp = tid & 7;    // loader: row base, 16B col

    const uint32_t ca = (lane & 7) + ((lane >> 4) & 1) * 8;
    const uint32_t ma = ((lane >> 3) & 1) * 8;
    const uint32_t cb = (lane & 7) + ((lane >> 3) & 1) * 8;
    const uint32_t nb = (lane >> 4) * 8;

    float acc[2][2][4];
#pragma unroll
    for (int mf = 0; mf < 2; mf++)
#pragma unroll
        for (int nf = 0; nf < 2; nf++)
#pragma unroll
            for (int i = 0; i < 4; i++) acc[mf][nf][i] = 0.f;

#define KP_LOAD(c, st) {                                                       \
    uint32_t base = sb + (st) * KP_STG;                                        \
    const int tt = (c) * 64;                                                   \
    _Pragma("unroll")                                                          \
    for (int i = 0; i < 2; i++) {                                              \
        int r = lr + 32 * i;                                                   \
        cp16(base + (uint32_t)r * KP_ROW + lp * 16,                            \
             &g_kf[((size_t)(b*Tc + tt + r) * Hc + h) * Fc + d0 + lp * 8]);    \
        cp16(base + KP_V + (uint32_t)r * KP_ROW + lp * 16,                     \
             &g_v[(size_t)(b*Tc + tt + r) * HIDc + h * 128 + e0 + lp * 8]);    \
    } }

    KP_LOAD(0, 0); CP_COMMIT();
    KP_LOAD(1, 1); CP_COMMIT();

    const size_t sseq = ((size_t)(b*Hc + h)) * NCc * (size_t)(Fc * Dc);

    for (int c = 0; c < NCc; c++) {
        CP_WAIT(1);
        __syncthreads();   // buffer c%3 ready; previous S staging fully read

        // stage exclusive state (before accumulating chunk c) into sS
#pragma unroll
        for (int mf = 0; mf < 2; mf++)
#pragma unroll
            for (int nf = 0; nf < 2; nf++) {
                int d = wm * 32 + mf * 16 + g;
                int e = wn * 16 + nf * 8 + t4 * 2;
                *(uint32_t*)(smc + KP_SS + ((uint32_t)d * KP_ROW + e * 2)) =
                    pack2(acc[mf][nf][0], acc[mf][nf][1]);
                *(uint32_t*)(smc + KP_SS + ((uint32_t)(d + 8) * KP_ROW + e * 2)) =
                    pack2(acc[mf][nf][2], acc[mf][nf][3]);
            }

        // accumulate chunk c: state += kf_slice^T @ v_slice
        const uint32_t kfb = sb + (c % 3) * KP_STG;
        const uint32_t vb  = kfb + KP_V;
#pragma unroll
        for (int ks = 0; ks < 4; ks++) {
            uint32_t bbf[4];
            LDSM4T(bbf, vb + ((ks*16 + cb) * KP_ROW + (wn*16 + nb) * 2));
#pragma unroll
            for (int mf = 0; mf < 2; mf++) {
                uint32_t a[4];
                LDSM4T(a, kfb + ((ks*16 + ca) * KP_ROW + (wm*32 + mf*16 + ma) * 2));
                mma_f16(acc[mf][0], a, bbf);
                mma_f16(acc[mf][1], a, bbf + 2);
            }
        }

        // prefetch chunk c+2
        if (c + 2 < NCc) KP_LOAD(c + 2, (c + 2) % 3);
        CP_COMMIT();

        __syncthreads();   // sS fully staged

        // coalesced S write for chunk c
        const size_t sbase = sseq + (size_t)c * (Fc * Dc);
#pragma unroll
        for (int i = 0; i < 2; i++) {
            int r = lr + 32 * i;
            *(uint4*)(&g_s[sbase + (size_t)(d0 + r) * 128 + e0 + lp * 8]) =
                *(const uint4*)(smc + KP_SS + (uint32_t)r * KP_ROW + lp * 16);
        }
    }
#undef KP_LOAD
}

// ---------------------------------------------------------------------------
// Output per chunk (fp16 mma): o = tril(qf @ kf^T) @ v + qf @ S  -> fp16
// S streamed in 4x64-row quarters, double-buffered in the dead kf region.
// o staged through v buffer for coalesced stores + per-token sumsq partials.
// 2 CTAs/SM.
// ---------------------------------------------------------------------------
#define OQF 0
#define OKF 33792                     // kf (64x264) / S quarter bufs (2 x 64x136)
#define OSQ(i) (OKF + (i)*17408)
#define OV  68608                     // v (64x136) / o staging (64x136)
#define OAT 86016
#define OUT_SMEM 95232

__global__ __launch_bounds__(256, 2) void out_kernel()
{
    extern __shared__ char smc[];
    const uint32_t sb = smem_u32(smc);
    const int chunk = blockIdx.x, h = blockIdx.y, b = blockIdx.z;
    const int tid = threadIdx.x, wid = tid >> 5, lane = tid & 31;
    const int g = lane >> 2, t4 = lane & 3;
    const int t0 = chunk * 64;
    const int wm = wid & 1, wn = wid >> 1;

    const size_t qbase = ((size_t)(b*Tc + t0) * Hc + h) * Fc;
#pragma unroll
    for (int i = 0; i < 8; i++) {
        int l = tid + i * 256;
        int r = l >> 5, p = l & 31;
        size_t gs = qbase + (size_t)r * (Hc*Fc) + p * 8;
        *(uint4*)(smc + OQF + ((uint32_t)r * 264 + p * 8) * 2) = *(const uint4*)(&g_qf[gs]);
        *(uint4*)(smc + OKF + ((uint32_t)r * 264 + p * 8) * 2) = *(const uint4*)(&g_kf[gs]);
    }
#pragma unroll
    for (int i = 0; i < 4; i++) {
        int l = tid + i * 256;
        int r = l >> 4, p = l & 15;
        *(uint4*)(smc + OV + ((uint32_t)r * 136 + p * 8) * 2) =
            *(const uint4*)(&g_v[(size_t)(b*Tc + t0 + r) * HIDc + h * 128 + p * 8]);
    }
    __syncthreads();

    // phase 1: scores = tril(qf @ kf^T)
    {
        float sc[2][2][4];
#pragma unroll
        for (int mf = 0; mf < 2; mf++)
#pragma unroll
            for (int nf = 0; nf < 2; nf++)
#pragma unroll
                for (int i = 0; i < 4; i++) sc[mf][nf][i] = 0.f;

        const uint32_t aoff = OQF + (uint32_t)(wm*32 + (lane&7) + ((lane>>3)&1)*8) * 528
                            + (lane>>4)*16;
        const uint32_t boff = OKF + (uint32_t)(wn*16 + (lane>>4)*8 + (lane&7)) * 528
                            + ((lane>>3)&1)*16;
#pragma unroll
        for (int ks = 0; ks < 16; ks++) {
            uint32_t a[2][4], bbf[4];
            LDSM4(a[0], sb + aoff + ks * 32);
            LDSM4(a[1], sb + aoff + 16 * 528 + ks * 32);
            LDSM4(bbf, sb + boff + ks * 32);
            mma_f16(sc[0][0], a[0], bbf);
            mma_f16(sc[0][1], a[0], bbf + 2);
            mma_f16(sc[1][0], a[1], bbf);
            mma_f16(sc[1][1], a[1], bbf + 2);
        }
#pragma unroll
        for (int mf = 0; mf < 2; mf++)
#pragma unroll
            for (int nf = 0; nf < 2; nf++) {
                int ci = wm*32 + mf*16 + g;
                int cj = wn*16 + nf*8 + t4*2;
                float v0 = (cj     <= ci) ? sc[mf][nf][0] : 0.f;
                float v1 = (cj + 1 <= ci) ? sc[mf][nf][1] : 0.f;
                *(uint32_t*)(smc + OAT + ((uint32_t)ci * 72 + cj) * 2) = pack2(v0, v1);
                int ci2 = ci + 8;
                float v2 = (cj     <= ci2) ? sc[mf][nf][2] : 0.f;
                float v3 = (cj + 1 <= ci2) ? sc[mf][nf][3] : 0.f;
                *(uint32_t*)(smc + OAT + ((uint32_t)ci2 * 72 + cj) * 2) = pack2(v2, v3);
            }
    }
    __syncthreads();

    // phase 2: o = attn @ v + qf @ S, S in 4 quarters double-buffered
    const size_t sbase = (((size_t)(b*Hc + h)) * NCc + chunk) * (size_t)(Fc * Dc);
    float o[2][4][4];
#pragma unroll
    for (int mf = 0; mf < 2; mf++)
#pragma unroll
        for (int nf = 0; nf < 4; nf++)
#pragma unroll
            for (int i = 0; i < 4; i++) o[mf][nf][i] = 0.f;

    const uint32_t cb = (lane & 7) + ((lane >> 3) & 1) * 8;
    const uint32_t nb = (lane >> 4) * 8;
    const uint32_t a2 = OQF + (uint32_t)(wm*32 + (lane&7) + ((lane>>3)&1)*8) * 528
                      + (lane>>4)*16;

#pragma unroll
    for (int qq = 0; qq < 2; qq++) {
#pragma unroll
        for (int i = 0; i < 4; i++) {
            int l = tid + i * 256;
            int f = l >> 4, p = l & 15;
            cp16(sb + OSQ(qq) + ((uint32_t)f * 136 + p * 8) * 2,
                 &g_s[sbase + (size_t)(qq * 64 + f) * 128 + p * 8]);
        }
        CP_COMMIT();
    }

    // attn @ v (independent of S; overlaps S loads)
    {
        const uint32_t a1 = OAT + (uint32_t)(wm*32 + (lane&7) + ((lane>>3)&1)*8) * 144
                          + (lane>>4)*16;
#pragma unroll
        for (int ks = 0; ks < 4; ks++) {
            uint32_t a[2][4];
            LDSM4(a[0], sb + a1 + ks * 32);
            LDSM4(a[1], sb + a1 + 16 * 144 + ks * 32);
#pragma unroll
            for (int np = 0; np < 2; np++) {
                uint32_t bbf[4];
                LDSM4T(bbf, sb + OV + ((ks*16 + cb) * 136 + wn*32 + np*16 + nb) * 2);
                mma_f16(o[0][2*np],   a[0], bbf);
                mma_f16(o[0][2*np+1], a[0], bbf + 2);
                mma_f16(o[1][2*np],   a[1], bbf);
                mma_f16(o[1][2*np+1], a[1], bbf + 2);
            }
        }
    }

#pragma unroll
    for (int qq = 0; qq < 4; qq++) {
        if (qq < 3) { CP_WAIT(1); } else { CP_WAIT(0); }
        __syncthreads();
        const uint32_t sq = sb + OSQ(qq & 1);
#pragma unroll
        for (int kss = 0; kss < 4; kss++) {
            const int ks = qq * 4 + kss;
            uint32_t a[2][4];
            LDSM4(a[0], sb + a2 + ks * 32);
            LDSM4(a[1], sb + a2 + 16 * 528 + ks * 32);
#pragma unroll
            for (int np = 0; np < 2; np++) {
                uint32_t bbf[4];
                LDSM4T(bbf, sq + ((kss*16 + cb) * 136 + wn*32 + np*16 + nb) * 2);
                mma_f16(o[0][2*np],   a[0], bbf);
                mma_f16(o[0][2*np+1], a[0], bbf + 2);
                mma_f16(o[1][2*np],   a[1], bbf);
                mma_f16(o[1][2*np+1], a[1], bbf + 2);
            }
        }
        __syncthreads();
        if (qq + 2 < 4) {
#pragma unroll
            for (int i = 0; i < 4; i++) {
                int l = tid + i * 256;
                int f = l >> 4, p = l & 15;
                cp16(sb + OSQ(qq & 1) + ((uint32_t)f * 136 + p * 8) * 2,
                     &g_s[sbase + (size_t)((qq + 2) * 64 + f) * 128 + p * 8]);
            }
            CP_COMMIT();
        }
    }

    // stage o through the dead v buffer, then coalesced 16B writes + sumsq
#pragma unroll
    for (int mf = 0; mf < 2; mf++)
#pragma unroll
        for (int nf = 0; nf < 4; nf++) {
            int r = wm*32 + mf*16 + g;
            int e = wn*32 + nf*8 + t4*2;
            *(uint32_t*)(smc + OV + ((uint32_t)r * 136 + e) * 2) =
                pack2(o[mf][nf][0], o[mf][nf][1]);
            *(uint32_t*)(smc + OV + ((uint32_t)(r + 8) * 136 + e) * 2) =
                pack2(o[mf][nf][2], o[mf][nf][3]);
        }
    __syncthreads();
#pragma unroll
    for (int i = 0; i < 4; i++) {
        int l = tid + i * 256;
        int r = l >> 4, p = l & 15;
        *(uint4*)(&g_oh[(size_t)(b*Tc + t0 + r) * HIDc + h * 128 + p * 8]) =
            *(const uint4*)(smc + OV + ((uint32_t)r * 136 + p * 8) * 2);
    }

    // per-token sumsq partial (rmsnorm): 4 threads per token, 32 dims each
    {
        const int r = tid >> 2, part = tid & 3;
        float s = 0.f;
        const __half2* row = (const __half2*)(smc + OV + (uint32_t)r * 136 * 2);
#pragma unroll
        for (int j = 0; j < 16; j++) {
            float2 v = __half22float2(row[part * 16 + j]);
            s += v.x * v.x + v.y * v.y;
        }
        s += __shfl_xor_sync(0xffffffffu, s, 1);
        s += __shfl_xor_sync(0xffffffffu, s, 2);
        if (part == 0)
            g_prs[(size_t)(b*Tc + t0 + r) * Hc + h] = s;
    }
}

// ---------------------------------------------------------------------------
// Launch
// ---------------------------------------------------------------------------
extern "C" void kernel_launch(void* const* d_in, const int* in_sizes, int n_in,
                              void* d_out, int out_size)
{
    const float* x    = (const float*)d_in[0];
    const float* Wq   = (const float*)d_in[1];
    const float* Wk   = (const float*)d_in[2];
    const float* Wv   = (const float*)d_in[3];
    const float* Wo   = (const float*)d_in[4];
    const float* fmqw = (const float*)d_in[5];
    const float* fmqb = (const float*)d_in[6];
    const float* fmkw = (const float*)d_in[7];
    const float* fmkb = (const float*)d_in[8];
    float* out = (float*)d_out;

    __half* xh;
    cudaGetSymbolAddress((void**)&xh, g_xh);

    cudaFuncSetAttribute(gemm_qkv,  cudaFuncAttributeMaxDynamicSharedMemorySize, GEMM_SMEM);
    cudaFuncSetAttribute(gemm_o,    cudaFuncAttributeMaxDynamicSharedMemorySize, GEMM_SMEM);
    cudaFuncSetAttribute(fold_w,    cudaFuncAttributeMaxDynamicSharedMemorySize, FOLD_SMEM);
    cudaFuncSetAttribute(kvscan_kernel, cudaFuncAttributeMaxDynamicSharedMemorySize, KP_SMEM);
    cudaFuncSetAttribute(out_kernel,cudaFuncAttributeMaxDynamicSharedMemorySize, OUT_SMEM);

    // conversions + weight folding
    f2h<<<MTOT*HIDc/2048, 256>>>(x, xh, MTOT*HIDc);
    wconv<<<dim3(HIDc*HIDc/2048, 1, 2), 256>>>(Wv, Wo);
    fold_w<<<dim3(8, 8, 2), 256, FOLD_SMEM>>>(fmqw, fmkw, Wq, Wk);

    // fused QKV GEMM + hedgehog softmax epilogue
    gemm_qkv<<<dim3(HIDc/128, MTOT/128, 3), 256, GEMM_SMEM>>>(fmqb, fmkb);

    // fused KV accumulation + exclusive prefix scan (state in registers)
    kvscan_kernel<<<dim3(2, 4, Bc*Hc), 256, KP_SMEM>>>();

    out_kernel<<<dim3(NCc, Hc, Bc), 256, OUT_SMEM>>>();

    gemm_o<<<dim3(HIDc/128, MTOT/128, 1), 256, GEMM_SMEM>>>(out);
}

// round 14
// speedup vs baseline: 1.3691x; 1.0253x over previous
#include <cuda_runtime.h>
#include <cuda_fp16.h>
#include <cstdint>
#include <math.h>

// Problem constants
#define Bc   2
#define Tc   8192
#define Hc   8
#define Dc   128
#define HIDc 1024
#define NCc  128          // T / CHUNK
#define Fc   256          // hedgehog feature dim (2*DQK)
#define MTOT (Bc*Tc)      // 16384 tokens

// ---------------------------------------------------------------------------
// Scratch (device globals — no allocations allowed)
// ---------------------------------------------------------------------------
__device__ __half g_xh  [(size_t)MTOT*HIDc];      // 32 MB
__device__ __half g_wvh [HIDc*HIDc];
__device__ __half g_woh [HIDc*HIDc];
__device__ __half g_wq2 [HIDc*HIDc];              // folded fmq @ Wq (per head)
__device__ __half g_wk2 [HIDc*HIDc];              // folded fmk @ Wk
__device__ __half g_v   [(size_t)MTOT*HIDc];
__device__ __half g_qf  [(size_t)MTOT*Hc*Fc];     // 64 MB (pre-scaled)
__device__ __half g_kf  [(size_t)MTOT*Hc*Fc];     // 64 MB
__device__ __half g_s   [(size_t)Bc*Hc*NCc*Fc*Dc]; // 128 MB exclusive prefix (fp16)
__device__ __half g_oh  [(size_t)MTOT*HIDc];      // attention out (unnormalized)
__device__ float  g_prs [MTOT*Hc];                // per-(token,head) partial sumsq

// ---------------------------------------------------------------------------
// Helpers
// ---------------------------------------------------------------------------
__device__ __forceinline__ uint32_t smem_u32(const void* p) {
    uint32_t a;
    asm("{ .reg .u64 t; cvta.to.shared.u64 t, %1; cvt.u32.u64 %0, t; }" : "=r"(a) : "l"(p));
    return a;
}
__device__ __forceinline__ uint32_t pack2(float lo, float hi) {
    __half2 h = __floats2half2_rn(lo, hi);
    return *reinterpret_cast<uint32_t*>(&h);
}
__device__ __forceinline__ void mma_f16(float* c, const uint32_t* a, const uint32_t* b) {
    asm volatile(
        "mma.sync.aligned.m16n8k16.row.col.f32.f16.f16.f32 "
        "{%0,%1,%2,%3}, {%4,%5,%6,%7}, {%8,%9}, {%0,%1,%2,%3};"
        : "+f"(c[0]), "+f"(c[1]), "+f"(c[2]), "+f"(c[3])
        : "r"(a[0]), "r"(a[1]), "r"(a[2]), "r"(a[3]), "r"(b[0]), "r"(b[1]));
}
#define LDSM4(r, addr) \
    asm volatile("ldmatrix.sync.aligned.m8n8.x4.shared.b16 {%0,%1,%2,%3}, [%4];" \
        : "=r"((r)[0]), "=r"((r)[1]), "=r"((r)[2]), "=r"((r)[3]) : "r"(addr))
#define LDSM4T(r, addr) \
    asm volatile("ldmatrix.sync.aligned.m8n8.x4.trans.shared.b16 {%0,%1,%2,%3}, [%4];" \
        : "=r"((r)[0]), "=r"((r)[1]), "=r"((r)[2]), "=r"((r)[3]) : "r"(addr))
__device__ __forceinline__ void cp16(uint32_t dst, const void* src) {
    asm volatile("cp.async.cg.shared.global [%0], [%1], 16;" :: "r"(dst), "l"(src) : "memory");
}
#define CP_COMMIT() asm volatile("cp.async.commit_group;" ::: "memory")
#define CP_WAIT(n)  asm volatile("cp.async.wait_group %0;" :: "n"(n) : "memory")

// ---------------------------------------------------------------------------
// Merged f32 -> f16 conversion: blocks [0,8192) -> x, [8192,8704) -> Wv,
// [8704,9216) -> Wo.
// ---------------------------------------------------------------------------
__global__ __launch_bounds__(256) void conv_all(
    const float* __restrict__ x, const float* __restrict__ Wv,
    const float* __restrict__ Wo)
{
    int bidx = blockIdx.x;
    const float* s;
    __half* d;
    int base;
    if (bidx < 8192)      { s = x;  d = g_xh;  base = bidx; }
    else if (bidx < 8704) { s = Wv; d = g_wvh; base = bidx - 8192; }
    else                  { s = Wo; d = g_woh; base = bidx - 8704; }
    int i = (base * 256 + threadIdx.x) * 8;
    float4 a = *(const float4*)(s + i), b = *(const float4*)(s + i + 4);
    *(uint4*)(d + i) = make_uint4(pack2(a.x, a.y), pack2(a.z, a.w),
                                  pack2(b.x, b.y), pack2(b.z, b.w));
}

// ---------------------------------------------------------------------------
// Fold: W2[h*128+i, c] = sum_j fm[i,j] * W[h*128+j, c]   (reads f32 W directly)
// ---------------------------------------------------------------------------
#define FSKP 136
#define FD_A 0
#define FD_B (128*FSKP*2)               // 34816
#define FOLD_SMEM (2*128*FSKP*2)        // 69632

__global__ __launch_bounds__(256) void fold_w(
    const float* __restrict__ fmq, const float* __restrict__ fmk,
    const float* __restrict__ Wq,  const float* __restrict__ Wk)
{
    const int z = blockIdx.z;
    const float* fm = z ? fmk : fmq;
    const float* Wf = z ? Wk : Wq;
    __half* W2 = z ? g_wk2 : g_wq2;

    extern __shared__ char smc[];
    const uint32_t sb = smem_u32(smc);
    const int tid = threadIdx.x, wid = tid >> 5, lane = tid & 31;
    const int wm = wid & 3, wn = wid >> 2;
    const int qr = lane >> 2, qc = lane & 3;
    const int ct = blockIdx.x, h = blockIdx.y;

#pragma unroll
    for (int it = 0; it < 16; it++) {
        int e = tid + it * 256;
        int r = e >> 5, c4 = e & 31;
        float4 f = *(const float4*)(fm + r * 128 + c4 * 4);
        *(uint2*)(smc + FD_A + ((uint32_t)r * FSKP + c4 * 4) * 2) =
            make_uint2(pack2(f.x, f.y), pack2(f.z, f.w));
    }
#pragma unroll
    for (int it = 0; it < 16; it++) {
        int e = tid + it * 256;
        int r = e >> 5, c4 = e & 31;
        float4 f = *(const float4*)(Wf + (size_t)(h * 128 + r) * 1024 + ct * 128 + c4 * 4);
        *(uint2*)(smc + FD_B + ((uint32_t)r * FSKP + c4 * 4) * 2) =
            make_uint2(pack2(f.x, f.y), pack2(f.z, f.w));
    }
    __syncthreads();

    float acc[2][8][4];
#pragma unroll
    for (int mf = 0; mf < 2; mf++)
#pragma unroll
        for (int nf = 0; nf < 8; nf++)
#pragma unroll
            for (int i = 0; i < 4; i++) acc[mf][nf][i] = 0.f;

    const uint32_t a_off = FD_A + (uint32_t)(wm*32 + (lane&7) + ((lane>>3)&1)*8) * (FSKP*2)
                         + (lane>>4)*16;
    const uint32_t cb = (lane & 7) + ((lane >> 3) & 1) * 8;
    const uint32_t nb = (lane >> 4) * 8;

#pragma unroll
    for (int ks = 0; ks < 8; ks++) {
        uint32_t a[2][4];
        LDSM4(a[0], sb + a_off + ks * 32);
        LDSM4(a[1], sb + a_off + 16 * FSKP * 2 + ks * 32);
#pragma unroll
        for (int np = 0; np < 4; np++) {
            uint32_t b[4];
            LDSM4T(b, sb + FD_B + ((ks*16 + cb) * FSKP + wn*64 + np*16 + nb) * 2);
            mma_f16(acc[0][2*np],   a[0], b);
            mma_f16(acc[0][2*np+1], a[0], b + 2);
            mma_f16(acc[1][2*np],   a[1], b);
            mma_f16(acc[1][2*np+1], a[1], b + 2);
        }
    }

#pragma unroll
    for (int mf = 0; mf < 2; mf++) {
        const int i0 = h * 128 + wm * 32 + mf * 16 + qr;
#pragma unroll
        for (int nf = 0; nf < 8; nf++) {
            const int c0 = ct * 128 + wn * 64 + nf * 8 + qc * 2;
            *(uint32_t*)&W2[(size_t)i0 * 1024 + c0] = pack2(acc[mf][nf][0], acc[mf][nf][1]);
            *(uint32_t*)&W2[(size_t)(i0 + 8) * 1024 + c0] = pack2(acc[mf][nf][2], acc[mf][nf][3]);
        }
    }
}

// ---------------------------------------------------------------------------
// GEMM core macros (CTA 128x128, BK=64, 3-stage, 8 warps 4x2, 2 CTAs/SM)
// ---------------------------------------------------------------------------
#define SKP_B   144                   // 64 halves + 8 pad = 144 bytes per row
#define GA_B    (128*SKP_B)           // 18432
#define GSTG    (2*GA_B)              // 36864
#define GEMM_SMEM (3*GSTG)            // 110592

#define GEMM_MAIN(X, W)                                                    \
    const int pr = tid >> 3, pp = tid & 7;                                 \
    const __half* Xp = (X) + (size_t)(m0 + pr) * 1024 + pp * 8;            \
    const __half* Wp = (W) + (size_t)(n0 + pr) * 1024 + pp * 8;            \
    const uint32_t a_off = (uint32_t)(wm*32 + (lane&7) + ((lane>>3)&1)*8) * SKP_B \
                         + (lane>>4)*16;                                   \
    const uint32_t b_off = (uint32_t)(wn*64 + (lane>>4)*8 + (lane&7)) * SKP_B \
                         + ((lane>>3)&1)*16;                               \
    float acc[2][8][4];                                                    \
    _Pragma("unroll")                                                      \
    for (int mf = 0; mf < 2; mf++)                                         \
        _Pragma("unroll")                                                  \
        for (int nf = 0; nf < 8; nf++)                                     \
            _Pragma("unroll")                                              \
            for (int i = 0; i < 4; i++) acc[mf][nf][i] = 0.f;              \
    LOAD_STAGE(0, 0); CP_COMMIT();                                         \
    LOAD_STAGE(1, 1); CP_COMMIT();                                         \
    for (int kt = 0; kt < 16; kt++) {                                      \
        const int st = kt % 3;                                             \
        CP_WAIT(1);                                                        \
        __syncthreads();                                                   \
        const uint32_t As = sb + st * GSTG, Bs = As + GA_B;                \
        _Pragma("unroll")                                                  \
        for (int ks = 0; ks < 4; ks++) {                                   \
            uint32_t a[2][4];                                              \
            LDSM4(a[0], As + a_off + ks * 32);                             \
            LDSM4(a[1], As + a_off + 16 * SKP_B + ks * 32);                \
            _Pragma("unroll")                                              \
            for (int np = 0; np < 4; np++) {                               \
                uint32_t b[4];                                             \
                LDSM4(b, Bs + b_off + np * (16 * SKP_B) + ks * 32);        \
                mma_f16(acc[0][2*np],   a[0], b);                          \
                mma_f16(acc[0][2*np+1], a[0], b + 2);                      \
                mma_f16(acc[1][2*np],   a[1], b);                          \
                mma_f16(acc[1][2*np+1], a[1], b + 2);                      \
            }                                                              \
        }                                                                  \
        if (kt + 2 < 16) LOAD_STAGE(kt + 2, (kt + 2) % 3);                 \
        CP_COMMIT();                                                       \
    }

#define LOAD_STAGE(kt, st) {                                              \
    uint32_t base = sb + (st) * GSTG;                                     \
    const __half* xk = Xp + (kt) * 64;                                    \
    const __half* wk = Wp + (kt) * 64;                                    \
    _Pragma("unroll")                                                     \
    for (int i = 0; i < 4; i++) {                                         \
        uint32_t so = (uint32_t)(pr + 32*i) * SKP_B + pp * 16;            \
        cp16(base + so, xk + (size_t)(32*i) * 1024);                      \
        cp16(base + GA_B + so, wk + (size_t)(32*i) * 1024);               \
    } }

// ---------------------------------------------------------------------------
// Fused QKV GEMM. z=0: q (softmax epilogue, scale 1/16), z=1: k (softmax),
// z=2: v (fp16 write).
// ---------------------------------------------------------------------------
__global__ __launch_bounds__(256, 2) void gemm_qkv(
    const float* __restrict__ biasq, const float* __restrict__ biask)
{
    const int z = blockIdx.z;
    const __half* W = (z == 0) ? g_wq2 : ((z == 1) ? g_wk2 : g_wvh);

    extern __shared__ char smc[];
    const uint32_t sb = smem_u32(smc);
    const int tid = threadIdx.x, wid = tid >> 5, lane = tid & 31;
    const int wm = wid & 3, wn = wid >> 2;
    const int qr = lane >> 2, qc = lane & 3;
    const int m0 = blockIdx.y * 128, n0 = blockIdx.x * 128;

    GEMM_MAIN(g_xh, W)

    if (z == 2) {
#pragma unroll
        for (int mf = 0; mf < 2; mf++) {
            const int r0 = m0 + wm * 32 + mf * 16 + qr;
#pragma unroll
            for (int nf = 0; nf < 8; nf++) {
                const int c0 = n0 + wn * 64 + nf * 8 + qc * 2;
                *(uint32_t*)&g_v[(size_t)r0 * 1024 + c0] =
                    pack2(acc[mf][nf][0], acc[mf][nf][1]);
                *(uint32_t*)&g_v[(size_t)(r0 + 8) * 1024 + c0] =
                    pack2(acc[mf][nf][2], acc[mf][nf][3]);
            }
        }
        return;
    }

    // q/k: hedgehog softmax epilogue. Reuse stage smem as f32 ys[128][132].
    __syncthreads();
    float* ys = (float*)smc;
#pragma unroll
    for (int mf = 0; mf < 2; mf++) {
        const int r0 = wm * 32 + mf * 16 + qr;
#pragma unroll
        for (int nf = 0; nf < 8; nf++) {
            const int c0 = wn * 64 + nf * 8 + qc * 2;
            *(float2*)(ys + r0 * 132 + c0) = make_float2(acc[mf][nf][0], acc[mf][nf][1]);
            *(float2*)(ys + (r0 + 8) * 132 + c0) = make_float2(acc[mf][nf][2], acc[mf][nf][3]);
        }
    }
    __syncthreads();

    const float* bias = z ? biask : biasq;
    const float scale = z ? 1.0f : 0.0625f;   // 256^-0.5 folded into qf
    __half* dst = z ? g_kf : g_qf;
    const int h = blockIdx.x;
    float4 bv = *(const float4*)(bias + lane * 4);

    for (int rr = 0; rr < 16; rr += 2) {
        const int r0 = wid * 16 + rr;
        float y[2][4], m[2];
#pragma unroll
        for (int u = 0; u < 2; u++) {
            float4 v4 = *(const float4*)(ys + (r0 + u) * 132 + lane * 4);
            y[u][0] = 2.f * (v4.x + bv.x); y[u][1] = 2.f * (v4.y + bv.y);
            y[u][2] = 2.f * (v4.z + bv.z); y[u][3] = 2.f * (v4.w + bv.w);
            m[u] = fmaxf(fmaxf(fabsf(y[u][0]), fabsf(y[u][1])),
                         fmaxf(fabsf(y[u][2]), fabsf(y[u][3])));
        }
#pragma unroll
        for (int off = 16; off >= 1; off >>= 1) {
            m[0] = fmaxf(m[0], __shfl_xor_sync(0xffffffffu, m[0], off));
            m[1] = fmaxf(m[1], __shfl_xor_sync(0xffffffffu, m[1], off));
        }
        float ep[2][4], en[2][4], zs[2] = {0.f, 0.f};
#pragma unroll
        for (int u = 0; u < 2; u++)
#pragma unroll
            for (int j = 0; j < 4; j++) {
                ep[u][j] = __expf( y[u][j] - m[u]);
                en[u][j] = __expf(-y[u][j] - m[u]);
                zs[u] += ep[u][j] + en[u][j];
            }
#pragma unroll
        for (int off = 16; off >= 1; off >>= 1) {
            zs[0] += __shfl_xor_sync(0xffffffffu, zs[0], off);
            zs[1] += __shfl_xor_sync(0xffffffffu, zs[1], off);
        }
#pragma unroll
        for (int u = 0; u < 2; u++) {
            const float inv = scale / zs[u];
            __half* drow = dst + ((size_t)(m0 + r0 + u) * Hc + h) * Fc;
            *(uint2*)(drow + lane * 4) =
                make_uint2(pack2(ep[u][0]*inv, ep[u][1]*inv),
                           pack2(ep[u][2]*inv, ep[u][3]*inv));
            *(uint2*)(drow + 128 + lane * 4) =
                make_uint2(pack2(en[u][0]*inv, en[u][1]*inv),
                           pack2(en[u][2]*inv, en[u][3]*inv));
        }
    }
}

// ---------------------------------------------------------------------------
// Wo GEMM with rmsnorm row-scale epilogue (rs computed inline from g_prs):
// out[r][c] = rs[r] * (o @ Wo^T)
// ---------------------------------------------------------------------------
__global__ __launch_bounds__(256, 2) void gemm_o(float* __restrict__ out)
{
    extern __shared__ char smc[];
    __shared__ float rs_s[128];
    const uint32_t sb = smem_u32(smc);
    const int tid = threadIdx.x, wid = tid >> 5, lane = tid & 31;
    const int wm = wid & 3, wn = wid >> 2;
    const int qr = lane >> 2, qc = lane & 3;
    const int m0 = blockIdx.y * 128, n0 = blockIdx.x * 128;

    if (tid < 128) {
        float4 a = *(const float4*)&g_prs[(size_t)(m0 + tid) * Hc];
        float4 b4 = *(const float4*)&g_prs[(size_t)(m0 + tid) * Hc + 4];
        float s = a.x + a.y + a.z + a.w + b4.x + b4.y + b4.z + b4.w;
        rs_s[tid] = rsqrtf(s * (1.f / HIDc) + 1e-5f);
    }

    GEMM_MAIN(g_oh, g_woh)

#pragma unroll
    for (int mf = 0; mf < 2; mf++) {
        const int rl = wm * 32 + mf * 16 + qr;
        const int r0 = m0 + rl;
        const float s0 = rs_s[rl], s1 = rs_s[rl + 8];
#pragma unroll
        for (int nf = 0; nf < 8; nf++) {
            const int c0 = n0 + wn * 64 + nf * 8 + qc * 2;
            *(float2*)&out[(size_t)r0 * 1024 + c0] =
                make_float2(acc[mf][nf][0] * s0, acc[mf][nf][1] * s0);
            *(float2*)&out[(size_t)(r0 + 8) * 1024 + c0] =
                make_float2(acc[mf][nf][2] * s1, acc[mf][nf][3] * s1);
        }
    }
}

// ---------------------------------------------------------------------------
// Fused KV scan: per (b, h, d-slice 64, e-slice 64) CTA walks 128 chunks,
// keeping the 64x64 f32 state in mma accumulators. Processes chunk PAIRS per
// iteration (half the barriers): 4 load buffers, 2 S staging buffers.
// 8 warps 2(d)x4(e). grid (2, 4, 16), 256 threads.
// ---------------------------------------------------------------------------
#define KP_ROW 144                    // 72 halves per smem row
#define KP_V   (64*KP_ROW)            // 9216: v slice offset within stage
#define KP_STG (2*64*KP_ROW)          // 18432 per stage
#define KP_SS0 (4*KP_STG)             // 73728
#define KP_SS1 (KP_SS0 + 64*KP_ROW)   // 82944
#define KP_SMEM (KP_SS1 + 64*KP_ROW)  // 92160

__global__ __launch_bounds__(256) void kvscan_kernel()
{
    extern __shared__ char smc[];
    const uint32_t sb = smem_u32(smc);
    const int e0 = blockIdx.x * 64, d0 = blockIdx.y * 64;
    const int b = blockIdx.z >> 3, h = blockIdx.z & 7;
    const int tid = threadIdx.x, wid = tid >> 5, lane = tid & 31;
    const int wm = wid & 1, wn = wid >> 1;
    const int g = lane >> 2, t4 = lane & 3;
    const int lr = tid >> 3, lp = tid & 7;    // loader: row base, 16B col

    const uint32_t ca = (lane & 7) + ((lane >> 4) & 1) * 8;
    const uint32_t ma = ((lane >> 3) & 1) * 8;
    const uint32_t cb = (lane & 7) + ((lane >> 3) & 1) * 8;
    const uint32_t nb = (lane >> 4) * 8;

    float acc[2][2][4];
#pragma unroll
    for (int mf = 0; mf < 2; mf++)
#pragma unroll
        for (int nf = 0; nf < 2; nf++)
#pragma unroll
            for (int i = 0; i < 4; i++) acc[mf][nf][i] = 0.f;

#define KP_LOAD(c, st) {                                                       \
    uint32_t base = sb + (st) * KP_STG;                                        \
    const int tt = (c) * 64;                                                   \
    _Pragma("unroll")                                                          \
    for (int i = 0; i < 2; i++) {                                              \
        int r = lr + 32 * i;                                                   \
        cp16(base + (uint32_t)r * KP_ROW + lp * 16,                            \
             &g_kf[((size_t)(b*Tc + tt + r) * Hc + h) * Fc + d0 + lp * 8]);    \
        cp16(base + KP_V + (uint32_t)r * KP_ROW + lp * 16,                     \
             &g_v[(size_t)(b*Tc + tt + r) * HIDc + h * 128 + e0 + lp * 8]);    \
    } }

// stage exclusive state into S staging buffer `off`
#define KP_STAGE(off) {                                                        \
    _Pragma("unroll")                                                          \
    for (int mf = 0; mf < 2; mf++)                                             \
        _Pragma("unroll")                                                      \
        for (int nf = 0; nf < 2; nf++) {                                       \
            int d = wm * 32 + mf * 16 + g;                                     \
            int e = wn * 16 + nf * 8 + t4 * 2;                                 \
            *(uint32_t*)(smc + (off) + ((uint32_t)d * KP_ROW + e * 2)) =       \
                pack2(acc[mf][nf][0], acc[mf][nf][1]);                         \
            *(uint32_t*)(smc + (off) + ((uint32_t)(d + 8) * KP_ROW + e * 2)) = \
                pack2(acc[mf][nf][2], acc[mf][nf][3]);                         \
        } }

// accumulate one chunk from load buffer `st`
#define KP_MMA(st) {                                                           \
    const uint32_t kfb = sb + (st) * KP_STG;                                   \
    const uint32_t vb  = kfb + KP_V;                                           \
    _Pragma("unroll")                                                          \
    for (int ks = 0; ks < 4; ks++) {                                           \
        uint32_t bbf[4];                                                       \
        LDSM4T(bbf, vb + ((ks*16 + cb) * KP_ROW + (wn*16 + nb) * 2));          \
        _Pragma("unroll")                                                      \
        for (int mf = 0; mf < 2; mf++) {                                       \
            uint32_t a[4];                                                     \
            LDSM4T(a, kfb + ((ks*16 + ca) * KP_ROW + (wm*32 + mf*16 + ma) * 2)); \
            mma_f16(acc[mf][0], a, bbf);                                       \
            mma_f16(acc[mf][1], a, bbf + 2);                                   \
        }                                                                      \
    } }

    KP_LOAD(0, 0); KP_LOAD(1, 1); CP_COMMIT();
    KP_LOAD(2, 2); KP_LOAD(3, 3); CP_COMMIT();

    const size_t sseq = ((size_t)(b*Hc + h)) * NCc * (size_t)(Fc * Dc);

    for (int c = 0; c < NCc; c += 2) {
        CP_WAIT(1);
        __syncthreads();   // pair (c, c+1) buffers ready; prior SS reads done

        KP_STAGE(KP_SS0)       // exclusive state for chunk c
        KP_MMA(c & 3)          // state += chunk c
        KP_STAGE(KP_SS1)       // exclusive state for chunk c+1
        KP_MMA((c + 1) & 3)    // state += chunk c+1

        if (c + 4 < NCc) { KP_LOAD(c + 4, (c + 4) & 3); KP_LOAD(c + 5, (c + 5) & 3); }
        CP_COMMIT();

        __syncthreads();   // both S stages fully written

        const size_t sb0 = sseq + (size_t)c * (Fc * Dc);
        const size_t sb1 = sb0 + (size_t)(Fc * Dc);
#pragma unroll
        for (int i = 0; i < 2; i++) {
            int r = lr + 32 * i;
            *(uint4*)(&g_s[sb0 + (size_t)(d0 + r) * 128 + e0 + lp * 8]) =
                *(const uint4*)(smc + KP_SS0 + (uint32_t)r * KP_ROW + lp * 16);
            *(uint4*)(&g_s[sb1 + (size_t)(d0 + r) * 128 + e0 + lp * 8]) =
                *(const uint4*)(smc + KP_SS1 + (uint32_t)r * KP_ROW + lp * 16);
        }
    }
#undef KP_LOAD
#undef KP_STAGE
#undef KP_MMA
}

// ---------------------------------------------------------------------------
// Output per chunk (fp16 mma): o = tril(qf @ kf^T) @ v + qf @ S  -> fp16
// S streamed in 4x64-row quarters, double-buffered in the dead kf region.
// o staged through v buffer for coalesced stores + per-token sumsq partials.
// 2 CTAs/SM.
// ---------------------------------------------------------------------------
#define OQF 0
#define OKF 33792                     // kf (64x264) / S quarter bufs (2 x 64x136)
#define OSQ(i) (OKF + (i)*17408)
#define OV  68608                     // v (64x136) / o staging (64x136)
#define OAT 86016
#define OUT_SMEM 95232

__global__ __launch_bounds__(256, 2) void out_kernel()
{
    extern __shared__ char smc[];
    const uint32_t sb = smem_u32(smc);
    const int chunk = blockIdx.x, h = blockIdx.y, b = blockIdx.z;
    const int tid = threadIdx.x, wid = tid >> 5, lane = tid & 31;
    const int g = lane >> 2, t4 = lane & 3;
    const int t0 = chunk * 64;
    const int wm = wid & 1, wn = wid >> 1;

    const size_t qbase = ((size_t)(b*Tc + t0) * Hc + h) * Fc;
#pragma unroll
    for (int i = 0; i < 8; i++) {
        int l = tid + i * 256;
        int r = l >> 5, p = l & 31;
        size_t gs = qbase + (size_t)r * (Hc*Fc) + p * 8;
        *(uint4*)(smc + OQF + ((uint32_t)r * 264 + p * 8) * 2) = *(const uint4*)(&g_qf[gs]);
        *(uint4*)(smc + OKF + ((uint32_t)r * 264 + p * 8) * 2) = *(const uint4*)(&g_kf[gs]);
    }
#pragma unroll
    for (int i = 0; i < 4; i++) {
        int l = tid + i * 256;
        int r = l >> 4, p = l & 15;
        *(uint4*)(smc + OV + ((uint32_t)r * 136 + p * 8) * 2) =
            *(const uint4*)(&g_v[(size_t)(b*Tc + t0 + r) * HIDc + h * 128 + p * 8]);
    }
    __syncthreads();

    // phase 1: scores = tril(qf @ kf^T)
    {
        float sc[2][2][4];
#pragma unroll
        for (int mf = 0; mf < 2; mf++)
#pragma unroll
            for (int nf = 0; nf < 2; nf++)
#pragma unroll
                for (int i = 0; i < 4; i++) sc[mf][nf][i] = 0.f;

        const uint32_t aoff = OQF + (uint32_t)(wm*32 + (lane&7) + ((lane>>3)&1)*8) * 528
                            + (lane>>4)*16;
        const uint32_t boff = OKF + (uint32_t)(wn*16 + (lane>>4)*8 + (lane&7)) * 528
                            + ((lane>>3)&1)*16;
#pragma unroll
        for (int ks = 0; ks < 16; ks++) {
            uint32_t a[2][4], bbf[4];
            LDSM4(a[0], sb + aoff + ks * 32);
            LDSM4(a[1], sb + aoff + 16 * 528 + ks * 32);
            LDSM4(bbf, sb + boff + ks * 32);
            mma_f16(sc[0][0], a[0], bbf);
            mma_f16(sc[0][1], a[0], bbf + 2);
            mma_f16(sc[1][0], a[1], bbf);
            mma_f16(sc[1][1], a[1], bbf + 2);
        }
#pragma unroll
        for (int mf = 0; mf < 2; mf++)
#pragma unroll
            for (int nf = 0; nf < 2; nf++) {
                int ci = wm*32 + mf*16 + g;
                int cj = wn*16 + nf*8 + t4*2;
                float v0 = (cj     <= ci) ? sc[mf][nf][0] : 0.f;
                float v1 = (cj + 1 <= ci) ? sc[mf][nf][1] : 0.f;
                *(uint32_t*)(smc + OAT + ((uint32_t)ci * 72 + cj) * 2) = pack2(v0, v1);
                int ci2 = ci + 8;
                float v2 = (cj     <= ci2) ? sc[mf][nf][2] : 0.f;
                float v3 = (cj + 1 <= ci2) ? sc[mf][nf][3] : 0.f;
                *(uint32_t*)(smc + OAT + ((uint32_t)ci2 * 72 + cj) * 2) = pack2(v2, v3);
            }
    }
    __syncthreads();

    // phase 2: o = attn @ v + qf @ S, S in 4 quarters double-buffered
    const size_t sbase = (((size_t)(b*Hc + h)) * NCc + chunk) * (size_t)(Fc * Dc);
    float o[2][4][4];
#pragma unroll
    for (int mf = 0; mf < 2; mf++)
#pragma unroll
        for (int nf = 0; nf < 4; nf++)
#pragma unroll
            for (int i = 0; i < 4; i++) o[mf][nf][i] = 0.f;

    const uint32_t cb = (lane & 7) + ((lane >> 3) & 1) * 8;
    const uint32_t nb = (lane >> 4) * 8;
    const uint32_t a2 = OQF + (uint32_t)(wm*32 + (lane&7) + ((lane>>3)&1)*8) * 528
                      + (lane>>4)*16;

#pragma unroll
    for (int qq = 0; qq < 2; qq++) {
#pragma unroll
        for (int i = 0; i < 4; i++) {
            int l = tid + i * 256;
            int f = l >> 4, p = l & 15;
            cp16(sb + OSQ(qq) + ((uint32_t)f * 136 + p * 8) * 2,
                 &g_s[sbase + (size_t)(qq * 64 + f) * 128 + p * 8]);
        }
        CP_COMMIT();
    }

    // attn @ v (independent of S; overlaps S loads)
    {
        const uint32_t a1 = OAT + (uint32_t)(wm*32 + (lane&7) + ((lane>>3)&1)*8) * 144
                          + (lane>>4)*16;
#pragma unroll
        for (int ks = 0; ks < 4; ks++) {
            uint32_t a[2][4];
            LDSM4(a[0], sb + a1 + ks * 32);
            LDSM4(a[1], sb + a1 + 16 * 144 + ks * 32);
#pragma unroll
            for (int np = 0; np < 2; np++) {
                uint32_t bbf[4];
                LDSM4T(bbf, sb + OV + ((ks*16 + cb) * 136 + wn*32 + np*16 + nb) * 2);
                mma_f16(o[0][2*np],   a[0], bbf);
                mma_f16(o[0][2*np+1], a[0], bbf + 2);
                mma_f16(o[1][2*np],   a[1], bbf);
                mma_f16(o[1][2*np+1], a[1], bbf + 2);
            }
        }
    }

#pragma unroll
    for (int qq = 0; qq < 4; qq++) {
        if (qq < 3) { CP_WAIT(1); } else { CP_WAIT(0); }
        __syncthreads();
        const uint32_t sq = sb + OSQ(qq & 1);
#pragma unroll
        for (int kss = 0; kss < 4; kss++) {
            const int ks = qq * 4 + kss;
            uint32_t a[2][4];
            LDSM4(a[0], sb + a2 + ks * 32);
            LDSM4(a[1], sb + a2 + 16 * 528 + ks * 32);
#pragma unroll
            for (int np = 0; np < 2; np++) {
                uint32_t bbf[4];
                LDSM4T(bbf, sq + ((kss*16 + cb) * 136 + wn*32 + np*16 + nb) * 2);
                mma_f16(o[0][2*np],   a[0], bbf);
                mma_f16(o[0][2*np+1], a[0], bbf + 2);
                mma_f16(o[1][2*np],   a[1], bbf);
                mma_f16(o[1][2*np+1], a[1], bbf + 2);
            }
        }
        __syncthreads();
        if (qq + 2 < 4) {
#pragma unroll
            for (int i = 0; i < 4; i++) {
                int l = tid + i * 256;
                int f = l >> 4, p = l & 15;
                cp16(sb + OSQ(qq & 1) + ((uint32_t)f * 136 + p * 8) * 2,
                     &g_s[sbase + (size_t)((qq + 2) * 64 + f) * 128 + p * 8]);
            }
            CP_COMMIT();
        }
    }

    // stage o through the dead v buffer, then coalesced 16B writes + sumsq
#pragma unroll
    for (int mf = 0; mf < 2; mf++)
#pragma unroll
        for (int nf = 0; nf < 4; nf++) {
            int r = wm*32 + mf*16 + g;
            int e = wn*32 + nf*8 + t4*2;
            *(uint32_t*)(smc + OV + ((uint32_t)r * 136 + e) * 2) =
                pack2(o[mf][nf][0], o[mf][nf][1]);
            *(uint32_t*)(smc + OV + ((uint32_t)(r + 8) * 136 + e) * 2) =
                pack2(o[mf][nf][2], o[mf][nf][3]);
        }
    __syncthreads();
#pragma unroll
    for (int i = 0; i < 4; i++) {
        int l = tid + i * 256;
        int r = l >> 4, p = l & 15;
        *(uint4*)(&g_oh[(size_t)(b*Tc + t0 + r) * HIDc + h * 128 + p * 8]) =
            *(const uint4*)(smc + OV + ((uint32_t)r * 136 + p * 8) * 2);
    }

    // per-token sumsq partial (rmsnorm): 4 threads per token, 32 dims each
    {
        const int r = tid >> 2, part = tid & 3;
        float s = 0.f;
        const __half2* row = (const __half2*)(smc + OV + (uint32_t)r * 136 * 2);
#pragma unroll
        for (int j = 0; j < 16; j++) {
            float2 v = __half22float2(row[part * 16 + j]);
            s += v.x * v.x + v.y * v.y;
        }
        s += __shfl_xor_sync(0xffffffffu, s, 1);
        s += __shfl_xor_sync(0xffffffffu, s, 2);
        if (part == 0)
            g_prs[(size_t)(b*Tc + t0 + r) * Hc + h] = s;
    }
}

// ---------------------------------------------------------------------------
// Launch
// ---------------------------------------------------------------------------
extern "C" void kernel_launch(void* const* d_in, const int* in_sizes, int n_in,
                              void* d_out, int out_size)
{
    const float* x    = (const float*)d_in[0];
    const float* Wq   = (const float*)d_in[1];
    const float* Wk   = (const float*)d_in[2];
    const float* Wv   = (const float*)d_in[3];
    const float* Wo   = (const float*)d_in[4];
    const float* fmqw = (const float*)d_in[5];
    const float* fmqb = (const float*)d_in[6];
    const float* fmkw = (const float*)d_in[7];
    const float* fmkb = (const float*)d_in[8];
    float* out = (float*)d_out;

    cudaFuncSetAttribute(gemm_qkv,  cudaFuncAttributeMaxDynamicSharedMemorySize, GEMM_SMEM);
    cudaFuncSetAttribute(gemm_o,    cudaFuncAttributeMaxDynamicSharedMemorySize, GEMM_SMEM);
    cudaFuncSetAttribute(fold_w,    cudaFuncAttributeMaxDynamicSharedMemorySize, FOLD_SMEM);
    cudaFuncSetAttribute(kvscan_kernel, cudaFuncAttributeMaxDynamicSharedMemorySize, KP_SMEM);
    cudaFuncSetAttribute(out_kernel,cudaFuncAttributeMaxDynamicSharedMemorySize, OUT_SMEM);

    // conversions (x, Wv, Wo fused) + weight folding
    conv_all<<<9216, 256>>>(x, Wv, Wo);
    fold_w<<<dim3(8, 8, 2), 256, FOLD_SMEM>>>(fmqw, fmkw, Wq, Wk);

    // fused QKV GEMM + hedgehog softmax epilogue
    gemm_qkv<<<dim3(HIDc/128, MTOT/128, 3), 256, GEMM_SMEM>>>(fmqb, fmkb);

    // fused KV accumulation + exclusive prefix scan (state in registers)
    kvscan_kernel<<<dim3(2, 4, Bc*Hc), 256, KP_SMEM>>>();

    out_kernel<<<dim3(NCc, Hc, Bc), 256, OUT_SMEM>>>();

    gemm_o<<<dim3(HIDc/128, MTOT/128, 1), 256, GEMM_SMEM>>>(out);
}

// round 15
// speedup vs baseline: 1.3709x; 1.0013x over previous
#include <cuda_runtime.h>
#include <cuda_fp16.h>
#include <cstdint>
#include <math.h>

// Problem constants
#define Bc   2
#define Tc   8192
#define Hc   8
#define Dc   128
#define HIDc 1024
#define NCc  128          // T / CHUNK
#define Fc   256          // hedgehog feature dim (2*DQK)
#define MTOT (Bc*Tc)      // 16384 tokens

// ---------------------------------------------------------------------------
// Scratch (device globals — no allocations allowed)
// ---------------------------------------------------------------------------
__device__ __half g_xh  [(size_t)MTOT*HIDc];      // 32 MB
__device__ __half g_wvh [HIDc*HIDc];
__device__ __half g_woh [HIDc*HIDc];
__device__ __half g_wq2 [HIDc*HIDc];              // folded fmq @ Wq (per head)
__device__ __half g_wk2 [HIDc*HIDc];              // folded fmk @ Wk
__device__ __half g_v   [(size_t)MTOT*HIDc];
__device__ __half g_qf  [(size_t)MTOT*Hc*Fc];     // 64 MB (pre-scaled)
__device__ __half g_kf  [(size_t)MTOT*Hc*Fc];     // 64 MB
__device__ __half g_s   [(size_t)Bc*Hc*NCc*Fc*Dc]; // 128 MB exclusive prefix (fp16)
__device__ __half g_oh  [(size_t)MTOT*HIDc];      // attention out (unnormalized)
__device__ float  g_prs [MTOT*Hc];                // per-(token,head) partial sumsq

// ---------------------------------------------------------------------------
// Helpers
// ---------------------------------------------------------------------------
__device__ __forceinline__ uint32_t smem_u32(const void* p) {
    uint32_t a;
    asm("{ .reg .u64 t; cvta.to.shared.u64 t, %1; cvt.u32.u64 %0, t; }" : "=r"(a) : "l"(p));
    return a;
}
__device__ __forceinline__ uint32_t pack2(float lo, float hi) {
    __half2 h = __floats2half2_rn(lo, hi);
    return *reinterpret_cast<uint32_t*>(&h);
}
__device__ __forceinline__ void mma_f16(float* c, const uint32_t* a, const uint32_t* b) {
    asm volatile(
        "mma.sync.aligned.m16n8k16.row.col.f32.f16.f16.f32 "
        "{%0,%1,%2,%3}, {%4,%5,%6,%7}, {%8,%9}, {%0,%1,%2,%3};"
        : "+f"(c[0]), "+f"(c[1]), "+f"(c[2]), "+f"(c[3])
        : "r"(a[0]), "r"(a[1]), "r"(a[2]), "r"(a[3]), "r"(b[0]), "r"(b[1]));
}
#define LDSM4(r, addr) \
    asm volatile("ldmatrix.sync.aligned.m8n8.x4.shared.b16 {%0,%1,%2,%3}, [%4];" \
        : "=r"((r)[0]), "=r"((r)[1]), "=r"((r)[2]), "=r"((r)[3]) : "r"(addr))
#define LDSM4T(r, addr) \
    asm volatile("ldmatrix.sync.aligned.m8n8.x4.trans.shared.b16 {%0,%1,%2,%3}, [%4];" \
        : "=r"((r)[0]), "=r"((r)[1]), "=r"((r)[2]), "=r"((r)[3]) : "r"(addr))
__device__ __forceinline__ void cp16(uint32_t dst, const void* src) {
    asm volatile("cp.async.cg.shared.global [%0], [%1], 16;" :: "r"(dst), "l"(src) : "memory");
}
#define CP_COMMIT() asm volatile("cp.async.commit_group;" ::: "memory")
#define CP_WAIT(n)  asm volatile("cp.async.wait_group %0;" :: "n"(n) : "memory")

// ---------------------------------------------------------------------------
// Merged f32 -> f16 conversion: blocks [0,8192) -> x, [8192,8704) -> Wv,
// [8704,9216) -> Wo.
// ---------------------------------------------------------------------------
__global__ __launch_bounds__(256) void conv_all(
    const float* __restrict__ x, const float* __restrict__ Wv,
    const float* __restrict__ Wo)
{
    int bidx = blockIdx.x;
    const float* s;
    __half* d;
    int base;
    if (bidx < 8192)      { s = x;  d = g_xh;  base = bidx; }
    else if (bidx < 8704) { s = Wv; d = g_wvh; base = bidx - 8192; }
    else                  { s = Wo; d = g_woh; base = bidx - 8704; }
    int i = (base * 256 + threadIdx.x) * 8;
    float4 a = *(const float4*)(s + i), b = *(const float4*)(s + i + 4);
    *(uint4*)(d + i) = make_uint4(pack2(a.x, a.y), pack2(a.z, a.w),
                                  pack2(b.x, b.y), pack2(b.z, b.w));
}

// ---------------------------------------------------------------------------
// Fold: W2[h*128+i, c] = sum_j fm[i,j] * W[h*128+j, c]   (reads f32 W directly)
// ---------------------------------------------------------------------------
#define FSKP 136
#define FD_A 0
#define FD_B (128*FSKP*2)               // 34816
#define FOLD_SMEM (2*128*FSKP*2)        // 69632

__global__ __launch_bounds__(256) void fold_w(
    const float* __restrict__ fmq, const float* __restrict__ fmk,
    const float* __restrict__ Wq,  const float* __restrict__ Wk)
{
    const int z = blockIdx.z;
    const float* fm = z ? fmk : fmq;
    const float* Wf = z ? Wk : Wq;
    __half* W2 = z ? g_wk2 : g_wq2;

    extern __shared__ char smc[];
    const uint32_t sb = smem_u32(smc);
    const int tid = threadIdx.x, wid = tid >> 5, lane = tid & 31;
    const int wm = wid & 3, wn = wid >> 2;
    const int qr = lane >> 2, qc = lane & 3;
    const int ct = blockIdx.x, h = blockIdx.y;

#pragma unroll
    for (int it = 0; it < 16; it++) {
        int e = tid + it * 256;
        int r = e >> 5, c4 = e & 31;
        float4 f = *(const float4*)(fm + r * 128 + c4 * 4);
        *(uint2*)(smc + FD_A + ((uint32_t)r * FSKP + c4 * 4) * 2) =
            make_uint2(pack2(f.x, f.y), pack2(f.z, f.w));
    }
#pragma unroll
    for (int it = 0; it < 16; it++) {
        int e = tid + it * 256;
        int r = e >> 5, c4 = e & 31;
        float4 f = *(const float4*)(Wf + (size_t)(h * 128 + r) * 1024 + ct * 128 + c4 * 4);
        *(uint2*)(smc + FD_B + ((uint32_t)r * FSKP + c4 * 4) * 2) =
            make_uint2(pack2(f.x, f.y), pack2(f.z, f.w));
    }
    __syncthreads();

    float acc[2][8][4];
#pragma unroll
    for (int mf = 0; mf < 2; mf++)
#pragma unroll
        for (int nf = 0; nf < 8; nf++)
#pragma unroll
            for (int i = 0; i < 4; i++) acc[mf][nf][i] = 0.f;

    const uint32_t a_off = FD_A + (uint32_t)(wm*32 + (lane&7) + ((lane>>3)&1)*8) * (FSKP*2)
                         + (lane>>4)*16;
    const uint32_t cb = (lane & 7) + ((lane >> 3) & 1) * 8;
    const uint32_t nb = (lane >> 4) * 8;

#pragma unroll
    for (int ks = 0; ks < 8; ks++) {
        uint32_t a[2][4];
        LDSM4(a[0], sb + a_off + ks * 32);
        LDSM4(a[1], sb + a_off + 16 * FSKP * 2 + ks * 32);
#pragma unroll
        for (int np = 0; np < 4; np++) {
            uint32_t b[4];
            LDSM4T(b, sb + FD_B + ((ks*16 + cb) * FSKP + wn*64 + np*16 + nb) * 2);
            mma_f16(acc[0][2*np],   a[0], b);
            mma_f16(acc[0][2*np+1], a[0], b + 2);
            mma_f16(acc[1][2*np],   a[1], b);
            mma_f16(acc[1][2*np+1], a[1], b + 2);
        }
    }

#pragma unroll
    for (int mf = 0; mf < 2; mf++) {
        const int i0 = h * 128 + wm * 32 + mf * 16 + qr;
#pragma unroll
        for (int nf = 0; nf < 8; nf++) {
            const int c0 = ct * 128 + wn * 64 + nf * 8 + qc * 2;
            *(uint32_t*)&W2[(size_t)i0 * 1024 + c0] = pack2(acc[mf][nf][0], acc[mf][nf][1]);
            *(uint32_t*)&W2[(size_t)(i0 + 8) * 1024 + c0] = pack2(acc[mf][nf][2], acc[mf][nf][3]);
        }
    }
}

// ---------------------------------------------------------------------------
// GEMM core macros (CTA 128x128, BK=64, 3-stage, 8 warps 4x2, 2 CTAs/SM)
// ---------------------------------------------------------------------------
#define SKP_B   144                   // 64 halves + 8 pad = 144 bytes per row
#define GA_B    (128*SKP_B)           // 18432
#define GSTG    (2*GA_B)              // 36864
#define GEMM_SMEM (3*GSTG)            // 110592

#define GEMM_MAIN(X, W)                                                    \
    const int pr = tid >> 3, pp = tid & 7;                                 \
    const __half* Xp = (X) + (size_t)(m0 + pr) * 1024 + pp * 8;            \
    const __half* Wp = (W) + (size_t)(n0 + pr) * 1024 + pp * 8;            \
    const uint32_t a_off = (uint32_t)(wm*32 + (lane&7) + ((lane>>3)&1)*8) * SKP_B \
                         + (lane>>4)*16;                                   \
    const uint32_t b_off = (uint32_t)(wn*64 + (lane>>4)*8 + (lane&7)) * SKP_B \
                         + ((lane>>3)&1)*16;                               \
    float acc[2][8][4];                                                    \
    _Pragma("unroll")                                                      \
    for (int mf = 0; mf < 2; mf++)                                         \
        _Pragma("unroll")                                                  \
        for (int nf = 0; nf < 8; nf++)                                     \
            _Pragma("unroll")                                              \
            for (int i = 0; i < 4; i++) acc[mf][nf][i] = 0.f;              \
    LOAD_STAGE(0, 0); CP_COMMIT();                                         \
    LOAD_STAGE(1, 1); CP_COMMIT();                                         \
    for (int kt = 0; kt < 16; kt++) {                                      \
        const int st = kt % 3;                                             \
        CP_WAIT(1);                                                        \
        __syncthreads();                                                   \
        const uint32_t As = sb + st * GSTG, Bs = As + GA_B;                \
        _Pragma("unroll")                                                  \
        for (int ks = 0; ks < 4; ks++) {                                   \
            uint32_t a[2][4];                                              \
            LDSM4(a[0], As + a_off + ks * 32);                             \
            LDSM4(a[1], As + a_off + 16 * SKP_B + ks * 32);                \
            _Pragma("unroll")                                              \
            for (int np = 0; np < 4; np++) {                               \
                uint32_t b[4];                                             \
                LDSM4(b, Bs + b_off + np * (16 * SKP_B) + ks * 32);        \
                mma_f16(acc[0][2*np],   a[0], b);                          \
                mma_f16(acc[0][2*np+1], a[0], b + 2);                      \
                mma_f16(acc[1][2*np],   a[1], b);                          \
                mma_f16(acc[1][2*np+1], a[1], b + 2);                      \
            }                                                              \
        }                                                                  \
        if (kt + 2 < 16) LOAD_STAGE(kt + 2, (kt + 2) % 3);                 \
        CP_COMMIT();                                                       \
    }

#define LOAD_STAGE(kt, st) {                                              \
    uint32_t base = sb + (st) * GSTG;                                     \
    const __half* xk = Xp + (kt) * 64;                                    \
    const __half* wk = Wp + (kt) * 64;                                    \
    _Pragma("unroll")                                                     \
    for (int i = 0; i < 4; i++) {                                         \
        uint32_t so = (uint32_t)(pr + 32*i) * SKP_B + pp * 16;            \
        cp16(base + so, xk + (size_t)(32*i) * 1024);                      \
        cp16(base + GA_B + so, wk + (size_t)(32*i) * 1024);               \
    } }

// ---------------------------------------------------------------------------
// Fused QKV GEMM. z=0: q (softmax epilogue, scale 1/16), z=1: k (softmax),
// z=2: v (fp16 write).
// ---------------------------------------------------------------------------
__global__ __launch_bounds__(256, 2) void gemm_qkv(
    const float* __restrict__ biasq, const float* __restrict__ biask)
{
    const int z = blockIdx.z;
    const __half* W = (z == 0) ? g_wq2 : ((z == 1) ? g_wk2 : g_wvh);

    extern __shared__ char smc[];
    const uint32_t sb = smem_u32(smc);
    const int tid = threadIdx.x, wid = tid >> 5, lane = tid & 31;
    const int wm = wid & 3, wn = wid >> 2;
    const int qr = lane >> 2, qc = lane & 3;
    const int m0 = blockIdx.y * 128, n0 = blockIdx.x * 128;

    GEMM_MAIN(g_xh, W)

    if (z == 2) {
#pragma unroll
        for (int mf = 0; mf < 2; mf++) {
            const int r0 = m0 + wm * 32 + mf * 16 + qr;
#pragma unroll
            for (int nf = 0; nf < 8; nf++) {
                const int c0 = n0 + wn * 64 + nf * 8 + qc * 2;
                *(uint32_t*)&g_v[(size_t)r0 * 1024 + c0] =
                    pack2(acc[mf][nf][0], acc[mf][nf][1]);
                *(uint32_t*)&g_v[(size_t)(r0 + 8) * 1024 + c0] =
                    pack2(acc[mf][nf][2], acc[mf][nf][3]);
            }
        }
        return;
    }

    // q/k: hedgehog softmax epilogue. Reuse stage smem as f32 ys[128][132].
    __syncthreads();
    float* ys = (float*)smc;
#pragma unroll
    for (int mf = 0; mf < 2; mf++) {
        const int r0 = wm * 32 + mf * 16 + qr;
#pragma unroll
        for (int nf = 0; nf < 8; nf++) {
            const int c0 = wn * 64 + nf * 8 + qc * 2;
            *(float2*)(ys + r0 * 132 + c0) = make_float2(acc[mf][nf][0], acc[mf][nf][1]);
            *(float2*)(ys + (r0 + 8) * 132 + c0) = make_float2(acc[mf][nf][2], acc[mf][nf][3]);
        }
    }
    __syncthreads();

    const float* bias = z ? biask : biasq;
    const float scale = z ? 1.0f : 0.0625f;   // 256^-0.5 folded into qf
    __half* dst = z ? g_kf : g_qf;
    const int h = blockIdx.x;
    float4 bv = *(const float4*)(bias + lane * 4);

    for (int rr = 0; rr < 16; rr += 2) {
        const int r0 = wid * 16 + rr;
        float y[2][4], m[2];
#pragma unroll
        for (int u = 0; u < 2; u++) {
            float4 v4 = *(const float4*)(ys + (r0 + u) * 132 + lane * 4);
            y[u][0] = 2.f * (v4.x + bv.x); y[u][1] = 2.f * (v4.y + bv.y);
            y[u][2] = 2.f * (v4.z + bv.z); y[u][3] = 2.f * (v4.w + bv.w);
            m[u] = fmaxf(fmaxf(fabsf(y[u][0]), fabsf(y[u][1])),
                         fmaxf(fabsf(y[u][2]), fabsf(y[u][3])));
        }
#pragma unroll
        for (int off = 16; off >= 1; off >>= 1) {
            m[0] = fmaxf(m[0], __shfl_xor_sync(0xffffffffu, m[0], off));
            m[1] = fmaxf(m[1], __shfl_xor_sync(0xffffffffu, m[1], off));
        }
        float ep[2][4], en[2][4], zs[2] = {0.f, 0.f};
#pragma unroll
        for (int u = 0; u < 2; u++)
#pragma unroll
            for (int j = 0; j < 4; j++) {
                ep[u][j] = __expf( y[u][j] - m[u]);
                en[u][j] = __expf(-y[u][j] - m[u]);
                zs[u] += ep[u][j] + en[u][j];
            }
#pragma unroll
        for (int off = 16; off >= 1; off >>= 1) {
            zs[0] += __shfl_xor_sync(0xffffffffu, zs[0], off);
            zs[1] += __shfl_xor_sync(0xffffffffu, zs[1], off);
        }
#pragma unroll
        for (int u = 0; u < 2; u++) {
            const float inv = scale / zs[u];
            __half* drow = dst + ((size_t)(m0 + r0 + u) * Hc + h) * Fc;
            *(uint2*)(drow + lane * 4) =
                make_uint2(pack2(ep[u][0]*inv, ep[u][1]*inv),
                           pack2(ep[u][2]*inv, ep[u][3]*inv));
            *(uint2*)(drow + 128 + lane * 4) =
                make_uint2(pack2(en[u][0]*inv, en[u][1]*inv),
                           pack2(en[u][2]*inv, en[u][3]*inv));
        }
    }
}

// ---------------------------------------------------------------------------
// Wo GEMM with rmsnorm row-scale epilogue (rs computed inline from g_prs):
// out[r][c] = rs[r] * (o @ Wo^T)
// ---------------------------------------------------------------------------
__global__ __launch_bounds__(256, 2) void gemm_o(float* __restrict__ out)
{
    extern __shared__ char smc[];
    __shared__ float rs_s[128];
    const uint32_t sb = smem_u32(smc);
    const int tid = threadIdx.x, wid = tid >> 5, lane = tid & 31;
    const int wm = wid & 3, wn = wid >> 2;
    const int qr = lane >> 2, qc = lane & 3;
    const int m0 = blockIdx.y * 128, n0 = blockIdx.x * 128;

    if (tid < 128) {
        float4 a = *(const float4*)&g_prs[(size_t)(m0 + tid) * Hc];
        float4 b4 = *(const float4*)&g_prs[(size_t)(m0 + tid) * Hc + 4];
        float s = a.x + a.y + a.z + a.w + b4.x + b4.y + b4.z + b4.w;
        rs_s[tid] = rsqrtf(s * (1.f / HIDc) + 1e-5f);
    }

    GEMM_MAIN(g_oh, g_woh)

#pragma unroll
    for (int mf = 0; mf < 2; mf++) {
        const int rl = wm * 32 + mf * 16 + qr;
        const int r0 = m0 + rl;
        const float s0 = rs_s[rl], s1 = rs_s[rl + 8];
#pragma unroll
        for (int nf = 0; nf < 8; nf++) {
            const int c0 = n0 + wn * 64 + nf * 8 + qc * 2;
            *(float2*)&out[(size_t)r0 * 1024 + c0] =
                make_float2(acc[mf][nf][0] * s0, acc[mf][nf][1] * s0);
            *(float2*)&out[(size_t)(r0 + 8) * 1024 + c0] =
                make_float2(acc[mf][nf][2] * s1, acc[mf][nf][3] * s1);
        }
    }
}

// ---------------------------------------------------------------------------
// Fused KV scan, 512 threads: per (b, h, d-slice 64, e-slice 64) CTA walks
// 128 chunks keeping the 64x64 f32 state in mma accumulators (warp grid
// 4(d)x4(e), warp tile 16x16). Chunk PAIRS per iteration; 4 load buffers,
// 2 S staging buffers. grid (2, 4, 16).
// ---------------------------------------------------------------------------
#define KP_ROW 144                    // 72 halves per smem row
#define KP_V   (64*KP_ROW)            // 9216: v slice offset within stage
#define KP_STG (2*64*KP_ROW)          // 18432 per stage
#define KP_SS0 (4*KP_STG)             // 73728
#define KP_SS1 (KP_SS0 + 64*KP_ROW)   // 82944
#define KP_SMEM (KP_SS1 + 64*KP_ROW)  // 92160

__global__ __launch_bounds__(512) void kvscan_kernel()
{
    extern __shared__ char smc[];
    const uint32_t sb = smem_u32(smc);
    const int e0 = blockIdx.x * 64, d0 = blockIdx.y * 64;
    const int b = blockIdx.z >> 3, h = blockIdx.z & 7;
    const int tid = threadIdx.x, wid = tid >> 5, lane = tid & 31;
    const int wm = wid & 3, wn = wid >> 2;   // 4(d groups of 16) x 4(e groups of 16)
    const int g = lane >> 2, t4 = lane & 3;
    const int lr = tid >> 3, lp = tid & 7;   // loader: row 0..63, 16B col 0..7

    const uint32_t ca = (lane & 7) + ((lane >> 4) & 1) * 8;
    const uint32_t ma = ((lane >> 3) & 1) * 8;
    const uint32_t cb = (lane & 7) + ((lane >> 3) & 1) * 8;
    const uint32_t nb = (lane >> 4) * 8;

    float acc[2][4];                         // 2 n-frags of the 16x16 tile
#pragma unroll
    for (int nf = 0; nf < 2; nf++)
#pragma unroll
        for (int i = 0; i < 4; i++) acc[nf][i] = 0.f;

#define KP_LOAD(c, st) {                                                       \
    uint32_t base = sb + (st) * KP_STG;                                        \
    const int tt = (c) * 64;                                                   \
    cp16(base + (uint32_t)lr * KP_ROW + lp * 16,                               \
         &g_kf[((size_t)(b*Tc + tt + lr) * Hc + h) * Fc + d0 + lp * 8]);       \
    cp16(base + KP_V + (uint32_t)lr * KP_ROW + lp * 16,                        \
         &g_v[(size_t)(b*Tc + tt + lr) * HIDc + h * 128 + e0 + lp * 8]); }

#define KP_STAGE(off) {                                                        \
    _Pragma("unroll")                                                          \
    for (int nf = 0; nf < 2; nf++) {                                           \
        int d = wm * 16 + g;                                                   \
        int e = wn * 16 + nf * 8 + t4 * 2;                                     \
        *(uint32_t*)(smc + (off) + ((uint32_t)d * KP_ROW + e * 2)) =           \
            pack2(acc[nf][0], acc[nf][1]);                                     \
        *(uint32_t*)(smc + (off) + ((uint32_t)(d + 8) * KP_ROW + e * 2)) =     \
            pack2(acc[nf][2], acc[nf][3]);                                     \
    } }

#define KP_MMA(st) {                                                           \
    const uint32_t kfb = sb + (st) * KP_STG;                                   \
    const uint32_t vb  = kfb + KP_V;                                           \
    _Pragma("unroll")                                                          \
    for (int ks = 0; ks < 4; ks++) {                                           \
        uint32_t bbf[4], a[4];                                                 \
        LDSM4T(bbf, vb + ((ks*16 + cb) * KP_ROW + (wn*16 + nb) * 2));          \
        LDSM4T(a,  kfb + ((ks*16 + ca) * KP_ROW + (wm*16 + ma) * 2));          \
        mma_f16(acc[0], a, bbf);                                               \
        mma_f16(acc[1], a, bbf + 2);                                           \
    } }

    KP_LOAD(0, 0); KP_LOAD(1, 1); CP_COMMIT();
    KP_LOAD(2, 2); KP_LOAD(3, 3); CP_COMMIT();

    const size_t sseq = ((size_t)(b*Hc + h)) * NCc * (size_t)(Fc * Dc);

    for (int c = 0; c < NCc; c += 2) {
        CP_WAIT(1);
        __syncthreads();   // pair (c, c+1) buffers ready; prior SS reads done

        KP_STAGE(KP_SS0)       // exclusive state for chunk c
        KP_MMA(c & 3)          // state += chunk c
        KP_STAGE(KP_SS1)       // exclusive state for chunk c+1
        KP_MMA((c + 1) & 3)    // state += chunk c+1

        if (c + 4 < NCc) { KP_LOAD(c + 4, (c + 4) & 3); KP_LOAD(c + 5, (c + 5) & 3); }
        CP_COMMIT();

        __syncthreads();   // both S stages fully written

        const size_t sb0 = sseq + (size_t)c * (Fc * Dc);
        const size_t sb1 = sb0 + (size_t)(Fc * Dc);
        *(uint4*)(&g_s[sb0 + (size_t)(d0 + lr) * 128 + e0 + lp * 8]) =
            *(const uint4*)(smc + KP_SS0 + (uint32_t)lr * KP_ROW + lp * 16);
        *(uint4*)(&g_s[sb1 + (size_t)(d0 + lr) * 128 + e0 + lp * 8]) =
            *(const uint4*)(smc + KP_SS1 + (uint32_t)lr * KP_ROW + lp * 16);
    }
#undef KP_LOAD
#undef KP_STAGE
#undef KP_MMA
}

// ---------------------------------------------------------------------------
// Output per chunk (fp16 mma): o = tril(qf @ kf^T) @ v + qf @ S  -> fp16
// Front loads via cp.async. S streamed in 4x64-row quarters, double-buffered
// in the dead kf region. o staged through v buffer for coalesced stores +
// per-token sumsq partials. 2 CTAs/SM.
// ---------------------------------------------------------------------------
#define OQF 0
#define OKF 33792                     // kf (64x264) / S quarter bufs (2 x 64x136)
#define OSQ(i) (OKF + (i)*17408)
#define OV  68608                     // v (64x136) / o staging (64x136)
#define OAT 86016
#define OUT_SMEM 95232

__global__ __launch_bounds__(256, 2) void out_kernel()
{
    extern __shared__ char smc[];
    const uint32_t sb = smem_u32(smc);
    const int chunk = blockIdx.x, h = blockIdx.y, b = blockIdx.z;
    const int tid = threadIdx.x, wid = tid >> 5, lane = tid & 31;
    const int g = lane >> 2, t4 = lane & 3;
    const int t0 = chunk * 64;
    const int wm = wid & 1, wn = wid >> 1;

    const size_t qbase = ((size_t)(b*Tc + t0) * Hc + h) * Fc;
#pragma unroll
    for (int i = 0; i < 8; i++) {
        int l = tid + i * 256;
        int r = l >> 5, p = l & 31;
        size_t gs = qbase + (size_t)r * (Hc*Fc) + p * 8;
        cp16(sb + OQF + ((uint32_t)r * 264 + p * 8) * 2, &g_qf[gs]);
        cp16(sb + OKF + ((uint32_t)r * 264 + p * 8) * 2, &g_kf[gs]);
    }
#pragma unroll
    for (int i = 0; i < 4; i++) {
        int l = tid + i * 256;
        int r = l >> 4, p = l & 15;
        cp16(sb + OV + ((uint32_t)r * 136 + p * 8) * 2,
             &g_v[(size_t)(b*Tc + t0 + r) * HIDc + h * 128 + p * 8]);
    }
    CP_COMMIT(); CP_WAIT(0);
    __syncthreads();

    // phase 1: scores = tril(qf @ kf^T)
    {
        float sc[2][2][4];
#pragma unroll
        for (int mf = 0; mf < 2; mf++)
#pragma unroll
            for (int nf = 0; nf < 2; nf++)
#pragma unroll
                for (int i = 0; i < 4; i++) sc[mf][nf][i] = 0.f;

        const uint32_t aoff = OQF + (uint32_t)(wm*32 + (lane&7) + ((lane>>3)&1)*8) * 528
                            + (lane>>4)*16;
        const uint32_t boff = OKF + (uint32_t)(wn*16 + (lane>>4)*8 + (lane&7)) * 528
                            + ((lane>>3)&1)*16;
#pragma unroll
        for (int ks = 0; ks < 16; ks++) {
            uint32_t a[2][4], bbf[4];
            LDSM4(a[0], sb + aoff + ks * 32);
            LDSM4(a[1], sb + aoff + 16 * 528 + ks * 32);
            LDSM4(bbf, sb + boff + ks * 32);
            mma_f16(sc[0][0], a[0], bbf);
            mma_f16(sc[0][1], a[0], bbf + 2);
            mma_f16(sc[1][0], a[1], bbf);
            mma_f16(sc[1][1], a[1], bbf + 2);
        }
#pragma unroll
        for (int mf = 0; mf < 2; mf++)
#pragma unroll
            for (int nf = 0; nf < 2; nf++) {
                int ci = wm*32 + mf*16 + g;
                int cj = wn*16 + nf*8 + t4*2;
                float v0 = (cj     <= ci) ? sc[mf][nf][0] : 0.f;
                float v1 = (cj + 1 <= ci) ? sc[mf][nf][1] : 0.f;
                *(uint32_t*)(smc + OAT + ((uint32_t)ci * 72 + cj) * 2) = pack2(v0, v1);
                int ci2 = ci + 8;
                float v2 = (cj     <= ci2) ? sc[mf][nf][2] : 0.f;
                float v3 = (cj + 1 <= ci2) ? sc[mf][nf][3] : 0.f;
                *(uint32_t*)(smc + OAT + ((uint32_t)ci2 * 72 + cj) * 2) = pack2(v2, v3);
            }
    }
    __syncthreads();

    // phase 2: o = attn @ v + qf @ S, S in 4 quarters double-buffered
    const size_t sbase = (((size_t)(b*Hc + h)) * NCc + chunk) * (size_t)(Fc * Dc);
    float o[2][4][4];
#pragma unroll
    for (int mf = 0; mf < 2; mf++)
#pragma unroll
        for (int nf = 0; nf < 4; nf++)
#pragma unroll
            for (int i = 0; i < 4; i++) o[mf][nf][i] = 0.f;

    const uint32_t cb = (lane & 7) + ((lane >> 3) & 1) * 8;
    const uint32_t nb = (lane >> 4) * 8;
    const uint32_t a2 = OQF + (uint32_t)(wm*32 + (lane&7) + ((lane>>3)&1)*8) * 528
                      + (lane>>4)*16;

#pragma unroll
    for (int qq = 0; qq < 2; qq++) {
#pragma unroll
        for (int i = 0; i < 4; i++) {
            int l = tid + i * 256;
            int f = l >> 4, p = l & 15;
            cp16(sb + OSQ(qq) + ((uint32_t)f * 136 + p * 8) * 2,
                 &g_s[sbase + (size_t)(qq * 64 + f) * 128 + p * 8]);
        }
        CP_COMMIT();
    }

    // attn @ v (independent of S; overlaps S loads)
    {
        const uint32_t a1 = OAT + (uint32_t)(wm*32 + (lane&7) + ((lane>>3)&1)*8) * 144
                          + (lane>>4)*16;
#pragma unroll
        for (int ks = 0; ks < 4; ks++) {
            uint32_t a[2][4];
            LDSM4(a[0], sb + a1 + ks * 32);
            LDSM4(a[1], sb + a1 + 16 * 144 + ks * 32);
#pragma unroll
            for (int np = 0; np < 2; np++) {
                uint32_t bbf[4];
                LDSM4T(bbf, sb + OV + ((ks*16 + cb) * 136 + wn*32 + np*16 + nb) * 2);
                mma_f16(o[0][2*np],   a[0], bbf);
                mma_f16(o[0][2*np+1], a[0], bbf + 2);
                mma_f16(o[1][2*np],   a[1], bbf);
                mma_f16(o[1][2*np+1], a[1], bbf + 2);
            }
        }
    }

#pragma unroll
    for (int qq = 0; qq < 4; qq++) {
        if (qq < 3) { CP_WAIT(1); } else { CP_WAIT(0); }
        __syncthreads();
        const uint32_t sq = sb + OSQ(qq & 1);
#pragma unroll
        for (int kss = 0; kss < 4; kss++) {
            const int ks = qq * 4 + kss;
            uint32_t a[2][4];
            LDSM4(a[0], sb + a2 + ks * 32);
            LDSM4(a[1], sb + a2 + 16 * 528 + ks * 32);
#pragma unroll
            for (int np = 0; np < 2; np++) {
                uint32_t bbf[4];
                LDSM4T(bbf, sq + ((kss*16 + cb) * 136 + wn*32 + np*16 + nb) * 2);
                mma_f16(o[0][2*np],   a[0], bbf);
                mma_f16(o[0][2*np+1], a[0], bbf + 2);
                mma_f16(o[1][2*np],   a[1], bbf);
                mma_f16(o[1][2*np+1], a[1], bbf + 2);
            }
        }
        __syncthreads();
        if (qq + 2 < 4) {
#pragma unroll
            for (int i = 0; i < 4; i++) {
                int l = tid + i * 256;
                int f = l >> 4, p = l & 15;
                cp16(sb + OSQ(qq & 1) + ((uint32_t)f * 136 + p * 8) * 2,
                     &g_s[sbase + (size_t)((qq + 2) * 64 + f) * 128 + p * 8]);
            }
            CP_COMMIT();
        }
    }

    // stage o through the dead v buffer, then coalesced 16B writes + sumsq
#pragma unroll
    for (int mf = 0; mf < 2; mf++)
#pragma unroll
        for (int nf = 0; nf < 4; nf++) {
            int r = wm*32 + mf*16 + g;
            int e = wn*32 + nf*8 + t4*2;
            *(uint32_t*)(smc + OV + ((uint32_t)r * 136 + e) * 2) =
                pack2(o[mf][nf][0], o[mf][nf][1]);
            *(uint32_t*)(smc + OV + ((uint32_t)(r + 8) * 136 + e) * 2) =
                pack2(o[mf][nf][2], o[mf][nf][3]);
        }
    __syncthreads();
#pragma unroll
    for (int i = 0; i < 4; i++) {
        int l = tid + i * 256;
        int r = l >> 4, p = l & 15;
        *(uint4*)(&g_oh[(size_t)(b*Tc + t0 + r) * HIDc + h * 128 + p * 8]) =
            *(const uint4*)(smc + OV + ((uint32_t)r * 136 + p * 8) * 2);
    }

    // per-token sumsq partial (rmsnorm): 4 threads per token, 32 dims each
    {
        const int r = tid >> 2, part = tid & 3;
        float s = 0.f;
        const __half2* row = (const __half2*)(smc + OV + (uint32_t)r * 136 * 2);
#pragma unroll
        for (int j = 0; j < 16; j++) {
            float2 v = __half22float2(row[part * 16 + j]);
            s += v.x * v.x + v.y * v.y;
        }
        s += __shfl_xor_sync(0xffffffffu, s, 1);
        s += __shfl_xor_sync(0xffffffffu, s, 2);
        if (part == 0)
            g_prs[(size_t)(b*Tc + t0 + r) * Hc + h] = s;
    }
}

// ---------------------------------------------------------------------------
// Launch
// ---------------------------------------------------------------------------
extern "C" void kernel_launch(void* const* d_in, const int* in_sizes, int n_in,
                              void* d_out, int out_size)
{
    const float* x    = (const float*)d_in[0];
    const float* Wq   = (const float*)d_in[1];
    const float* Wk   = (const float*)d_in[2];
    const float* Wv   = (const float*)d_in[3];
    const float* Wo   = (const float*)d_in[4];
    const float* fmqw = (const float*)d_in[5];
    const float* fmqb = (const float*)d_in[6];
    const float* fmkw = (const float*)d_in[7];
    const float* fmkb = (const float*)d_in[8];
    float* out = (float*)d_out;

    cudaFuncSetAttribute(gemm_qkv,  cudaFuncAttributeMaxDynamicSharedMemorySize, GEMM_SMEM);
    cudaFuncSetAttribute(gemm_o,    cudaFuncAttributeMaxDynamicSharedMemorySize, GEMM_SMEM);
    cudaFuncSetAttribute(fold_w,    cudaFuncAttributeMaxDynamicSharedMemorySize, FOLD_SMEM);
    cudaFuncSetAttribute(kvscan_kernel, cudaFuncAttributeMaxDynamicSharedMemorySize, KP_SMEM);
    cudaFuncSetAttribute(out_kernel,cudaFuncAttributeMaxDynamicSharedMemorySize, OUT_SMEM);

    // conversions (x, Wv, Wo fused) + weight folding
    conv_all<<<9216, 256>>>(x, Wv, Wo);
    fold_w<<<dim3(8, 8, 2), 256, FOLD_SMEM>>>(fmqw, fmkw, Wq, Wk);

    // fused QKV GEMM + hedgehog softmax epilogue
    gemm_qkv<<<dim3(HIDc/128, MTOT/128, 3), 256, GEMM_SMEM>>>(fmqb, fmkb);

    // fused KV accumulation + exclusive prefix scan (state in registers)
    kvscan_kernel<<<dim3(2, 4, Bc*Hc), 512, KP_SMEM>>>();

    out_kernel<<<dim3(NCc, Hc, Bc), 256, OUT_SMEM>>>();

    gemm_o<<<dim3(HIDc/128, MTOT/128, 1), 256, GEMM_SMEM>>>(out);
}